// round 1
// baseline (speedup 1.0000x reference)
#include <cuda_runtime.h>
#include <math.h>
#include <stdint.h>

#define T_TOK 4096
#define H_DIM 2048
#define D_DIM 1024
#define NE_RT 16
#define NE_SH 2

// ---------------- scratch (device globals; no allocations) ----------------
__device__ int   g_cnt[NE_RT];
__device__ int   g_tok[NE_RT * T_TOK];
__device__ float g_gate[NE_RT * T_TOK];
__device__ float g_mid_sh[(size_t)NE_SH * T_TOK * D_DIM];   // 32 MB
__device__ float g_mid_rt[(size_t)NE_RT * T_TOK * D_DIM];   // 268 MB (bucketed)

// ---------------- helpers ----------------
__device__ __forceinline__ uint32_t f2tf(float f) {
    uint32_t u;
    asm("cvt.rna.tf32.f32 %0, %1;" : "=r"(u) : "f"(f));
    return u;
}
__device__ __forceinline__ float gelu_f(float v) {
    return 0.5f * v * (1.0f + erff(v * 0.70710678118654752440f));
}

// ---------------- router ----------------
__global__ void zero_cnt_kernel() {
    if (threadIdx.x < NE_RT) g_cnt[threadIdx.x] = 0;
}

__global__ void router_kernel(const float* __restrict__ x,
                              const float* __restrict__ Wr) {
    int warp = threadIdx.x >> 5;
    int lane = threadIdx.x & 31;
    int t = blockIdx.x * 8 + warp;
    if (t >= T_TOK) return;

    float acc[NE_RT];
#pragma unroll
    for (int e = 0; e < NE_RT; e++) acc[e] = 0.f;

    const float* xr = x + (size_t)t * H_DIM;
    for (int h = lane; h < H_DIM; h += 32) {
        float xv = xr[h];
        const float4* w4 = reinterpret_cast<const float4*>(Wr + (size_t)h * NE_RT);
#pragma unroll
        for (int q = 0; q < 4; q++) {
            float4 w = w4[q];
            acc[4*q+0] += xv * w.x;
            acc[4*q+1] += xv * w.y;
            acc[4*q+2] += xv * w.z;
            acc[4*q+3] += xv * w.w;
        }
    }
#pragma unroll
    for (int e = 0; e < NE_RT; e++) {
#pragma unroll
        for (int off = 16; off > 0; off >>= 1)
            acc[e] += __shfl_xor_sync(0xffffffffu, acc[e], off);
    }
    if (lane == 0) {
        float mx = acc[0];
#pragma unroll
        for (int e = 1; e < NE_RT; e++) mx = fmaxf(mx, acc[e]);
        float p[NE_RT];
        float s = 0.f;
#pragma unroll
        for (int e = 0; e < NE_RT; e++) { p[e] = expf(acc[e] - mx); s += p[e]; }
        float inv = 1.0f / s;

        int i1 = 0; float v1 = p[0];
#pragma unroll
        for (int e = 1; e < NE_RT; e++) if (p[e] > v1) { v1 = p[e]; i1 = e; }
        int i2 = -1; float v2 = -1.f;
#pragma unroll
        for (int e = 0; e < NE_RT; e++) if (e != i1 && p[e] > v2) { v2 = p[e]; i2 = e; }

        int pos = atomicAdd(&g_cnt[i1], 1);
        g_tok[i1 * T_TOK + pos]  = t;
        g_gate[i1 * T_TOK + pos] = v1 * inv;
        pos = atomicAdd(&g_cnt[i2], 1);
        g_tok[i2 * T_TOK + pos]  = t;
        g_gate[i2 * T_TOK + pos] = v2 * inv;
    }
}

// ---------------- tiled tf32 GEMM (mma.sync m16n8k8) ----------------
// MODE 0: mid_sh[e]  = gelu( x @ Wsh_up[e] )                 M=T N=1024 K=2048
// MODE 1: mid_rt[e,i]= gelu( x[tok] @ Wrt_up[e] ) * gate     M=cnt N=1024 K=2048 (gathered)
// MODE 2: out        = sum_e mid_sh[e] @ Wsh_down[e]         M=T N=2048 K=2*1024 (plain store)
// MODE 3: out[tok]  += mid_rt[e,i] @ Wrt_down[e]             M=cnt N=2048 K=1024 (atomicAdd)

#define BM 128
#define BN 64
#define BK 32
#define AS_STRIDE 36
#define BS_STRIDE 72

template <int MODE>
__global__ void __launch_bounds__(256) gemm_moe(const float* __restrict__ X,
                                                const float* __restrict__ W,
                                                float* __restrict__ OUT) {
    constexpr int KTOT = (MODE == 3) ? 1024 : 2048;
    constexpr int NN   = (MODE <= 1) ? 1024 : 2048;
    constexpr int LDA  = (MODE <= 1) ? 2048 : 1024;

    const int e = (MODE == 2) ? 0 : blockIdx.z;

    int cnt = T_TOK;
    if (MODE == 1 || MODE == 3) {
        cnt = g_cnt[e];
        if ((int)blockIdx.y * BM >= cnt) return;
    }

    __shared__ uint32_t As[BM * AS_STRIDE];
    __shared__ uint32_t Bs[BK * BS_STRIDE];

    const int tid  = threadIdx.x;
    const int lane = tid & 31;
    const int warp = tid >> 5;
    const int wm   = warp >> 1;  // 0..3 (32 rows each)
    const int wn   = warp & 1;   // 0..1 (32 cols each)
    const int m0   = blockIdx.y * BM;
    const int n0   = blockIdx.x * BN;

    const float* Abase;
    const float* Bbase;
    if (MODE == 0 || MODE == 1) {
        Abase = X;
        Bbase = W + (size_t)e * H_DIM * D_DIM;
    } else if (MODE == 2) {
        Abase = g_mid_sh;
        Bbase = W;
    } else {
        Abase = g_mid_rt + (size_t)e * T_TOK * D_DIM;
        Bbase = W + (size_t)e * D_DIM * H_DIM;
    }

    float c[2][4][4];
#pragma unroll
    for (int i = 0; i < 2; i++)
#pragma unroll
        for (int j = 0; j < 4; j++)
#pragma unroll
            for (int q = 0; q < 4; q++) c[i][j][q] = 0.f;

    for (int k0 = 0; k0 < KTOT; k0 += BK) {
        const float* Ak = Abase;
        const float* Bk = Bbase;
        int kloc = k0;
        if (MODE == 2 && k0 >= 1024) {
            Ak = g_mid_sh + (size_t)T_TOK * D_DIM;
            Bk = W + (size_t)D_DIM * H_DIM;
            kloc = k0 - 1024;
        }

        // ---- stage A tile: BM x BK (1024 float4 by 256 threads) ----
#pragma unroll
        for (int j = 0; j < 4; j++) {
            int idx = tid + 256 * j;
            int r   = idx >> 3;   // 0..127
            int c4  = idx & 7;    // 0..7
            float4 v = make_float4(0.f, 0.f, 0.f, 0.f);
            int grow = m0 + r;
            if (MODE == 1) {
                if (grow < cnt) {
                    int tok = g_tok[e * T_TOK + grow];
                    v = *reinterpret_cast<const float4*>(
                        Ak + (size_t)tok * LDA + kloc + c4 * 4);
                }
            } else if (MODE == 3) {
                if (grow < cnt) {
                    v = *reinterpret_cast<const float4*>(
                        Ak + (size_t)grow * LDA + kloc + c4 * 4);
                }
            } else {
                v = *reinterpret_cast<const float4*>(
                    Ak + (size_t)grow * LDA + kloc + c4 * 4);
            }
            uint4 u;
            u.x = f2tf(v.x); u.y = f2tf(v.y); u.z = f2tf(v.z); u.w = f2tf(v.w);
            *reinterpret_cast<uint4*>(&As[r * AS_STRIDE + c4 * 4]) = u;
        }
        // ---- stage B tile: BK x BN (512 float4 by 256 threads) ----
#pragma unroll
        for (int j = 0; j < 2; j++) {
            int idx = tid + 256 * j;
            int r   = idx >> 4;   // 0..31 (k row)
            int c4  = idx & 15;   // 0..15
            float4 v = *reinterpret_cast<const float4*>(
                Bk + (size_t)(kloc + r) * NN + n0 + c4 * 4);
            uint4 u;
            u.x = f2tf(v.x); u.y = f2tf(v.y); u.z = f2tf(v.z); u.w = f2tf(v.w);
            *reinterpret_cast<uint4*>(&Bs[r * BS_STRIDE + c4 * 4]) = u;
        }
        __syncthreads();

#pragma unroll
        for (int ks = 0; ks < 4; ks++) {
            uint32_t a[2][4];
#pragma unroll
            for (int im = 0; im < 2; im++) {
                int m  = wm * 32 + im * 16 + (lane >> 2);
                int kk = ks * 8 + (lane & 3);
                a[im][0] = As[m * AS_STRIDE + kk];
                a[im][1] = As[(m + 8) * AS_STRIDE + kk];
                a[im][2] = As[m * AS_STRIDE + kk + 4];
                a[im][3] = As[(m + 8) * AS_STRIDE + kk + 4];
            }
            uint32_t b[4][2];
#pragma unroll
            for (int in_ = 0; in_ < 4; in_++) {
                int n  = wn * 32 + in_ * 8 + (lane >> 2);
                int kk = ks * 8 + (lane & 3);
                b[in_][0] = Bs[kk * BS_STRIDE + n];
                b[in_][1] = Bs[(kk + 4) * BS_STRIDE + n];
            }
#pragma unroll
            for (int im = 0; im < 2; im++)
#pragma unroll
                for (int in_ = 0; in_ < 4; in_++)
                    asm volatile(
                        "mma.sync.aligned.m16n8k8.row.col.f32.tf32.tf32.f32 "
                        "{%0,%1,%2,%3}, {%4,%5,%6,%7}, {%8,%9}, {%0,%1,%2,%3};"
                        : "+f"(c[im][in_][0]), "+f"(c[im][in_][1]),
                          "+f"(c[im][in_][2]), "+f"(c[im][in_][3])
                        : "r"(a[im][0]), "r"(a[im][1]), "r"(a[im][2]), "r"(a[im][3]),
                          "r"(b[in_][0]), "r"(b[in_][1]));
        }
        __syncthreads();
    }

    // ---- epilogue ----
#pragma unroll
    for (int im = 0; im < 2; im++) {
#pragma unroll
        for (int in_ = 0; in_ < 4; in_++) {
#pragma unroll
            for (int half = 0; half < 2; half++) {
                int r    = wm * 32 + im * 16 + half * 8 + (lane >> 2);
                int grow = m0 + r;
                int gcol = n0 + wn * 32 + in_ * 8 + 2 * (lane & 3);
                float v0 = c[im][in_][half * 2 + 0];
                float v1 = c[im][in_][half * 2 + 1];
                if (MODE == 0) {
                    float* dst = g_mid_sh + (size_t)e * T_TOK * D_DIM +
                                 (size_t)grow * D_DIM + gcol;
                    dst[0] = gelu_f(v0);
                    dst[1] = gelu_f(v1);
                } else if (MODE == 1) {
                    if (grow < cnt) {
                        float gate = g_gate[e * T_TOK + grow];
                        float* dst = g_mid_rt +
                                     ((size_t)e * T_TOK + grow) * D_DIM + gcol;
                        dst[0] = gelu_f(v0) * gate;
                        dst[1] = gelu_f(v1) * gate;
                    }
                } else if (MODE == 2) {
                    float* dst = OUT + (size_t)grow * H_DIM + gcol;
                    dst[0] = v0;
                    dst[1] = v1;
                } else {
                    if (grow < cnt) {
                        int tok = g_tok[e * T_TOK + grow];
                        float* dst = OUT + (size_t)tok * H_DIM + gcol;
                        atomicAdd(dst + 0, v0);
                        atomicAdd(dst + 1, v1);
                    }
                }
            }
        }
    }
}

// ---------------- launch ----------------
extern "C" void kernel_launch(void* const* d_in, const int* in_sizes, int n_in,
                              void* d_out, int out_size) {
    const float* x      = (const float*)d_in[0];
    const float* Wsh_up = (const float*)d_in[1];
    const float* Wsh_dn = (const float*)d_in[2];
    const float* Wrt_up = (const float*)d_in[3];
    const float* Wrt_dn = (const float*)d_in[4];
    const float* Wr     = (const float*)d_in[5];
    float* out = (float*)d_out;

    zero_cnt_kernel<<<1, 32>>>();
    router_kernel<<<T_TOK / 8, 256>>>(x, Wr);

    // shared-expert up (+gelu)
    gemm_moe<0><<<dim3(D_DIM / BN, T_TOK / BM, NE_SH), 256>>>(x, Wsh_up, nullptr);
    // routed-expert up, gathered (+gelu * gate)
    gemm_moe<1><<<dim3(D_DIM / BN, T_TOK / BM, NE_RT), 256>>>(x, Wrt_up, nullptr);
    // shared-expert down (both experts fused in K), writes out
    gemm_moe<2><<<dim3(H_DIM / BN, T_TOK / BM, 1), 256>>>(nullptr, Wsh_dn, out);
    // routed-expert down, scatter atomicAdd into out (ordered after mode 2)
    gemm_moe<3><<<dim3(H_DIM / BN, T_TOK / BM, NE_RT), 256>>>(nullptr, Wrt_dn, out);
}

// round 5
// speedup vs baseline: 1.4627x; 1.4627x over previous
#include <cuda_runtime.h>
#include <math.h>
#include <stdint.h>

#define T_TOK 4096
#define H_DIM 2048
#define D_DIM 1024
#define NE_RT 16
#define NE_SH 2

// ---------------- scratch (device globals; no allocations) ----------------
__device__ int   g_cnt[NE_RT];
__device__ int   g_tok[NE_RT * T_TOK];
__device__ float g_gate[NE_RT * T_TOK];
__device__ float g_mid_sh[(size_t)NE_SH * T_TOK * D_DIM];
__device__ float g_mid_rt[(size_t)NE_RT * T_TOK * D_DIM];

// ---------------- helpers ----------------
__device__ __forceinline__ uint32_t f2tf(float f) {
    uint32_t u;
    asm("cvt.rna.tf32.f32 %0, %1;" : "=r"(u) : "f"(f));
    return u;
}
__device__ __forceinline__ float gelu_f(float v) {
    return 0.5f * v * (1.0f + erff(v * 0.70710678118654752440f));
}
__device__ __forceinline__ void cp16(uint32_t dst_smem, const void* src, bool pred) {
    int sz = pred ? 16 : 0;
    asm volatile("cp.async.cg.shared.global [%0], [%1], 16, %2;\n"
                 :: "r"(dst_smem), "l"(src), "r"(sz) : "memory");
}
__device__ __forceinline__ void cp_commit() {
    asm volatile("cp.async.commit_group;" ::: "memory");
}

// ---------------- router ----------------
__global__ void zero_cnt_kernel() {
    if (threadIdx.x < NE_RT) g_cnt[threadIdx.x] = 0;
}

__global__ void router_kernel(const float* __restrict__ x,
                              const float* __restrict__ Wr) {
    int warp = threadIdx.x >> 5;
    int lane = threadIdx.x & 31;
    int t = blockIdx.x * 8 + warp;
    if (t >= T_TOK) return;

    float acc[NE_RT];
#pragma unroll
    for (int e = 0; e < NE_RT; e++) acc[e] = 0.f;

    const float* xr = x + (size_t)t * H_DIM;
    for (int h = lane; h < H_DIM; h += 32) {
        float xv = xr[h];
        const float4* w4 = reinterpret_cast<const float4*>(Wr + (size_t)h * NE_RT);
#pragma unroll
        for (int q = 0; q < 4; q++) {
            float4 w = w4[q];
            acc[4*q+0] += xv * w.x;
            acc[4*q+1] += xv * w.y;
            acc[4*q+2] += xv * w.z;
            acc[4*q+3] += xv * w.w;
        }
    }
#pragma unroll
    for (int e = 0; e < NE_RT; e++) {
#pragma unroll
        for (int off = 16; off > 0; off >>= 1)
            acc[e] += __shfl_xor_sync(0xffffffffu, acc[e], off);
    }
    if (lane == 0) {
        float mx = acc[0];
#pragma unroll
        for (int e = 1; e < NE_RT; e++) mx = fmaxf(mx, acc[e]);
        float p[NE_RT];
        float s = 0.f;
#pragma unroll
        for (int e = 0; e < NE_RT; e++) { p[e] = expf(acc[e] - mx); s += p[e]; }
        float inv = 1.0f / s;

        int i1 = 0; float v1 = p[0];
#pragma unroll
        for (int e = 1; e < NE_RT; e++) if (p[e] > v1) { v1 = p[e]; i1 = e; }
        int i2 = -1; float v2 = -1.f;
#pragma unroll
        for (int e = 0; e < NE_RT; e++) if (e != i1 && p[e] > v2) { v2 = p[e]; i2 = e; }

        int pos = atomicAdd(&g_cnt[i1], 1);
        g_tok[i1 * T_TOK + pos]  = t;
        g_gate[i1 * T_TOK + pos] = v1 * inv;
        pos = atomicAdd(&g_cnt[i2], 1);
        g_tok[i2 * T_TOK + pos]  = t;
        g_gate[i2 * T_TOK + pos] = v2 * inv;
    }
}

// ---------------- 3-stage pipelined tf32 GEMM (mma.sync m16n8k8) ----------------
// MODE 0: mid_sh[e]  = gelu( x @ Wsh_up[e] )                 M=T N=1024 K=2048
// MODE 1: mid_rt[e,i]= gelu( x[tok] @ Wrt_up[e] ) * gate     M=cnt (gather by tok)
// MODE 2: out        = sum_e mid_sh[e] @ Wsh_down[e]         K fused 2*1024
// MODE 3: out[tok]  += mid_rt[e,i] @ Wrt_down[e]             A read by bucket row,
//                                                            SCATTER by tok (fixed!)

#define BM 128
#define BN 128
#define BK 32
#define STAGES 3
#define ASTR 36
#define BSTR 132
#define A_WORDS (BM * ASTR)               // 4608
#define B_WORDS (BK * BSTR)               // 4224
#define STAGE_WORDS (A_WORDS + B_WORDS)   // 8832
#define SMEM_BYTES (STAGES * STAGE_WORDS * 4 + BM * 8)

template <int MODE>
__global__ void __launch_bounds__(256) gemm_moe(const float* __restrict__ X,
                                                const float* __restrict__ W,
                                                float* __restrict__ OUT) {
    constexpr int KTOT = (MODE == 3) ? 1024 : 2048;
    constexpr int NN   = (MODE <= 1) ? 1024 : 2048;
    constexpr int LDA  = (MODE <= 1) ? 2048 : 1024;

    const int e = (MODE == 2) ? 0 : blockIdx.z;

    int cnt = T_TOK;
    if (MODE == 1 || MODE == 3) {
        cnt = g_cnt[e];
        if ((int)blockIdx.y * BM >= cnt) return;
    }

    extern __shared__ float sm[];
    int*   s_tok  = (int*)(sm + STAGES * STAGE_WORDS);
    float* s_gate = (float*)(s_tok + BM);

    const int tid  = threadIdx.x;
    const int lane = tid & 31;
    const int warp = tid >> 5;
    const int wm   = warp >> 2;  // 0..1  (64 rows)
    const int wn   = warp & 3;   // 0..3  (32 cols)
    const int m0   = blockIdx.y * BM;
    const int n0   = blockIdx.x * BN;

    const float* Abase;
    const float* Bbase;
    if (MODE == 0 || MODE == 1) {
        Abase = X;
        Bbase = W + (size_t)e * H_DIM * D_DIM;
    } else if (MODE == 2) {
        Abase = g_mid_sh;
        Bbase = W;
    } else {
        Abase = g_mid_rt + (size_t)e * T_TOK * D_DIM;
        Bbase = W + (size_t)e * D_DIM * H_DIM;
    }

    // per-row table.
    // MODE 0/2: tok = grow (row identity).
    // MODE 1  : tok = SOURCE token (gather A from x[tok]); gate.
    // MODE 3  : tok = DEST token (scatter OUT[tok]); A is read at bucket row m0+r.
    if (tid < BM) {
        int grow = m0 + tid;
        int tok;
        float gate = 0.f;
        if (MODE == 0 || MODE == 2) {
            tok = grow;
        } else if (MODE == 1) {
            if (grow < cnt) {
                tok  = g_tok[e * T_TOK + grow];
                gate = g_gate[e * T_TOK + grow];
            } else tok = -1;
        } else {
            tok = (grow < cnt) ? g_tok[e * T_TOK + grow] : -1;
        }
        s_tok[tid]  = tok;
        s_gate[tid] = gate;
    }
    __syncthreads();

    auto load_stage = [&](int s, int k0) {
        float* As = sm + s * STAGE_WORDS;
        float* Bs = As + A_WORDS;
        const float* Ak = Abase;
        const float* Bk = Bbase;
        int kloc = k0;
        if (MODE == 2 && k0 >= 1024) {
            Ak   = g_mid_sh + (size_t)T_TOK * D_DIM;
            Bk   = W + (size_t)D_DIM * H_DIM;
            kloc = k0 - 1024;
        }
        uint32_t a_sm = (uint32_t)__cvta_generic_to_shared(As);
        uint32_t b_sm = (uint32_t)__cvta_generic_to_shared(Bs);
#pragma unroll
        for (int j = 0; j < 4; j++) {
            int idx = tid + 256 * j;
            int r   = idx >> 3;
            int c4  = idx & 7;
            int tok = s_tok[r];
            bool valid = tok >= 0;
            // MODE 1 gathers A by source token; MODE 0/2/3 read row m0+r.
            int srow = (MODE == 1) ? (valid ? tok : 0) : (m0 + r);
            const float* src = Ak + (size_t)srow * LDA + kloc + c4 * 4;
            cp16(a_sm + (r * ASTR + c4 * 4) * 4, src, valid);
        }
#pragma unroll
        for (int j = 0; j < 4; j++) {
            int idx = tid + 256 * j;
            int r   = idx >> 5;
            int c4  = idx & 31;
            const float* src = Bk + (size_t)(kloc + r) * NN + n0 + c4 * 4;
            cp16(b_sm + (r * BSTR + c4 * 4) * 4, src, true);
        }
    };

    float c[4][4][4];
#pragma unroll
    for (int i = 0; i < 4; i++)
#pragma unroll
        for (int j = 0; j < 4; j++)
#pragma unroll
            for (int q = 0; q < 4; q++) c[i][j][q] = 0.f;

    constexpr int nK = KTOT / BK;

#pragma unroll
    for (int s = 0; s < STAGES - 1; s++) {
        load_stage(s, s * BK);
        cp_commit();
    }

    for (int ki = 0; ki < nK; ki++) {
        asm volatile("cp.async.wait_group %0;" :: "n"(STAGES - 2) : "memory");
        __syncthreads();

        const float* As = sm + (ki % STAGES) * STAGE_WORDS;
        const float* Bs = As + A_WORDS;

#pragma unroll
        for (int ks = 0; ks < 4; ks++) {
            uint32_t a[4][4];
#pragma unroll
            for (int im = 0; im < 4; im++) {
                int m  = wm * 64 + im * 16 + (lane >> 2);
                int kk = ks * 8 + (lane & 3);
                a[im][0] = f2tf(As[m * ASTR + kk]);
                a[im][1] = f2tf(As[(m + 8) * ASTR + kk]);
                a[im][2] = f2tf(As[m * ASTR + kk + 4]);
                a[im][3] = f2tf(As[(m + 8) * ASTR + kk + 4]);
            }
            uint32_t b[4][2];
#pragma unroll
            for (int in_ = 0; in_ < 4; in_++) {
                int n  = wn * 32 + in_ * 8 + (lane >> 2);
                int kk = ks * 8 + (lane & 3);
                b[in_][0] = f2tf(Bs[kk * BSTR + n]);
                b[in_][1] = f2tf(Bs[(kk + 4) * BSTR + n]);
            }
#pragma unroll
            for (int im = 0; im < 4; im++)
#pragma unroll
                for (int in_ = 0; in_ < 4; in_++)
                    asm volatile(
                        "mma.sync.aligned.m16n8k8.row.col.f32.tf32.tf32.f32 "
                        "{%0,%1,%2,%3}, {%4,%5,%6,%7}, {%8,%9}, {%0,%1,%2,%3};"
                        : "+f"(c[im][in_][0]), "+f"(c[im][in_][1]),
                          "+f"(c[im][in_][2]), "+f"(c[im][in_][3])
                        : "r"(a[im][0]), "r"(a[im][1]), "r"(a[im][2]), "r"(a[im][3]),
                          "r"(b[in_][0]), "r"(b[in_][1]));
        }

        // refill the stage read in iteration ki-1 (safe: the barrier above
        // guarantees all threads finished reading it)
        int kn = ki + STAGES - 1;
        if (kn < nK) load_stage(kn % STAGES, kn * BK);
        cp_commit();
    }

    // ---- epilogue ----
#pragma unroll
    for (int im = 0; im < 4; im++) {
#pragma unroll
        for (int in_ = 0; in_ < 4; in_++) {
#pragma unroll
            for (int half = 0; half < 2; half++) {
                int rr   = wm * 64 + im * 16 + half * 8 + (lane >> 2);
                int grow = m0 + rr;
                int gcol = n0 + wn * 32 + in_ * 8 + 2 * (lane & 3);
                float v0 = c[im][in_][half * 2 + 0];
                float v1 = c[im][in_][half * 2 + 1];
                if (MODE == 0) {
                    float* dst = g_mid_sh + (size_t)e * T_TOK * D_DIM +
                                 (size_t)grow * D_DIM + gcol;
                    dst[0] = gelu_f(v0);
                    dst[1] = gelu_f(v1);
                } else if (MODE == 1) {
                    if (s_tok[rr] >= 0) {
                        float gate = s_gate[rr];
                        float* dst = g_mid_rt +
                                     ((size_t)e * T_TOK + grow) * D_DIM + gcol;
                        dst[0] = gelu_f(v0) * gate;
                        dst[1] = gelu_f(v1) * gate;
                    }
                } else if (MODE == 2) {
                    float* dst = OUT + (size_t)grow * H_DIM + gcol;
                    dst[0] = v0;
                    dst[1] = v1;
                } else {
                    int tok = s_tok[rr];   // DEST token (fixed)
                    if (tok >= 0) {
                        float* dst = OUT + (size_t)tok * H_DIM + gcol;
                        atomicAdd(dst + 0, v0);
                        atomicAdd(dst + 1, v1);
                    }
                }
            }
        }
    }
}

// ---------------- launch ----------------
extern "C" void kernel_launch(void* const* d_in, const int* in_sizes, int n_in,
                              void* d_out, int out_size) {
    const float* x      = (const float*)d_in[0];
    const float* Wsh_up = (const float*)d_in[1];
    const float* Wsh_dn = (const float*)d_in[2];
    const float* Wrt_up = (const float*)d_in[3];
    const float* Wrt_dn = (const float*)d_in[4];
    const float* Wr     = (const float*)d_in[5];
    float* out = (float*)d_out;

    cudaFuncSetAttribute(gemm_moe<0>, cudaFuncAttributeMaxDynamicSharedMemorySize, SMEM_BYTES);
    cudaFuncSetAttribute(gemm_moe<1>, cudaFuncAttributeMaxDynamicSharedMemorySize, SMEM_BYTES);
    cudaFuncSetAttribute(gemm_moe<2>, cudaFuncAttributeMaxDynamicSharedMemorySize, SMEM_BYTES);
    cudaFuncSetAttribute(gemm_moe<3>, cudaFuncAttributeMaxDynamicSharedMemorySize, SMEM_BYTES);

    zero_cnt_kernel<<<1, 32>>>();
    router_kernel<<<T_TOK / 8, 256>>>(x, Wr);

    gemm_moe<0><<<dim3(D_DIM / BN, T_TOK / BM, NE_SH), 256, SMEM_BYTES>>>(x, Wsh_up, nullptr);
    gemm_moe<1><<<dim3(D_DIM / BN, T_TOK / BM, NE_RT), 256, SMEM_BYTES>>>(x, Wrt_up, nullptr);
    gemm_moe<2><<<dim3(H_DIM / BN, T_TOK / BM, 1), 256, SMEM_BYTES>>>(nullptr, Wsh_dn, out);
    gemm_moe<3><<<dim3(H_DIM / BN, T_TOK / BM, NE_RT), 256, SMEM_BYTES>>>(nullptr, Wrt_dn, out);
}

// round 7
// speedup vs baseline: 1.5754x; 1.0770x over previous
#include <cuda_runtime.h>
#include <math.h>
#include <stdint.h>

#define T_TOK 4096
#define H_DIM 2048
#define D_DIM 1024
#define NE_RT 16
#define NE_SH 2

// ---------------- scratch (device globals; no allocations) ----------------
__device__ int   g_cnt[NE_RT];
__device__ int   g_tok[NE_RT * T_TOK];
__device__ float g_gate[NE_RT * T_TOK];
__device__ float g_mid_sh[(size_t)NE_SH * T_TOK * D_DIM];
__device__ float g_mid_rt[(size_t)NE_RT * T_TOK * D_DIM];
// pre-converted (tf32-rounded) copies of inputs
__device__ float g_xc[(size_t)T_TOK * H_DIM];
__device__ float g_wsh_up[(size_t)NE_SH * H_DIM * D_DIM];
__device__ float g_wsh_dn[(size_t)NE_SH * D_DIM * H_DIM];
__device__ float g_wrt_up[(size_t)NE_RT * H_DIM * D_DIM];
__device__ float g_wrt_dn[(size_t)NE_RT * D_DIM * H_DIM];

// ---------------- helpers ----------------
__device__ __forceinline__ uint32_t f2tf(float f) {
    uint32_t u;
    asm("cvt.rna.tf32.f32 %0, %1;" : "=r"(u) : "f"(f));
    return u;
}
__device__ __forceinline__ float gelu_f(float v) {
    return 0.5f * v * (1.0f + erff(v * 0.70710678118654752440f));
}
__device__ __forceinline__ void cp16(uint32_t dst_smem, const void* src, bool pred) {
    int sz = pred ? 16 : 0;
    asm volatile("cp.async.cg.shared.global [%0], [%1], 16, %2;\n"
                 :: "r"(dst_smem), "l"(src), "r"(sz) : "memory");
}
__device__ __forceinline__ void cp_commit() {
    asm volatile("cp.async.commit_group;" ::: "memory");
}

// ---------------- tf32 pre-conversion (one pass per tensor) ----------------
__global__ void conv_tf32_kernel(const float4* __restrict__ src,
                                 float4* __restrict__ dst, int n4) {
    int stride = gridDim.x * blockDim.x;
    for (int i = blockIdx.x * blockDim.x + threadIdx.x; i < n4; i += stride) {
        float4 v = src[i];
        float4 o;
        o.x = __uint_as_float(f2tf(v.x));
        o.y = __uint_as_float(f2tf(v.y));
        o.z = __uint_as_float(f2tf(v.z));
        o.w = __uint_as_float(f2tf(v.w));
        dst[i] = o;
    }
}

// ---------------- router ----------------
__global__ void zero_cnt_kernel() {
    if (threadIdx.x < NE_RT) g_cnt[threadIdx.x] = 0;
}

__global__ void router_kernel(const float* __restrict__ x,
                              const float* __restrict__ Wr) {
    int warp = threadIdx.x >> 5;
    int lane = threadIdx.x & 31;
    int t = blockIdx.x * 8 + warp;
    if (t >= T_TOK) return;

    float acc[NE_RT];
#pragma unroll
    for (int e = 0; e < NE_RT; e++) acc[e] = 0.f;

    const float* xr = x + (size_t)t * H_DIM;
    for (int h = lane; h < H_DIM; h += 32) {
        float xv = xr[h];
        const float4* w4 = reinterpret_cast<const float4*>(Wr + (size_t)h * NE_RT);
#pragma unroll
        for (int q = 0; q < 4; q++) {
            float4 w = w4[q];
            acc[4*q+0] += xv * w.x;
            acc[4*q+1] += xv * w.y;
            acc[4*q+2] += xv * w.z;
            acc[4*q+3] += xv * w.w;
        }
    }
#pragma unroll
    for (int e = 0; e < NE_RT; e++) {
#pragma unroll
        for (int off = 16; off > 0; off >>= 1)
            acc[e] += __shfl_xor_sync(0xffffffffu, acc[e], off);
    }
    if (lane == 0) {
        float mx = acc[0];
#pragma unroll
        for (int e = 1; e < NE_RT; e++) mx = fmaxf(mx, acc[e]);
        float p[NE_RT];
        float s = 0.f;
#pragma unroll
        for (int e = 0; e < NE_RT; e++) { p[e] = expf(acc[e] - mx); s += p[e]; }
        float inv = 1.0f / s;

        int i1 = 0; float v1 = p[0];
#pragma unroll
        for (int e = 1; e < NE_RT; e++) if (p[e] > v1) { v1 = p[e]; i1 = e; }
        int i2 = -1; float v2 = -1.f;
#pragma unroll
        for (int e = 0; e < NE_RT; e++) if (e != i1 && p[e] > v2) { v2 = p[e]; i2 = e; }

        int pos = atomicAdd(&g_cnt[i1], 1);
        g_tok[i1 * T_TOK + pos]  = t;
        g_gate[i1 * T_TOK + pos] = v1 * inv;
        pos = atomicAdd(&g_cnt[i2], 1);
        g_tok[i2 * T_TOK + pos]  = t;
        g_gate[i2 * T_TOK + pos] = v2 * inv;
    }
}

// -------- 3-stage cp.async tf32 GEMM, 128x128 CTA tile, 64x64 warp tiles --------
// All operands are PRE-CONVERTED tf32 bit patterns — zero cvt in the mainloop.
// MODE 0: mid_sh[e]  = tf32( gelu( x @ Wsh_up[e] ) )
// MODE 1: mid_rt[e,i]= tf32( gelu( x[tok] @ Wrt_up[e] ) * gate )   (gather)
// MODE 2: out        = sum_e mid_sh[e] @ Wsh_down[e]               (K fused)
// MODE 3: out[tok]  += mid_rt[e,i] @ Wrt_down[e]                   (scatter atomics)

#define BM 128
#define BN 128
#define BK 32
#define STAGES 3
#define NTHR 128
#define ASTR 36
#define BSTR 136
#define A_WORDS (BM * ASTR)               // 4608
#define B_WORDS (BK * BSTR)               // 4352
#define STAGE_WORDS (A_WORDS + B_WORDS)   // 8960
#define EPI_PITCH 132
#define SMEM_BYTES (STAGES * STAGE_WORDS * 4)

template <int MODE>
__global__ void __launch_bounds__(NTHR) gemm_moe(const float* __restrict__ OUT_only,
                                                 float* __restrict__ OUT) {
    constexpr int KTOT = (MODE == 3) ? 1024 : 2048;
    constexpr int NN   = (MODE <= 1) ? 1024 : 2048;
    constexpr int LDA  = (MODE <= 1) ? 2048 : 1024;
    constexpr int nK   = KTOT / BK;

    const int e = (MODE == 2) ? 0 : blockIdx.z;

    int cnt = T_TOK;
    if (MODE == 1 || MODE == 3) {
        cnt = g_cnt[e];
        if ((int)blockIdx.y * BM >= cnt) return;
    }

    extern __shared__ float sm[];
    __shared__ int   s_tok[BM];
    __shared__ float s_gate[BM];

    const int tid  = threadIdx.x;
    const int lane = tid & 31;
    const int warp = tid >> 5;
    const int wm   = warp >> 1;  // 0..1 (64 rows)
    const int wn   = warp & 1;   // 0..1 (64 cols)
    const int m0   = blockIdx.y * BM;
    const int n0   = blockIdx.x * BN;

    const float* Abase;
    const float* Bbase;
    if (MODE == 0 || MODE == 1) {
        Abase = g_xc;
        Bbase = (MODE == 0 ? g_wsh_up : g_wrt_up) + (size_t)e * H_DIM * D_DIM;
    } else if (MODE == 2) {
        Abase = g_mid_sh;
        Bbase = g_wsh_dn;
    } else {
        Abase = g_mid_rt + (size_t)e * T_TOK * D_DIM;
        Bbase = g_wrt_dn + (size_t)e * D_DIM * H_DIM;
    }

    // per-row table. MODE1: src token + gate. MODE3: dst token. MODE0/2: identity.
    if (tid < BM) {
        int grow = m0 + tid;
        int tok;
        float gate = 0.f;
        if (MODE == 0 || MODE == 2) {
            tok = grow;
        } else if (MODE == 1) {
            if (grow < cnt) {
                tok  = g_tok[e * T_TOK + grow];
                gate = g_gate[e * T_TOK + grow];
            } else tok = -1;
        } else {
            tok = (grow < cnt) ? g_tok[e * T_TOK + grow] : -1;
        }
        s_tok[tid]  = tok;
        s_gate[tid] = gate;
    }
    __syncthreads();

    auto load_stage = [&](int s, int k0) {
        float* As = sm + s * STAGE_WORDS;
        float* Bs = As + A_WORDS;
        const float* Ak = Abase;
        const float* Bk = Bbase;
        int kloc = k0;
        if (MODE == 2 && k0 >= 1024) {
            Ak   = g_mid_sh + (size_t)T_TOK * D_DIM;
            Bk   = g_wsh_dn + (size_t)D_DIM * H_DIM;
            kloc = k0 - 1024;
        }
        uint32_t a_sm = (uint32_t)__cvta_generic_to_shared(As);
        uint32_t b_sm = (uint32_t)__cvta_generic_to_shared(Bs);
#pragma unroll
        for (int j = 0; j < 8; j++) {             // A: 128 rows x 8 float4
            int idx = tid + NTHR * j;
            int r   = idx >> 3;
            int c4  = idx & 7;
            int tok = s_tok[r];
            bool valid;
            int  srow;
            if (MODE == 1)      { valid = tok >= 0; srow = valid ? tok : 0; }
            else if (MODE == 3) { valid = tok >= 0; srow = m0 + r; }
            else                { valid = true;     srow = m0 + r; }
            const float* src = Ak + (size_t)srow * LDA + kloc + c4 * 4;
            cp16(a_sm + (r * ASTR + c4 * 4) * 4, src, valid);
        }
#pragma unroll
        for (int j = 0; j < 8; j++) {             // B: 32 k-rows x 32 float4
            int idx = tid + NTHR * j;
            int r   = idx >> 5;
            int c4  = idx & 31;
            const float* src = Bk + (size_t)(kloc + r) * NN + n0 + c4 * 4;
            cp16(b_sm + (r * BSTR + c4 * 4) * 4, src, true);
        }
    };

    float c[4][8][4];
#pragma unroll
    for (int i = 0; i < 4; i++)
#pragma unroll
        for (int j = 0; j < 8; j++)
#pragma unroll
            for (int q = 0; q < 4; q++) c[i][j][q] = 0.f;

#pragma unroll
    for (int s = 0; s < STAGES - 1; s++) {
        load_stage(s, s * BK);
        cp_commit();
    }

    for (int ki = 0; ki < nK; ki++) {
        asm volatile("cp.async.wait_group %0;" :: "n"(STAGES - 2) : "memory");
        __syncthreads();

        const uint32_t* As = reinterpret_cast<const uint32_t*>(sm + (ki % STAGES) * STAGE_WORDS);
        const uint32_t* Bs = As + A_WORDS;

#pragma unroll
        for (int ks = 0; ks < 4; ks++) {
            const int kk = ks * 8 + (lane & 3);
            uint32_t a[4][4];
#pragma unroll
            for (int im = 0; im < 4; im++) {
                int m = wm * 64 + im * 16 + (lane >> 2);
                a[im][0] = As[m * ASTR + kk];
                a[im][1] = As[(m + 8) * ASTR + kk];
                a[im][2] = As[m * ASTR + kk + 4];
                a[im][3] = As[(m + 8) * ASTR + kk + 4];
            }
            uint32_t b[8][2];
#pragma unroll
            for (int in_ = 0; in_ < 8; in_++) {
                int n = wn * 64 + in_ * 8 + (lane >> 2);
                b[in_][0] = Bs[kk * BSTR + n];
                b[in_][1] = Bs[(kk + 4) * BSTR + n];
            }
#pragma unroll
            for (int im = 0; im < 4; im++)
#pragma unroll
                for (int in_ = 0; in_ < 8; in_++)
                    asm volatile(
                        "mma.sync.aligned.m16n8k8.row.col.f32.tf32.tf32.f32 "
                        "{%0,%1,%2,%3}, {%4,%5,%6,%7}, {%8,%9}, {%0,%1,%2,%3};"
                        : "+f"(c[im][in_][0]), "+f"(c[im][in_][1]),
                          "+f"(c[im][in_][2]), "+f"(c[im][in_][3])
                        : "r"(a[im][0]), "r"(a[im][1]), "r"(a[im][2]), "r"(a[im][3]),
                          "r"(b[in_][0]), "r"(b[in_][1]));
        }

        int kn = ki + STAGES - 1;
        if (kn < nK) load_stage(kn % STAGES, kn * BK);
        cp_commit();
    }

    // ---- epilogue: registers -> smem (pitch 132) -> coalesced/atomic stores ----
    __syncthreads();
    float* ep = sm;
#pragma unroll
    for (int im = 0; im < 4; im++) {
#pragma unroll
        for (int in_ = 0; in_ < 8; in_++) {
#pragma unroll
            for (int half = 0; half < 2; half++) {
                int rr = wm * 64 + im * 16 + half * 8 + (lane >> 2);
                int cc = wn * 64 + in_ * 8 + 2 * (lane & 3);
                float v0 = c[im][in_][half * 2 + 0];
                float v1 = c[im][in_][half * 2 + 1];
                if (MODE <= 1) {
                    v0 = gelu_f(v0);
                    v1 = gelu_f(v1);
                    if (MODE == 1) {
                        float gate = s_gate[rr];
                        v0 *= gate; v1 *= gate;
                    }
                    // store tf32-rounded so down-GEMMs need no cvt
                    v0 = __uint_as_float(f2tf(v0));
                    v1 = __uint_as_float(f2tf(v1));
                }
                ep[rr * EPI_PITCH + cc]     = v0;
                ep[rr * EPI_PITCH + cc + 1] = v1;
            }
        }
    }
    __syncthreads();

#pragma unroll
    for (int jj = 0; jj < 32; jj++) {
        int idx = tid + NTHR * jj;
        int r   = idx >> 5;
        int c4  = idx & 31;
        float4 v = *reinterpret_cast<float4*>(&ep[r * EPI_PITCH + c4 * 4]);
        int grow = m0 + r;
        int gcol = n0 + c4 * 4;
        if (MODE == 0) {
            *reinterpret_cast<float4*>(
                g_mid_sh + (size_t)e * T_TOK * D_DIM + (size_t)grow * D_DIM + gcol) = v;
        } else if (MODE == 1) {
            if (s_tok[r] >= 0)
                *reinterpret_cast<float4*>(
                    g_mid_rt + ((size_t)e * T_TOK + grow) * D_DIM + gcol) = v;
        } else if (MODE == 2) {
            *reinterpret_cast<float4*>(OUT + (size_t)grow * H_DIM + gcol) = v;
        } else {
            int tok = s_tok[r];
            if (tok >= 0) {
                float* dst = OUT + (size_t)tok * H_DIM + gcol;
                atomicAdd(dst + 0, v.x);
                atomicAdd(dst + 1, v.y);
                atomicAdd(dst + 2, v.z);
                atomicAdd(dst + 3, v.w);
            }
        }
    }
}

// ---------------- launch ----------------
extern "C" void kernel_launch(void* const* d_in, const int* in_sizes, int n_in,
                              void* d_out, int out_size) {
    const float* x      = (const float*)d_in[0];
    const float* Wsh_up = (const float*)d_in[1];
    const float* Wsh_dn = (const float*)d_in[2];
    const float* Wrt_up = (const float*)d_in[3];
    const float* Wrt_dn = (const float*)d_in[4];
    const float* Wr     = (const float*)d_in[5];
    float* out = (float*)d_out;

    cudaFuncSetAttribute(gemm_moe<0>, cudaFuncAttributeMaxDynamicSharedMemorySize, SMEM_BYTES);
    cudaFuncSetAttribute(gemm_moe<1>, cudaFuncAttributeMaxDynamicSharedMemorySize, SMEM_BYTES);
    cudaFuncSetAttribute(gemm_moe<2>, cudaFuncAttributeMaxDynamicSharedMemorySize, SMEM_BYTES);
    cudaFuncSetAttribute(gemm_moe<3>, cudaFuncAttributeMaxDynamicSharedMemorySize, SMEM_BYTES);

    // resolve device-global addresses (host-side; not graph nodes)
    float *d_xc, *d_wsu, *d_wsd, *d_wru, *d_wrd;
    cudaGetSymbolAddress((void**)&d_xc,  g_xc);
    cudaGetSymbolAddress((void**)&d_wsu, g_wsh_up);
    cudaGetSymbolAddress((void**)&d_wsd, g_wsh_dn);
    cudaGetSymbolAddress((void**)&d_wru, g_wrt_up);
    cudaGetSymbolAddress((void**)&d_wrd, g_wrt_dn);

    const int CB = 1184;  // 148 SMs * 8
    conv_tf32_kernel<<<CB, 256>>>((const float4*)x,      (float4*)d_xc,  (T_TOK * H_DIM) / 4);
    conv_tf32_kernel<<<CB, 256>>>((const float4*)Wsh_up, (float4*)d_wsu, (NE_SH * H_DIM * D_DIM) / 4);
    conv_tf32_kernel<<<CB, 256>>>((const float4*)Wsh_dn, (float4*)d_wsd, (NE_SH * D_DIM * H_DIM) / 4);
    conv_tf32_kernel<<<CB, 256>>>((const float4*)Wrt_up, (float4*)d_wru, (NE_RT * H_DIM * D_DIM) / 4);
    conv_tf32_kernel<<<CB, 256>>>((const float4*)Wrt_dn, (float4*)d_wrd, (NE_RT * D_DIM * H_DIM) / 4);

    zero_cnt_kernel<<<1, 32>>>();
    router_kernel<<<T_TOK / 8, 256>>>(x, Wr);

    gemm_moe<0><<<dim3(D_DIM / BN, T_TOK / BM, NE_SH), NTHR, SMEM_BYTES>>>(nullptr, nullptr);
    gemm_moe<1><<<dim3(D_DIM / BN, T_TOK / BM, NE_RT), NTHR, SMEM_BYTES>>>(nullptr, nullptr);
    gemm_moe<2><<<dim3(H_DIM / BN, T_TOK / BM, 1),     NTHR, SMEM_BYTES>>>(nullptr, out);
    gemm_moe<3><<<dim3(H_DIM / BN, T_TOK / BM, NE_RT), NTHR, SMEM_BYTES>>>(nullptr, out);
}

// round 8
// speedup vs baseline: 1.6217x; 1.0294x over previous
#include <cuda_runtime.h>
#include <math.h>
#include <stdint.h>

#define T_TOK 4096
#define H_DIM 2048
#define D_DIM 1024
#define NE_RT 16
#define NE_SH 2

// ---------------- scratch (device globals; no allocations) ----------------
__device__ int   g_cnt[NE_RT];
__device__ int   g_tok[NE_RT * T_TOK];
__device__ float g_gate[NE_RT * T_TOK];
__device__ float g_mid_sh[(size_t)NE_SH * T_TOK * D_DIM];
__device__ float g_mid_rt[(size_t)NE_RT * T_TOK * D_DIM];
// pre-converted (tf32-rounded) copies of inputs
__device__ float g_xc[(size_t)T_TOK * H_DIM];
__device__ float g_wsh_up[(size_t)NE_SH * H_DIM * D_DIM];
__device__ float g_wsh_dn[(size_t)NE_SH * D_DIM * H_DIM];
__device__ float g_wrt_up[(size_t)NE_RT * H_DIM * D_DIM];
__device__ float g_wrt_dn[(size_t)NE_RT * D_DIM * H_DIM];

// ---------------- helpers ----------------
__device__ __forceinline__ uint32_t f2tf(float f) {
    uint32_t u;
    asm("cvt.rna.tf32.f32 %0, %1;" : "=r"(u) : "f"(f));
    return u;
}
__device__ __forceinline__ float gelu_f(float v) {
    return 0.5f * v * (1.0f + erff(v * 0.70710678118654752440f));
}
__device__ __forceinline__ void cp16(uint32_t dst_smem, const void* src, bool pred) {
    int sz = pred ? 16 : 0;
    asm volatile("cp.async.cg.shared.global [%0], [%1], 16, %2;\n"
                 :: "r"(dst_smem), "l"(src), "r"(sz) : "memory");
}
__device__ __forceinline__ void cp_commit() {
    asm volatile("cp.async.commit_group;" ::: "memory");
}

// ---------------- merged tf32 pre-conversion (ONE launch) ----------------
struct ConvSeg { const float4* src; float4* dst; int n4; };
struct ConvArgs { ConvSeg seg[5]; };

__global__ void conv_all_kernel(ConvArgs a) {
    int stride = gridDim.x * blockDim.x;
    int t0 = blockIdx.x * blockDim.x + threadIdx.x;
#pragma unroll
    for (int s = 0; s < 5; s++) {
        const float4* src = a.seg[s].src;
        float4* dst = a.seg[s].dst;
        int n4 = a.seg[s].n4;
        for (int i = t0; i < n4; i += stride) {
            float4 v = src[i];
            float4 o;
            o.x = __uint_as_float(f2tf(v.x));
            o.y = __uint_as_float(f2tf(v.y));
            o.z = __uint_as_float(f2tf(v.z));
            o.w = __uint_as_float(f2tf(v.w));
            dst[i] = o;
        }
    }
}

// ---------------- router ----------------
__global__ void zero_cnt_kernel() {
    if (threadIdx.x < NE_RT) g_cnt[threadIdx.x] = 0;
}

__global__ void router_kernel(const float* __restrict__ x,
                              const float* __restrict__ Wr) {
    int warp = threadIdx.x >> 5;
    int lane = threadIdx.x & 31;
    int t = blockIdx.x * 8 + warp;
    if (t >= T_TOK) return;

    float acc[NE_RT];
#pragma unroll
    for (int e = 0; e < NE_RT; e++) acc[e] = 0.f;

    const float* xr = x + (size_t)t * H_DIM;
    for (int h = lane; h < H_DIM; h += 32) {
        float xv = xr[h];
        const float4* w4 = reinterpret_cast<const float4*>(Wr + (size_t)h * NE_RT);
#pragma unroll
        for (int q = 0; q < 4; q++) {
            float4 w = w4[q];
            acc[4*q+0] += xv * w.x;
            acc[4*q+1] += xv * w.y;
            acc[4*q+2] += xv * w.z;
            acc[4*q+3] += xv * w.w;
        }
    }
#pragma unroll
    for (int e = 0; e < NE_RT; e++) {
#pragma unroll
        for (int off = 16; off > 0; off >>= 1)
            acc[e] += __shfl_xor_sync(0xffffffffu, acc[e], off);
    }
    if (lane == 0) {
        float mx = acc[0];
#pragma unroll
        for (int e = 1; e < NE_RT; e++) mx = fmaxf(mx, acc[e]);
        float p[NE_RT];
        float s = 0.f;
#pragma unroll
        for (int e = 0; e < NE_RT; e++) { p[e] = expf(acc[e] - mx); s += p[e]; }
        float inv = 1.0f / s;

        int i1 = 0; float v1 = p[0];
#pragma unroll
        for (int e = 1; e < NE_RT; e++) if (p[e] > v1) { v1 = p[e]; i1 = e; }
        int i2 = -1; float v2 = -1.f;
#pragma unroll
        for (int e = 0; e < NE_RT; e++) if (e != i1 && p[e] > v2) { v2 = p[e]; i2 = e; }

        int pos = atomicAdd(&g_cnt[i1], 1);
        g_tok[i1 * T_TOK + pos]  = t;
        g_gate[i1 * T_TOK + pos] = v1 * inv;
        pos = atomicAdd(&g_cnt[i2], 1);
        g_tok[i2 * T_TOK + pos]  = t;
        g_gate[i2 * T_TOK + pos] = v2 * inv;
    }
}

// ------ 3-stage cp.async tf32 GEMM, 128x128 CTA tile, 256 thr, 64x32 warp tiles ------
// All operands PRE-CONVERTED tf32 bit patterns — zero cvt in the mainloop.
// MODE 0: mid_sh[e]  = tf32( gelu( x @ Wsh_up[e] ) )
// MODE 1: mid_rt[e,i]= tf32( gelu( x[tok] @ Wrt_up[e] ) * gate )   (gather)
// MODE 2: out        = sum_e mid_sh[e] @ Wsh_down[e]               (K fused)
// MODE 3: out[tok]  += mid_rt[e,i] @ Wrt_down[e]                   (scatter atomics)

#define BM 128
#define BN 128
#define BK 32
#define STAGES 3
#define NTHR 256
#define ASTR 36
#define BSTR 136
#define A_WORDS (BM * ASTR)               // 4608
#define B_WORDS (BK * BSTR)               // 4352
#define STAGE_WORDS (A_WORDS + B_WORDS)   // 8960
#define EPI_PITCH 132
#define SMEM_BYTES (STAGES * STAGE_WORDS * 4)

template <int MODE>
__global__ void __launch_bounds__(NTHR) gemm_moe(float* __restrict__ OUT) {
    constexpr int KTOT = (MODE == 3) ? 1024 : 2048;
    constexpr int NN   = (MODE <= 1) ? 1024 : 2048;
    constexpr int LDA  = (MODE <= 1) ? 2048 : 1024;
    constexpr int nK   = KTOT / BK;

    const int e = (MODE == 2) ? 0 : blockIdx.z;

    int cnt = T_TOK;
    if (MODE == 1 || MODE == 3) {
        cnt = g_cnt[e];
        if ((int)blockIdx.y * BM >= cnt) return;
    }

    extern __shared__ float sm[];
    __shared__ int   s_tok[BM];
    __shared__ float s_gate[BM];

    const int tid  = threadIdx.x;
    const int lane = tid & 31;
    const int warp = tid >> 5;
    const int wm   = warp >> 2;  // 0..1 (64-row band)
    const int wn   = warp & 3;   // 0..3 (32-col band)
    const int m0   = blockIdx.y * BM;
    const int n0   = blockIdx.x * BN;

    const float* Abase;
    const float* Bbase;
    if (MODE == 0 || MODE == 1) {
        Abase = g_xc;
        Bbase = (MODE == 0 ? g_wsh_up : g_wrt_up) + (size_t)e * H_DIM * D_DIM;
    } else if (MODE == 2) {
        Abase = g_mid_sh;
        Bbase = g_wsh_dn;
    } else {
        Abase = g_mid_rt + (size_t)e * T_TOK * D_DIM;
        Bbase = g_wrt_dn + (size_t)e * D_DIM * H_DIM;
    }

    // per-row table. MODE1: src token + gate. MODE3: dst token. MODE0/2: identity.
    if (tid < BM) {
        int grow = m0 + tid;
        int tok;
        float gate = 0.f;
        if (MODE == 0 || MODE == 2) {
            tok = grow;
        } else if (MODE == 1) {
            if (grow < cnt) {
                tok  = g_tok[e * T_TOK + grow];
                gate = g_gate[e * T_TOK + grow];
            } else tok = -1;
        } else {
            tok = (grow < cnt) ? g_tok[e * T_TOK + grow] : -1;
        }
        s_tok[tid]  = tok;
        s_gate[tid] = gate;
    }
    __syncthreads();

    auto load_stage = [&](int s, int k0) {
        float* As = sm + s * STAGE_WORDS;
        float* Bs = As + A_WORDS;
        const float* Ak = Abase;
        const float* Bk = Bbase;
        int kloc = k0;
        if (MODE == 2 && k0 >= 1024) {
            Ak   = g_mid_sh + (size_t)T_TOK * D_DIM;
            Bk   = g_wsh_dn + (size_t)D_DIM * H_DIM;
            kloc = k0 - 1024;
        }
        uint32_t a_sm = (uint32_t)__cvta_generic_to_shared(As);
        uint32_t b_sm = (uint32_t)__cvta_generic_to_shared(Bs);
#pragma unroll
        for (int j = 0; j < 4; j++) {             // A: 128 rows x 8 float4
            int idx = tid + NTHR * j;
            int r   = idx >> 3;
            int c4  = idx & 7;
            int tok = s_tok[r];
            bool valid;
            int  srow;
            if (MODE == 1)      { valid = tok >= 0; srow = valid ? tok : 0; }
            else if (MODE == 3) { valid = tok >= 0; srow = m0 + r; }
            else                { valid = true;     srow = m0 + r; }
            const float* src = Ak + (size_t)srow * LDA + kloc + c4 * 4;
            cp16(a_sm + (r * ASTR + c4 * 4) * 4, src, valid);
        }
#pragma unroll
        for (int j = 0; j < 4; j++) {             // B: 32 k-rows x 32 float4
            int idx = tid + NTHR * j;
            int r   = idx >> 5;
            int c4  = idx & 31;
            const float* src = Bk + (size_t)(kloc + r) * NN + n0 + c4 * 4;
            cp16(b_sm + (r * BSTR + c4 * 4) * 4, src, true);
        }
    };

    float c[4][4][4];
#pragma unroll
    for (int i = 0; i < 4; i++)
#pragma unroll
        for (int j = 0; j < 4; j++)
#pragma unroll
            for (int q = 0; q < 4; q++) c[i][j][q] = 0.f;

#pragma unroll
    for (int s = 0; s < STAGES - 1; s++) {
        load_stage(s, s * BK);
        cp_commit();
    }

    for (int ki = 0; ki < nK; ki++) {
        asm volatile("cp.async.wait_group %0;" :: "n"(STAGES - 2) : "memory");
        __syncthreads();

        const uint32_t* As = reinterpret_cast<const uint32_t*>(sm + (ki % STAGES) * STAGE_WORDS);
        const uint32_t* Bs = As + A_WORDS;

#pragma unroll
        for (int ks = 0; ks < 4; ks++) {
            const int kk = ks * 8 + (lane & 3);
            uint32_t a[4][4];
#pragma unroll
            for (int im = 0; im < 4; im++) {
                int m = wm * 64 + im * 16 + (lane >> 2);
                a[im][0] = As[m * ASTR + kk];
                a[im][1] = As[(m + 8) * ASTR + kk];
                a[im][2] = As[m * ASTR + kk + 4];
                a[im][3] = As[(m + 8) * ASTR + kk + 4];
            }
            uint32_t b[4][2];
#pragma unroll
            for (int in_ = 0; in_ < 4; in_++) {
                int n = wn * 32 + in_ * 8 + (lane >> 2);
                b[in_][0] = Bs[kk * BSTR + n];
                b[in_][1] = Bs[(kk + 4) * BSTR + n];
            }
#pragma unroll
            for (int im = 0; im < 4; im++)
#pragma unroll
                for (int in_ = 0; in_ < 4; in_++)
                    asm volatile(
                        "mma.sync.aligned.m16n8k8.row.col.f32.tf32.tf32.f32 "
                        "{%0,%1,%2,%3}, {%4,%5,%6,%7}, {%8,%9}, {%0,%1,%2,%3};"
                        : "+f"(c[im][in_][0]), "+f"(c[im][in_][1]),
                          "+f"(c[im][in_][2]), "+f"(c[im][in_][3])
                        : "r"(a[im][0]), "r"(a[im][1]), "r"(a[im][2]), "r"(a[im][3]),
                          "r"(b[in_][0]), "r"(b[in_][1]));
        }

        int kn = ki + STAGES - 1;
        if (kn < nK) load_stage(kn % STAGES, kn * BK);
        cp_commit();
    }

    // ---- epilogue: registers -> smem (pitch 132) -> coalesced/atomic stores ----
    __syncthreads();
    float* ep = sm;
#pragma unroll
    for (int im = 0; im < 4; im++) {
#pragma unroll
        for (int in_ = 0; in_ < 4; in_++) {
#pragma unroll
            for (int half = 0; half < 2; half++) {
                int rr = wm * 64 + im * 16 + half * 8 + (lane >> 2);
                int cc = wn * 32 + in_ * 8 + 2 * (lane & 3);
                float v0 = c[im][in_][half * 2 + 0];
                float v1 = c[im][in_][half * 2 + 1];
                if (MODE <= 1) {
                    v0 = gelu_f(v0);
                    v1 = gelu_f(v1);
                    if (MODE == 1) {
                        float gate = s_gate[rr];
                        v0 *= gate; v1 *= gate;
                    }
                    v0 = __uint_as_float(f2tf(v0));   // store tf32-rounded
                    v1 = __uint_as_float(f2tf(v1));
                }
                ep[rr * EPI_PITCH + cc]     = v0;
                ep[rr * EPI_PITCH + cc + 1] = v1;
            }
        }
    }
    __syncthreads();

#pragma unroll
    for (int jj = 0; jj < 16; jj++) {
        int idx = tid + NTHR * jj;
        int r   = idx >> 5;
        int c4  = idx & 31;
        float4 v = *reinterpret_cast<float4*>(&ep[r * EPI_PITCH + c4 * 4]);
        int grow = m0 + r;
        int gcol = n0 + c4 * 4;
        if (MODE == 0) {
            *reinterpret_cast<float4*>(
                g_mid_sh + (size_t)e * T_TOK * D_DIM + (size_t)grow * D_DIM + gcol) = v;
        } else if (MODE == 1) {
            if (s_tok[r] >= 0)
                *reinterpret_cast<float4*>(
                    g_mid_rt + ((size_t)e * T_TOK + grow) * D_DIM + gcol) = v;
        } else if (MODE == 2) {
            *reinterpret_cast<float4*>(OUT + (size_t)grow * H_DIM + gcol) = v;
        } else {
            int tok = s_tok[r];
            if (tok >= 0) {
                float* dst = OUT + (size_t)tok * H_DIM + gcol;
                atomicAdd(dst + 0, v.x);
                atomicAdd(dst + 1, v.y);
                atomicAdd(dst + 2, v.z);
                atomicAdd(dst + 3, v.w);
            }
        }
    }
}

// ---------------- launch ----------------
extern "C" void kernel_launch(void* const* d_in, const int* in_sizes, int n_in,
                              void* d_out, int out_size) {
    const float* x      = (const float*)d_in[0];
    const float* Wsh_up = (const float*)d_in[1];
    const float* Wsh_dn = (const float*)d_in[2];
    const float* Wrt_up = (const float*)d_in[3];
    const float* Wrt_dn = (const float*)d_in[4];
    const float* Wr     = (const float*)d_in[5];
    float* out = (float*)d_out;

    cudaFuncSetAttribute(gemm_moe<0>, cudaFuncAttributeMaxDynamicSharedMemorySize, SMEM_BYTES);
    cudaFuncSetAttribute(gemm_moe<1>, cudaFuncAttributeMaxDynamicSharedMemorySize, SMEM_BYTES);
    cudaFuncSetAttribute(gemm_moe<2>, cudaFuncAttributeMaxDynamicSharedMemorySize, SMEM_BYTES);
    cudaFuncSetAttribute(gemm_moe<3>, cudaFuncAttributeMaxDynamicSharedMemorySize, SMEM_BYTES);

    float *d_xc, *d_wsu, *d_wsd, *d_wru, *d_wrd;
    cudaGetSymbolAddress((void**)&d_xc,  g_xc);
    cudaGetSymbolAddress((void**)&d_wsu, g_wsh_up);
    cudaGetSymbolAddress((void**)&d_wsd, g_wsh_dn);
    cudaGetSymbolAddress((void**)&d_wru, g_wrt_up);
    cudaGetSymbolAddress((void**)&d_wrd, g_wrt_dn);

    ConvArgs ca;
    ca.seg[0] = { (const float4*)x,      (float4*)d_xc,  (T_TOK * H_DIM) / 4 };
    ca.seg[1] = { (const float4*)Wsh_up, (float4*)d_wsu, (NE_SH * H_DIM * D_DIM) / 4 };
    ca.seg[2] = { (const float4*)Wsh_dn, (float4*)d_wsd, (NE_SH * D_DIM * H_DIM) / 4 };
    ca.seg[3] = { (const float4*)Wrt_up, (float4*)d_wru, (NE_RT * H_DIM * D_DIM) / 4 };
    ca.seg[4] = { (const float4*)Wrt_dn, (float4*)d_wrd, (NE_RT * D_DIM * H_DIM) / 4 };
    conv_all_kernel<<<1184, 256>>>(ca);

    zero_cnt_kernel<<<1, 32>>>();
    router_kernel<<<T_TOK / 8, 256>>>(x, Wr);

    gemm_moe<0><<<dim3(D_DIM / BN, T_TOK / BM, NE_SH), NTHR, SMEM_BYTES>>>(nullptr);
    gemm_moe<1><<<dim3(D_DIM / BN, T_TOK / BM, NE_RT), NTHR, SMEM_BYTES>>>(nullptr);
    gemm_moe<2><<<dim3(H_DIM / BN, T_TOK / BM, 1),     NTHR, SMEM_BYTES>>>(out);
    gemm_moe<3><<<dim3(H_DIM / BN, T_TOK / BM, NE_RT), NTHR, SMEM_BYTES>>>(out);
}

// round 9
// speedup vs baseline: 1.6799x; 1.0359x over previous
#include <cuda_runtime.h>
#include <math.h>
#include <stdint.h>

#define T_TOK 4096
#define H_DIM 2048
#define D_DIM 1024
#define NE_RT 16
#define NE_SH 2

// ---------------- scratch (device globals; no allocations) ----------------
__device__ int   g_cnt[NE_RT];
__device__ int   g_tok[NE_RT * T_TOK];
__device__ float g_gate[NE_RT * T_TOK];
__device__ int   g_assign[2 * T_TOK];                     // per-token bucket slots
__device__ float g_mid_sh[(size_t)NE_SH * T_TOK * D_DIM];
__device__ float g_mid_rt[(size_t)NE_RT * T_TOK * D_DIM];
__device__ float g_out_rt[(size_t)NE_RT * T_TOK * H_DIM]; // routed down buckets
// pre-converted (tf32-rounded) copies of inputs
__device__ float g_xc[(size_t)T_TOK * H_DIM];
__device__ float g_wsh_up[(size_t)NE_SH * H_DIM * D_DIM];
__device__ float g_wsh_dn[(size_t)NE_SH * D_DIM * H_DIM];
__device__ float g_wrt_up[(size_t)NE_RT * H_DIM * D_DIM];
__device__ float g_wrt_dn[(size_t)NE_RT * D_DIM * H_DIM];

// ---------------- helpers ----------------
__device__ __forceinline__ uint32_t f2tf(float f) {
    uint32_t u;
    asm("cvt.rna.tf32.f32 %0, %1;" : "=r"(u) : "f"(f));
    return u;
}
__device__ __forceinline__ float gelu_f(float v) {
    return 0.5f * v * (1.0f + erff(v * 0.70710678118654752440f));
}
__device__ __forceinline__ void cp16(uint32_t dst_smem, const void* src, bool pred) {
    int sz = pred ? 16 : 0;
    asm volatile("cp.async.cg.shared.global [%0], [%1], 16, %2;\n"
                 :: "r"(dst_smem), "l"(src), "r"(sz) : "memory");
}
__device__ __forceinline__ void cp_commit() {
    asm volatile("cp.async.commit_group;" ::: "memory");
}

// ---------------- merged tf32 pre-conversion + cnt zero (ONE launch) ----------------
struct ConvSeg { const float4* src; float4* dst; int n4; };
struct ConvArgs { ConvSeg seg[5]; };

__global__ void conv_all_kernel(ConvArgs a) {
    if (blockIdx.x == 0 && threadIdx.x < NE_RT) g_cnt[threadIdx.x] = 0;
    int stride = gridDim.x * blockDim.x;
    int t0 = blockIdx.x * blockDim.x + threadIdx.x;
#pragma unroll
    for (int s = 0; s < 5; s++) {
        const float4* src = a.seg[s].src;
        float4* dst = a.seg[s].dst;
        int n4 = a.seg[s].n4;
        for (int i = t0; i < n4; i += stride) {
            float4 v = src[i];
            float4 o;
            o.x = __uint_as_float(f2tf(v.x));
            o.y = __uint_as_float(f2tf(v.y));
            o.z = __uint_as_float(f2tf(v.z));
            o.w = __uint_as_float(f2tf(v.w));
            dst[i] = o;
        }
    }
}

// ---------------- router ----------------
__global__ void router_kernel(const float* __restrict__ x,
                              const float* __restrict__ Wr) {
    int warp = threadIdx.x >> 5;
    int lane = threadIdx.x & 31;
    int t = blockIdx.x * 8 + warp;
    if (t >= T_TOK) return;

    float acc[NE_RT];
#pragma unroll
    for (int e = 0; e < NE_RT; e++) acc[e] = 0.f;

    const float* xr = x + (size_t)t * H_DIM;
    for (int h = lane; h < H_DIM; h += 32) {
        float xv = xr[h];
        const float4* w4 = reinterpret_cast<const float4*>(Wr + (size_t)h * NE_RT);
#pragma unroll
        for (int q = 0; q < 4; q++) {
            float4 w = w4[q];
            acc[4*q+0] += xv * w.x;
            acc[4*q+1] += xv * w.y;
            acc[4*q+2] += xv * w.z;
            acc[4*q+3] += xv * w.w;
        }
    }
#pragma unroll
    for (int e = 0; e < NE_RT; e++) {
#pragma unroll
        for (int off = 16; off > 0; off >>= 1)
            acc[e] += __shfl_xor_sync(0xffffffffu, acc[e], off);
    }
    if (lane == 0) {
        float mx = acc[0];
#pragma unroll
        for (int e = 1; e < NE_RT; e++) mx = fmaxf(mx, acc[e]);
        float p[NE_RT];
        float s = 0.f;
#pragma unroll
        for (int e = 0; e < NE_RT; e++) { p[e] = expf(acc[e] - mx); s += p[e]; }
        float inv = 1.0f / s;

        int i1 = 0; float v1 = p[0];
#pragma unroll
        for (int e = 1; e < NE_RT; e++) if (p[e] > v1) { v1 = p[e]; i1 = e; }
        int i2 = -1; float v2 = -1.f;
#pragma unroll
        for (int e = 0; e < NE_RT; e++) if (e != i1 && p[e] > v2) { v2 = p[e]; i2 = e; }

        int pos = atomicAdd(&g_cnt[i1], 1);
        g_tok[i1 * T_TOK + pos]  = t;
        g_gate[i1 * T_TOK + pos] = v1 * inv;
        g_assign[2 * t]          = i1 * T_TOK + pos;
        pos = atomicAdd(&g_cnt[i2], 1);
        g_tok[i2 * T_TOK + pos]  = t;
        g_gate[i2 * T_TOK + pos] = v2 * inv;
        g_assign[2 * t + 1]      = i2 * T_TOK + pos;
    }
}

// ------ unified 3-stage cp.async tf32 GEMM, 128x128 tile, 64x32 warp tiles ------
// PHASE 0 (up, gridz=18): z<2  shared e=z : mid_sh = tf32(gelu(x @ Wsh_up[e]))
//                         z>=2 routed e=z-2: mid_rt = tf32(gelu(x[tok] @ Wrt_up[e])*gate)
// PHASE 1 (down, gridz=17): z<16 routed: out_rt[e] = mid_rt[e] @ Wrt_down[e] (bucket store)
//                           z==16 shared: OUT = sum_e mid_sh[e] @ Wsh_down[e] (K fused)

#define BM 128
#define BN 128
#define BK 32
#define STAGES 3
#define NTHR 256
#define ASTR 36
#define BSTR 136
#define A_WORDS (BM * ASTR)
#define B_WORDS (BK * BSTR)
#define STAGE_WORDS (A_WORDS + B_WORDS)
#define EPI_PITCH 132
#define SMEM_BYTES (STAGES * STAGE_WORDS * 4)

template <int PHASE>
__global__ void __launch_bounds__(NTHR) gemm_fused(float* __restrict__ OUT) {
    constexpr int NN  = (PHASE == 0) ? 1024 : 2048;
    constexpr int LDA = (PHASE == 0) ? 2048 : 1024;

    const int z  = blockIdx.z;
    const bool sh = (PHASE == 0) ? (z < 2) : (z == 16);
    const int e  = (PHASE == 0) ? (sh ? z : z - 2) : z;

    const int KTOT = (PHASE == 1 && !sh) ? 1024 : 2048;
    const int nK   = KTOT / BK;

    const int m0 = blockIdx.y * BM;
    const int n0 = blockIdx.x * BN;

    int cnt = T_TOK;
    if (!sh) {
        cnt = g_cnt[e];
        if (m0 >= cnt) return;
    }

    extern __shared__ float sm[];
    __shared__ int   s_tok[BM];
    __shared__ float s_gate[BM];

    const int tid  = threadIdx.x;
    const int lane = tid & 31;
    const int warp = tid >> 5;
    const int wm   = warp >> 2;
    const int wn   = warp & 3;

    const float* Abase;
    const float* Bbase;
    if (PHASE == 0) {
        Abase = g_xc;
        Bbase = (sh ? g_wsh_up : g_wrt_up) + (size_t)e * H_DIM * D_DIM;
    } else {
        if (sh) { Abase = g_mid_sh; Bbase = g_wsh_dn; }
        else {
            Abase = g_mid_rt + (size_t)e * T_TOK * D_DIM;
            Bbase = g_wrt_dn + (size_t)e * D_DIM * H_DIM;
        }
    }

    // per-row table. up-routed: src token + gate; down-routed: validity; shared: identity.
    if (tid < BM) {
        int grow = m0 + tid;
        int tok;
        float gate = 0.f;
        if (sh) {
            tok = grow;
        } else if (PHASE == 0) {
            if (grow < cnt) {
                tok  = g_tok[e * T_TOK + grow];
                gate = g_gate[e * T_TOK + grow];
            } else tok = -1;
        } else {
            tok = (grow < cnt) ? grow : -1;
        }
        s_tok[tid]  = tok;
        s_gate[tid] = gate;
    }
    __syncthreads();

    // hoist per-thread A staging coords (invariant across k)
    int  a_srow[4];
    bool a_valid[4];
#pragma unroll
    for (int j = 0; j < 4; j++) {
        int r   = (tid + NTHR * j) >> 3;
        int tok = s_tok[r];
        if (PHASE == 0 && !sh) { a_valid[j] = tok >= 0; a_srow[j] = a_valid[j] ? tok : 0; }
        else                   { a_valid[j] = tok >= 0; a_srow[j] = m0 + r; }
    }

    auto load_stage = [&](int s, int k0) {
        float* As = sm + s * STAGE_WORDS;
        float* Bs = As + A_WORDS;
        const float* Ak = Abase;
        const float* Bk = Bbase;
        int kloc = k0;
        if (PHASE == 1 && sh && k0 >= 1024) {   // shared-down fused K: switch expert
            Ak   = g_mid_sh + (size_t)T_TOK * D_DIM;
            Bk   = g_wsh_dn + (size_t)D_DIM * H_DIM;
            kloc = k0 - 1024;
        }
        uint32_t a_sm = (uint32_t)__cvta_generic_to_shared(As);
        uint32_t b_sm = (uint32_t)__cvta_generic_to_shared(Bs);
#pragma unroll
        for (int j = 0; j < 4; j++) {
            int idx = tid + NTHR * j;
            int r   = idx >> 3;
            int c4  = idx & 7;
            const float* src = Ak + (size_t)a_srow[j] * LDA + kloc + c4 * 4;
            cp16(a_sm + (r * ASTR + c4 * 4) * 4, src, a_valid[j]);
        }
#pragma unroll
        for (int j = 0; j < 4; j++) {
            int idx = tid + NTHR * j;
            int r   = idx >> 5;
            int c4  = idx & 31;
            const float* src = Bk + (size_t)(kloc + r) * NN + n0 + c4 * 4;
            cp16(b_sm + (r * BSTR + c4 * 4) * 4, src, true);
        }
    };

    float c[4][4][4];
#pragma unroll
    for (int i = 0; i < 4; i++)
#pragma unroll
        for (int j = 0; j < 4; j++)
#pragma unroll
            for (int q = 0; q < 4; q++) c[i][j][q] = 0.f;

#pragma unroll
    for (int s = 0; s < STAGES - 1; s++) {
        load_stage(s, s * BK);
        cp_commit();
    }

    for (int ki = 0; ki < nK; ki++) {
        asm volatile("cp.async.wait_group %0;" :: "n"(STAGES - 2) : "memory");
        __syncthreads();

        const uint32_t* As = reinterpret_cast<const uint32_t*>(sm + (ki % STAGES) * STAGE_WORDS);
        const uint32_t* Bs = As + A_WORDS;

#pragma unroll
        for (int ks = 0; ks < 4; ks++) {
            const int kk = ks * 8 + (lane & 3);
            uint32_t a[4][4];
#pragma unroll
            for (int im = 0; im < 4; im++) {
                int m = wm * 64 + im * 16 + (lane >> 2);
                a[im][0] = As[m * ASTR + kk];
                a[im][1] = As[(m + 8) * ASTR + kk];
                a[im][2] = As[m * ASTR + kk + 4];
                a[im][3] = As[(m + 8) * ASTR + kk + 4];
            }
            uint32_t b[4][2];
#pragma unroll
            for (int in_ = 0; in_ < 4; in_++) {
                int n = wn * 32 + in_ * 8 + (lane >> 2);
                b[in_][0] = Bs[kk * BSTR + n];
                b[in_][1] = Bs[(kk + 4) * BSTR + n];
            }
#pragma unroll
            for (int im = 0; im < 4; im++)
#pragma unroll
                for (int in_ = 0; in_ < 4; in_++)
                    asm volatile(
                        "mma.sync.aligned.m16n8k8.row.col.f32.tf32.tf32.f32 "
                        "{%0,%1,%2,%3}, {%4,%5,%6,%7}, {%8,%9}, {%0,%1,%2,%3};"
                        : "+f"(c[im][in_][0]), "+f"(c[im][in_][1]),
                          "+f"(c[im][in_][2]), "+f"(c[im][in_][3])
                        : "r"(a[im][0]), "r"(a[im][1]), "r"(a[im][2]), "r"(a[im][3]),
                          "r"(b[in_][0]), "r"(b[in_][1]));
        }

        int kn = ki + STAGES - 1;
        if (kn < nK) load_stage(kn % STAGES, kn * BK);
        cp_commit();
    }

    // ---- epilogue: registers -> smem -> coalesced stores (no atomics) ----
    __syncthreads();
    float* ep = sm;
#pragma unroll
    for (int im = 0; im < 4; im++) {
#pragma unroll
        for (int in_ = 0; in_ < 4; in_++) {
#pragma unroll
            for (int half = 0; half < 2; half++) {
                int rr = wm * 64 + im * 16 + half * 8 + (lane >> 2);
                int cc = wn * 32 + in_ * 8 + 2 * (lane & 3);
                float v0 = c[im][in_][half * 2 + 0];
                float v1 = c[im][in_][half * 2 + 1];
                if (PHASE == 0) {
                    v0 = gelu_f(v0);
                    v1 = gelu_f(v1);
                    if (!sh) {
                        float gate = s_gate[rr];
                        v0 *= gate; v1 *= gate;
                    }
                    v0 = __uint_as_float(f2tf(v0));   // store tf32-rounded
                    v1 = __uint_as_float(f2tf(v1));
                }
                ep[rr * EPI_PITCH + cc]     = v0;
                ep[rr * EPI_PITCH + cc + 1] = v1;
            }
        }
    }
    __syncthreads();

#pragma unroll
    for (int jj = 0; jj < 16; jj++) {
        int idx = tid + NTHR * jj;
        int r   = idx >> 5;
        int c4  = idx & 31;
        float4 v = *reinterpret_cast<float4*>(&ep[r * EPI_PITCH + c4 * 4]);
        int grow = m0 + r;
        int gcol = n0 + c4 * 4;
        if (PHASE == 0) {
            if (sh) {
                *reinterpret_cast<float4*>(
                    g_mid_sh + (size_t)e * T_TOK * D_DIM + (size_t)grow * D_DIM + gcol) = v;
            } else if (s_tok[r] >= 0) {
                *reinterpret_cast<float4*>(
                    g_mid_rt + ((size_t)e * T_TOK + grow) * D_DIM + gcol) = v;
            }
        } else {
            if (sh) {
                *reinterpret_cast<float4*>(OUT + (size_t)grow * H_DIM + gcol) = v;
            } else if (s_tok[r] >= 0) {
                *reinterpret_cast<float4*>(
                    g_out_rt + ((size_t)e * T_TOK + grow) * H_DIM + gcol) = v;
            }
        }
    }
}

// ---------------- final combine: out[t] += bucket rows of t's two experts ----------------
__global__ void combine_kernel(float4* __restrict__ out) {
    const int HQ = H_DIM / 4;
    int idx = blockIdx.x * blockDim.x + threadIdx.x;
    if (idx >= T_TOK * HQ) return;
    int t = idx >> 9;           // / HQ (512)
    int c = idx & (HQ - 1);
    int a0 = g_assign[2 * t];
    int a1 = g_assign[2 * t + 1];
    const float4* rt = reinterpret_cast<const float4*>(g_out_rt);
    float4 o  = out[idx];
    float4 r0 = rt[(size_t)a0 * HQ + c];
    float4 r1 = rt[(size_t)a1 * HQ + c];
    o.x += r0.x + r1.x;
    o.y += r0.y + r1.y;
    o.z += r0.z + r1.z;
    o.w += r0.w + r1.w;
    out[idx] = o;
}

// ---------------- launch ----------------
extern "C" void kernel_launch(void* const* d_in, const int* in_sizes, int n_in,
                              void* d_out, int out_size) {
    const float* x      = (const float*)d_in[0];
    const float* Wsh_up = (const float*)d_in[1];
    const float* Wsh_dn = (const float*)d_in[2];
    const float* Wrt_up = (const float*)d_in[3];
    const float* Wrt_dn = (const float*)d_in[4];
    const float* Wr     = (const float*)d_in[5];
    float* out = (float*)d_out;

    cudaFuncSetAttribute(gemm_fused<0>, cudaFuncAttributeMaxDynamicSharedMemorySize, SMEM_BYTES);
    cudaFuncSetAttribute(gemm_fused<1>, cudaFuncAttributeMaxDynamicSharedMemorySize, SMEM_BYTES);

    float *d_xc, *d_wsu, *d_wsd, *d_wru, *d_wrd;
    cudaGetSymbolAddress((void**)&d_xc,  g_xc);
    cudaGetSymbolAddress((void**)&d_wsu, g_wsh_up);
    cudaGetSymbolAddress((void**)&d_wsd, g_wsh_dn);
    cudaGetSymbolAddress((void**)&d_wru, g_wrt_up);
    cudaGetSymbolAddress((void**)&d_wrd, g_wrt_dn);

    ConvArgs ca;
    ca.seg[0] = { (const float4*)x,      (float4*)d_xc,  (T_TOK * H_DIM) / 4 };
    ca.seg[1] = { (const float4*)Wsh_up, (float4*)d_wsu, (NE_SH * H_DIM * D_DIM) / 4 };
    ca.seg[2] = { (const float4*)Wsh_dn, (float4*)d_wsd, (NE_SH * D_DIM * H_DIM) / 4 };
    ca.seg[3] = { (const float4*)Wrt_up, (float4*)d_wru, (NE_RT * H_DIM * D_DIM) / 4 };
    ca.seg[4] = { (const float4*)Wrt_dn, (float4*)d_wrd, (NE_RT * D_DIM * H_DIM) / 4 };
    conv_all_kernel<<<1184, 256>>>(ca);

    router_kernel<<<T_TOK / 8, 256>>>(x, Wr);

    gemm_fused<0><<<dim3(D_DIM / BN, T_TOK / BM, NE_SH + NE_RT), NTHR, SMEM_BYTES>>>(nullptr);
    gemm_fused<1><<<dim3(H_DIM / BN, T_TOK / BM, NE_RT + 1),     NTHR, SMEM_BYTES>>>(out);

    combine_kernel<<<(T_TOK * (H_DIM / 4)) / 256, 256>>>((float4*)out);
}

// round 10
// speedup vs baseline: 1.7952x; 1.0686x over previous
#include <cuda_runtime.h>
#include <math.h>
#include <stdint.h>

#define T_TOK 4096
#define H_DIM 2048
#define D_DIM 1024
#define NE_RT 16
#define NE_SH 2

// ---------------- scratch (device globals; no allocations) ----------------
__device__ int   g_cnt[NE_RT];
__device__ int   g_tok[NE_RT * T_TOK];
__device__ float g_gate[NE_RT * T_TOK];
__device__ int   g_assign[2 * T_TOK];                     // per-token bucket slots
__device__ float g_mid_sh[(size_t)NE_SH * T_TOK * D_DIM];
__device__ float g_mid_rt[(size_t)NE_RT * T_TOK * D_DIM];
__device__ float g_out_rt[(size_t)NE_RT * T_TOK * H_DIM]; // routed down buckets
__device__ float g_xc[(size_t)T_TOK * H_DIM];             // tf32-rounded x (reused 18x)

// ---------------- helpers ----------------
__device__ __forceinline__ uint32_t f2tf(float f) {
    uint32_t u;
    asm("cvt.rna.tf32.f32 %0, %1;" : "=r"(u) : "f"(f));
    return u;
}
__device__ __forceinline__ uint32_t f2tf_u(uint32_t raw) {
    uint32_t u;
    asm("cvt.rna.tf32.f32 %0, %1;" : "=r"(u) : "f"(__uint_as_float(raw)));
    return u;
}
__device__ __forceinline__ float gelu_f(float v) {
    return 0.5f * v * (1.0f + erff(v * 0.70710678118654752440f));
}
__device__ __forceinline__ void cp16(uint32_t dst_smem, const void* src, bool pred) {
    int sz = pred ? 16 : 0;
    asm volatile("cp.async.cg.shared.global [%0], [%1], 16, %2;\n"
                 :: "r"(dst_smem), "l"(src), "r"(sz) : "memory");
}
__device__ __forceinline__ void cp_commit() {
    asm volatile("cp.async.commit_group;" ::: "memory");
}

// ---------------- x pre-conversion (only reused tensor) + cnt zero ----------------
__global__ void conv_x_kernel(const float4* __restrict__ src, float4* __restrict__ dst) {
    if (blockIdx.x == 0 && threadIdx.x < NE_RT) g_cnt[threadIdx.x] = 0;
    const int n4 = (T_TOK * H_DIM) / 4;
    int stride = gridDim.x * blockDim.x;
    for (int i = blockIdx.x * blockDim.x + threadIdx.x; i < n4; i += stride) {
        float4 v = src[i];
        float4 o;
        o.x = __uint_as_float(f2tf(v.x));
        o.y = __uint_as_float(f2tf(v.y));
        o.z = __uint_as_float(f2tf(v.z));
        o.w = __uint_as_float(f2tf(v.w));
        dst[i] = o;
    }
}

// ---------------- router ----------------
__global__ void router_kernel(const float* __restrict__ x,
                              const float* __restrict__ Wr) {
    int warp = threadIdx.x >> 5;
    int lane = threadIdx.x & 31;
    int t = blockIdx.x * 8 + warp;
    if (t >= T_TOK) return;

    float acc[NE_RT];
#pragma unroll
    for (int e = 0; e < NE_RT; e++) acc[e] = 0.f;

    const float* xr = x + (size_t)t * H_DIM;
    for (int h = lane; h < H_DIM; h += 32) {
        float xv = xr[h];
        const float4* w4 = reinterpret_cast<const float4*>(Wr + (size_t)h * NE_RT);
#pragma unroll
        for (int q = 0; q < 4; q++) {
            float4 w = w4[q];
            acc[4*q+0] += xv * w.x;
            acc[4*q+1] += xv * w.y;
            acc[4*q+2] += xv * w.z;
            acc[4*q+3] += xv * w.w;
        }
    }
#pragma unroll
    for (int e = 0; e < NE_RT; e++) {
#pragma unroll
        for (int off = 16; off > 0; off >>= 1)
            acc[e] += __shfl_xor_sync(0xffffffffu, acc[e], off);
    }
    if (lane == 0) {
        float mx = acc[0];
#pragma unroll
        for (int e = 1; e < NE_RT; e++) mx = fmaxf(mx, acc[e]);
        float p[NE_RT];
        float s = 0.f;
#pragma unroll
        for (int e = 0; e < NE_RT; e++) { p[e] = expf(acc[e] - mx); s += p[e]; }
        float inv = 1.0f / s;

        int i1 = 0; float v1 = p[0];
#pragma unroll
        for (int e = 1; e < NE_RT; e++) if (p[e] > v1) { v1 = p[e]; i1 = e; }
        int i2 = -1; float v2 = -1.f;
#pragma unroll
        for (int e = 0; e < NE_RT; e++) if (e != i1 && p[e] > v2) { v2 = p[e]; i2 = e; }

        int pos = atomicAdd(&g_cnt[i1], 1);
        g_tok[i1 * T_TOK + pos]  = t;
        g_gate[i1 * T_TOK + pos] = v1 * inv;
        g_assign[2 * t]          = i1 * T_TOK + pos;
        pos = atomicAdd(&g_cnt[i2], 1);
        g_tok[i2 * T_TOK + pos]  = t;
        g_gate[i2 * T_TOK + pos] = v2 * inv;
        g_assign[2 * t + 1]      = i2 * T_TOK + pos;
    }
}

// ------ unified 3-stage cp.async tf32 GEMM, 128x128 tile, 64x32 warp tiles ------
// A operands are tf32 already (g_xc / mids); B = RAW weights, cvt.rna applied
// at fragment-load time (8 cvts per ks, 32 per chunk).
// PHASE 0 (up, gridz=18): z<2  shared e=z : mid_sh = tf32(gelu(x @ Wsh_up[e]))
//                         z>=2 routed e=z-2: mid_rt = tf32(gelu(x[tok] @ Wrt_up[e])*gate)
// PHASE 1 (down, gridz=17): z<16 routed: out_rt[e] = mid_rt[e] @ Wrt_down[e]
//                           z==16 shared: OUT = sum_e mid_sh[e] @ Wsh_down[e] (K fused)

#define BM 128
#define BN 128
#define BK 32
#define STAGES 3
#define NTHR 256
#define ASTR 36
#define BSTR 136
#define A_WORDS (BM * ASTR)
#define B_WORDS (BK * BSTR)
#define STAGE_WORDS (A_WORDS + B_WORDS)
#define EPI_PITCH 132
#define SMEM_BYTES (STAGES * STAGE_WORDS * 4)

template <int PHASE>
__global__ void __launch_bounds__(NTHR) gemm_fused(const float* __restrict__ Wb0,
                                                   const float* __restrict__ Wb1,
                                                   float* __restrict__ OUT) {
    constexpr int NN  = (PHASE == 0) ? 1024 : 2048;
    constexpr int LDA = (PHASE == 0) ? 2048 : 1024;

    const int z  = blockIdx.z;
    const bool sh = (PHASE == 0) ? (z < 2) : (z == 16);
    const int e  = (PHASE == 0) ? (sh ? z : z - 2) : z;

    const int KTOT = (PHASE == 1 && !sh) ? 1024 : 2048;
    const int nK   = KTOT / BK;

    const int m0 = blockIdx.y * BM;
    const int n0 = blockIdx.x * BN;

    int cnt = T_TOK;
    if (!sh) {
        cnt = g_cnt[e];
        if (m0 >= cnt) return;
    }

    extern __shared__ float sm[];
    __shared__ int   s_tok[BM];
    __shared__ float s_gate[BM];

    const int tid  = threadIdx.x;
    const int lane = tid & 31;
    const int warp = tid >> 5;
    const int wm   = warp >> 2;
    const int wn   = warp & 3;

    // A base (always tf32 bit patterns); B base = raw weights
    const float* Abase;
    const float* Bbase;
    if (PHASE == 0) {
        Abase = g_xc;
        Bbase = (sh ? Wb0 : Wb1) + (size_t)e * H_DIM * D_DIM;   // Wb0=Wsh_up, Wb1=Wrt_up
    } else {
        if (sh) { Abase = g_mid_sh; Bbase = Wb1; }              // Wb1=Wsh_dn
        else {
            Abase = g_mid_rt + (size_t)e * T_TOK * D_DIM;
            Bbase = Wb0 + (size_t)e * D_DIM * H_DIM;            // Wb0=Wrt_dn
        }
    }

    // per-row table. up-routed: src token + gate; down-routed: validity; shared: identity.
    if (tid < BM) {
        int grow = m0 + tid;
        int tok;
        float gate = 0.f;
        if (sh) {
            tok = grow;
        } else if (PHASE == 0) {
            if (grow < cnt) {
                tok  = g_tok[e * T_TOK + grow];
                gate = g_gate[e * T_TOK + grow];
            } else tok = -1;
        } else {
            tok = (grow < cnt) ? grow : -1;
        }
        s_tok[tid]  = tok;
        s_gate[tid] = gate;
    }
    __syncthreads();

    // hoist per-thread A staging coords (invariant across k)
    int  a_srow[4];
    bool a_valid[4];
#pragma unroll
    for (int j = 0; j < 4; j++) {
        int r   = (tid + NTHR * j) >> 3;
        int tok = s_tok[r];
        if (PHASE == 0 && !sh) { a_valid[j] = tok >= 0; a_srow[j] = a_valid[j] ? tok : 0; }
        else                   { a_valid[j] = tok >= 0; a_srow[j] = m0 + r; }
    }

    auto load_stage = [&](int s, int k0) {
        float* As = sm + s * STAGE_WORDS;
        float* Bs = As + A_WORDS;
        const float* Ak = Abase;
        const float* Bk = Bbase;
        int kloc = k0;
        if (PHASE == 1 && sh && k0 >= 1024) {   // shared-down fused K: switch expert
            Ak   = g_mid_sh + (size_t)T_TOK * D_DIM;
            Bk   = Wb1 + (size_t)D_DIM * H_DIM;
            kloc = k0 - 1024;
        }
        uint32_t a_sm = (uint32_t)__cvta_generic_to_shared(As);
        uint32_t b_sm = (uint32_t)__cvta_generic_to_shared(Bs);
#pragma unroll
        for (int j = 0; j < 4; j++) {
            int idx = tid + NTHR * j;
            int r   = idx >> 3;
            int c4  = idx & 7;
            const float* src = Ak + (size_t)a_srow[j] * LDA + kloc + c4 * 4;
            cp16(a_sm + (r * ASTR + c4 * 4) * 4, src, a_valid[j]);
        }
#pragma unroll
        for (int j = 0; j < 4; j++) {
            int idx = tid + NTHR * j;
            int r   = idx >> 5;
            int c4  = idx & 31;
            const float* src = Bk + (size_t)(kloc + r) * NN + n0 + c4 * 4;
            cp16(b_sm + (r * BSTR + c4 * 4) * 4, src, true);
        }
    };

    float c[4][4][4];
#pragma unroll
    for (int i = 0; i < 4; i++)
#pragma unroll
        for (int j = 0; j < 4; j++)
#pragma unroll
            for (int q = 0; q < 4; q++) c[i][j][q] = 0.f;

#pragma unroll
    for (int s = 0; s < STAGES - 1; s++) {
        load_stage(s, s * BK);
        cp_commit();
    }

    for (int ki = 0; ki < nK; ki++) {
        asm volatile("cp.async.wait_group %0;" :: "n"(STAGES - 2) : "memory");
        __syncthreads();

        const uint32_t* As = reinterpret_cast<const uint32_t*>(sm + (ki % STAGES) * STAGE_WORDS);
        const uint32_t* Bs = As + A_WORDS;

#pragma unroll
        for (int ks = 0; ks < 4; ks++) {
            const int kk = ks * 8 + (lane & 3);
            uint32_t a[4][4];
#pragma unroll
            for (int im = 0; im < 4; im++) {
                int m = wm * 64 + im * 16 + (lane >> 2);
                a[im][0] = As[m * ASTR + kk];
                a[im][1] = As[(m + 8) * ASTR + kk];
                a[im][2] = As[m * ASTR + kk + 4];
                a[im][3] = As[(m + 8) * ASTR + kk + 4];
            }
            uint32_t b[4][2];
#pragma unroll
            for (int in_ = 0; in_ < 4; in_++) {
                int n = wn * 32 + in_ * 8 + (lane >> 2);
                b[in_][0] = f2tf_u(Bs[kk * BSTR + n]);        // raw weight -> tf32 (rna)
                b[in_][1] = f2tf_u(Bs[(kk + 4) * BSTR + n]);
            }
#pragma unroll
            for (int im = 0; im < 4; im++)
#pragma unroll
                for (int in_ = 0; in_ < 4; in_++)
                    asm volatile(
                        "mma.sync.aligned.m16n8k8.row.col.f32.tf32.tf32.f32 "
                        "{%0,%1,%2,%3}, {%4,%5,%6,%7}, {%8,%9}, {%0,%1,%2,%3};"
                        : "+f"(c[im][in_][0]), "+f"(c[im][in_][1]),
                          "+f"(c[im][in_][2]), "+f"(c[im][in_][3])
                        : "r"(a[im][0]), "r"(a[im][1]), "r"(a[im][2]), "r"(a[im][3]),
                          "r"(b[in_][0]), "r"(b[in_][1]));
        }

        int kn = ki + STAGES - 1;
        if (kn < nK) load_stage(kn % STAGES, kn * BK);
        cp_commit();
    }

    // ---- epilogue: registers -> smem -> coalesced stores (no atomics) ----
    __syncthreads();
    float* ep = sm;
#pragma unroll
    for (int im = 0; im < 4; im++) {
#pragma unroll
        for (int in_ = 0; in_ < 4; in_++) {
#pragma unroll
            for (int half = 0; half < 2; half++) {
                int rr = wm * 64 + im * 16 + half * 8 + (lane >> 2);
                int cc = wn * 32 + in_ * 8 + 2 * (lane & 3);
                float v0 = c[im][in_][half * 2 + 0];
                float v1 = c[im][in_][half * 2 + 1];
                if (PHASE == 0) {
                    v0 = gelu_f(v0);
                    v1 = gelu_f(v1);
                    if (!sh) {
                        float gate = s_gate[rr];
                        v0 *= gate; v1 *= gate;
                    }
                    v0 = __uint_as_float(f2tf(v0));   // store tf32-rounded
                    v1 = __uint_as_float(f2tf(v1));
                }
                ep[rr * EPI_PITCH + cc]     = v0;
                ep[rr * EPI_PITCH + cc + 1] = v1;
            }
        }
    }
    __syncthreads();

#pragma unroll
    for (int jj = 0; jj < 16; jj++) {
        int idx = tid + NTHR * jj;
        int r   = idx >> 5;
        int c4  = idx & 31;
        float4 v = *reinterpret_cast<float4*>(&ep[r * EPI_PITCH + c4 * 4]);
        int grow = m0 + r;
        int gcol = n0 + c4 * 4;
        if (PHASE == 0) {
            if (sh) {
                *reinterpret_cast<float4*>(
                    g_mid_sh + (size_t)e * T_TOK * D_DIM + (size_t)grow * D_DIM + gcol) = v;
            } else if (s_tok[r] >= 0) {
                *reinterpret_cast<float4*>(
                    g_mid_rt + ((size_t)e * T_TOK + grow) * D_DIM + gcol) = v;
            }
        } else {
            if (sh) {
                *reinterpret_cast<float4*>(OUT + (size_t)grow * H_DIM + gcol) = v;
            } else if (s_tok[r] >= 0) {
                *reinterpret_cast<float4*>(
                    g_out_rt + ((size_t)e * T_TOK + grow) * H_DIM + gcol) = v;
            }
        }
    }
}

// ---------------- final combine: out[t] += bucket rows of t's two experts ----------------
__global__ void combine_kernel(float4* __restrict__ out) {
    const int HQ = H_DIM / 4;
    int idx = blockIdx.x * blockDim.x + threadIdx.x;
    if (idx >= T_TOK * HQ) return;
    int t = idx >> 9;           // / HQ (512)
    int c = idx & (HQ - 1);
    int a0 = g_assign[2 * t];
    int a1 = g_assign[2 * t + 1];
    const float4* rt = reinterpret_cast<const float4*>(g_out_rt);
    float4 o  = out[idx];
    float4 r0 = rt[(size_t)a0 * HQ + c];
    float4 r1 = rt[(size_t)a1 * HQ + c];
    o.x += r0.x + r1.x;
    o.y += r0.y + r1.y;
    o.z += r0.z + r1.z;
    o.w += r0.w + r1.w;
    out[idx] = o;
}

// ---------------- launch ----------------
extern "C" void kernel_launch(void* const* d_in, const int* in_sizes, int n_in,
                              void* d_out, int out_size) {
    const float* x      = (const float*)d_in[0];
    const float* Wsh_up = (const float*)d_in[1];
    const float* Wsh_dn = (const float*)d_in[2];
    const float* Wrt_up = (const float*)d_in[3];
    const float* Wrt_dn = (const float*)d_in[4];
    const float* Wr     = (const float*)d_in[5];
    float* out = (float*)d_out;

    cudaFuncSetAttribute(gemm_fused<0>, cudaFuncAttributeMaxDynamicSharedMemorySize, SMEM_BYTES);
    cudaFuncSetAttribute(gemm_fused<1>, cudaFuncAttributeMaxDynamicSharedMemorySize, SMEM_BYTES);

    float* d_xc;
    cudaGetSymbolAddress((void**)&d_xc, g_xc);

    conv_x_kernel<<<1184, 256>>>((const float4*)x, (float4*)d_xc);
    router_kernel<<<T_TOK / 8, 256>>>(x, Wr);

    gemm_fused<0><<<dim3(D_DIM / BN, T_TOK / BM, NE_SH + NE_RT), NTHR, SMEM_BYTES>>>(
        Wsh_up, Wrt_up, nullptr);
    gemm_fused<1><<<dim3(H_DIM / BN, T_TOK / BM, NE_RT + 1), NTHR, SMEM_BYTES>>>(
        Wrt_dn, Wsh_dn, out);

    combine_kernel<<<(T_TOK * (H_DIM / 4)) / 256, 256>>>((float4*)out);
}

// round 11
// speedup vs baseline: 1.8428x; 1.0265x over previous
#include <cuda_runtime.h>
#include <math.h>
#include <stdint.h>

#define T_TOK 4096
#define H_DIM 2048
#define D_DIM 1024
#define NE_RT 16
#define NE_SH 2

// ---------------- scratch (device globals; no allocations) ----------------
__device__ int   g_cnt[NE_RT];
__device__ int   g_tok[NE_RT * T_TOK];
__device__ float g_gate[NE_RT * T_TOK];
__device__ int   g_assign[2 * T_TOK];                     // per-token bucket slots
__device__ float g_mid_sh[(size_t)NE_SH * T_TOK * D_DIM];
__device__ float g_mid_rt[(size_t)NE_RT * T_TOK * D_DIM];
__device__ float g_out_rt[(size_t)NE_RT * T_TOK * H_DIM]; // routed down buckets
__device__ float g_out_sh1[(size_t)T_TOK * H_DIM];        // shared expert 1 partial
__device__ float g_xc[(size_t)T_TOK * H_DIM];             // tf32-rounded x (reused 18x)

// ---------------- helpers ----------------
__device__ __forceinline__ uint32_t f2tf(float f) {
    uint32_t u;
    asm("cvt.rna.tf32.f32 %0, %1;" : "=r"(u) : "f"(f));
    return u;
}
__device__ __forceinline__ uint32_t f2tf_u(uint32_t raw) {
    uint32_t u;
    asm("cvt.rna.tf32.f32 %0, %1;" : "=r"(u) : "f"(__uint_as_float(raw)));
    return u;
}
__device__ __forceinline__ float gelu_f(float v) {
    return 0.5f * v * (1.0f + erff(v * 0.70710678118654752440f));
}
__device__ __forceinline__ void cp16(uint32_t dst_smem, const void* src, bool pred) {
    int sz = pred ? 16 : 0;
    asm volatile("cp.async.cg.shared.global [%0], [%1], 16, %2;\n"
                 :: "r"(dst_smem), "l"(src), "r"(sz) : "memory");
}
__device__ __forceinline__ void cp_commit() {
    asm volatile("cp.async.commit_group;" ::: "memory");
}

// ---------------- x pre-conversion (only reused tensor) + cnt zero ----------------
__global__ void conv_x_kernel(const float4* __restrict__ src, float4* __restrict__ dst) {
    if (blockIdx.x == 0 && threadIdx.x < NE_RT) g_cnt[threadIdx.x] = 0;
    const int n4 = (T_TOK * H_DIM) / 4;
    int stride = gridDim.x * blockDim.x;
    for (int i = blockIdx.x * blockDim.x + threadIdx.x; i < n4; i += stride) {
        float4 v = src[i];
        float4 o;
        o.x = __uint_as_float(f2tf(v.x));
        o.y = __uint_as_float(f2tf(v.y));
        o.z = __uint_as_float(f2tf(v.z));
        o.w = __uint_as_float(f2tf(v.w));
        dst[i] = o;
    }
}

// ---------------- router ----------------
__global__ void router_kernel(const float* __restrict__ x,
                              const float* __restrict__ Wr) {
    int warp = threadIdx.x >> 5;
    int lane = threadIdx.x & 31;
    int t = blockIdx.x * 8 + warp;
    if (t >= T_TOK) return;

    float acc[NE_RT];
#pragma unroll
    for (int e = 0; e < NE_RT; e++) acc[e] = 0.f;

    const float* xr = x + (size_t)t * H_DIM;
    for (int h = lane; h < H_DIM; h += 32) {
        float xv = xr[h];
        const float4* w4 = reinterpret_cast<const float4*>(Wr + (size_t)h * NE_RT);
#pragma unroll
        for (int q = 0; q < 4; q++) {
            float4 w = w4[q];
            acc[4*q+0] += xv * w.x;
            acc[4*q+1] += xv * w.y;
            acc[4*q+2] += xv * w.z;
            acc[4*q+3] += xv * w.w;
        }
    }
#pragma unroll
    for (int e = 0; e < NE_RT; e++) {
#pragma unroll
        for (int off = 16; off > 0; off >>= 1)
            acc[e] += __shfl_xor_sync(0xffffffffu, acc[e], off);
    }
    if (lane == 0) {
        float mx = acc[0];
#pragma unroll
        for (int e = 1; e < NE_RT; e++) mx = fmaxf(mx, acc[e]);
        float p[NE_RT];
        float s = 0.f;
#pragma unroll
        for (int e = 0; e < NE_RT; e++) { p[e] = expf(acc[e] - mx); s += p[e]; }
        float inv = 1.0f / s;

        int i1 = 0; float v1 = p[0];
#pragma unroll
        for (int e = 1; e < NE_RT; e++) if (p[e] > v1) { v1 = p[e]; i1 = e; }
        int i2 = -1; float v2 = -1.f;
#pragma unroll
        for (int e = 0; e < NE_RT; e++) if (e != i1 && p[e] > v2) { v2 = p[e]; i2 = e; }

        int pos = atomicAdd(&g_cnt[i1], 1);
        g_tok[i1 * T_TOK + pos]  = t;
        g_gate[i1 * T_TOK + pos] = v1 * inv;
        g_assign[2 * t]          = i1 * T_TOK + pos;
        pos = atomicAdd(&g_cnt[i2], 1);
        g_tok[i2 * T_TOK + pos]  = t;
        g_gate[i2 * T_TOK + pos] = v2 * inv;
        g_assign[2 * t + 1]      = i2 * T_TOK + pos;
    }
}

// ------ unified 3-stage cp.async tf32 GEMM, 128x128 tile, 64x32 warp tiles ------
// A operands are tf32 already (g_xc / mids); B = RAW weights, cvt.rna at use.
// PHASE 0 (up, gridz=18, K=2048): z<2 shared e=z; z>=2 routed e=z-2 (gather+gate)
// PHASE 1 (down, gridz=18, K=1024 UNIFORM):
//   z<16 routed e=z : out_rt[e] = mid_rt[e] @ Wrt_down[e]   (bucket store)
//   z==16 shared e0 : OUT       = mid_sh[0] @ Wsh_down[0]   (plain store)
//   z==17 shared e1 : out_sh1   = mid_sh[1] @ Wsh_down[1]   (bucket store)

#define BM 128
#define BN 128
#define BK 32
#define STAGES 3
#define NTHR 256
#define ASTR 36
#define BSTR 136
#define A_WORDS (BM * ASTR)
#define B_WORDS (BK * BSTR)
#define STAGE_WORDS (A_WORDS + B_WORDS)
#define EPI_PITCH 132
#define SMEM_BYTES (STAGES * STAGE_WORDS * 4)

template <int PHASE>
__global__ void __launch_bounds__(NTHR) gemm_fused(const float* __restrict__ Wb0,
                                                   const float* __restrict__ Wb1,
                                                   float* __restrict__ OUT) {
    constexpr int NN   = (PHASE == 0) ? 1024 : 2048;
    constexpr int LDA  = (PHASE == 0) ? 2048 : 1024;
    constexpr int KTOT = (PHASE == 0) ? 2048 : 1024;
    constexpr int nK   = KTOT / BK;

    const int z  = blockIdx.z;
    const bool sh = (PHASE == 0) ? (z < 2) : (z >= 16);
    const int e  = (PHASE == 0) ? (sh ? z : z - 2) : (sh ? z - 16 : z);

    const int m0 = blockIdx.y * BM;
    const int n0 = blockIdx.x * BN;

    int cnt = T_TOK;
    if (!sh) {
        cnt = g_cnt[e];
        if (m0 >= cnt) return;
    }

    extern __shared__ float sm[];
    __shared__ int   s_tok[BM];
    __shared__ float s_gate[BM];

    const int tid  = threadIdx.x;
    const int lane = tid & 31;
    const int warp = tid >> 5;
    const int wm   = warp >> 2;
    const int wn   = warp & 3;

    // A base (always tf32 bit patterns); B base = raw weights
    const float* Abase;
    const float* Bbase;
    if (PHASE == 0) {
        Abase = g_xc;
        Bbase = (sh ? Wb0 : Wb1) + (size_t)e * H_DIM * D_DIM;   // Wb0=Wsh_up, Wb1=Wrt_up
    } else {
        if (sh) {
            Abase = g_mid_sh + (size_t)e * T_TOK * D_DIM;
            Bbase = Wb1 + (size_t)e * D_DIM * H_DIM;            // Wb1=Wsh_dn
        } else {
            Abase = g_mid_rt + (size_t)e * T_TOK * D_DIM;
            Bbase = Wb0 + (size_t)e * D_DIM * H_DIM;            // Wb0=Wrt_dn
        }
    }

    // per-row table. up-routed: src token + gate; down-routed: validity; shared: identity.
    if (tid < BM) {
        int grow = m0 + tid;
        int tok;
        float gate = 0.f;
        if (sh) {
            tok = grow;
        } else if (PHASE == 0) {
            if (grow < cnt) {
                tok  = g_tok[e * T_TOK + grow];
                gate = g_gate[e * T_TOK + grow];
            } else tok = -1;
        } else {
            tok = (grow < cnt) ? grow : -1;
        }
        s_tok[tid]  = tok;
        s_gate[tid] = gate;
    }
    __syncthreads();

    // hoist per-thread A staging coords (invariant across k)
    int  a_srow[4];
    bool a_valid[4];
#pragma unroll
    for (int j = 0; j < 4; j++) {
        int r   = (tid + NTHR * j) >> 3;
        int tok = s_tok[r];
        if (PHASE == 0 && !sh) { a_valid[j] = tok >= 0; a_srow[j] = a_valid[j] ? tok : 0; }
        else                   { a_valid[j] = tok >= 0; a_srow[j] = m0 + r; }
    }

    auto load_stage = [&](int s, int k0) {
        float* As = sm + s * STAGE_WORDS;
        float* Bs = As + A_WORDS;
        uint32_t a_sm = (uint32_t)__cvta_generic_to_shared(As);
        uint32_t b_sm = (uint32_t)__cvta_generic_to_shared(Bs);
#pragma unroll
        for (int j = 0; j < 4; j++) {
            int idx = tid + NTHR * j;
            int r   = idx >> 3;
            int c4  = idx & 7;
            const float* src = Abase + (size_t)a_srow[j] * LDA + k0 + c4 * 4;
            cp16(a_sm + (r * ASTR + c4 * 4) * 4, src, a_valid[j]);
        }
#pragma unroll
        for (int j = 0; j < 4; j++) {
            int idx = tid + NTHR * j;
            int r   = idx >> 5;
            int c4  = idx & 31;
            const float* src = Bbase + (size_t)(k0 + r) * NN + n0 + c4 * 4;
            cp16(b_sm + (r * BSTR + c4 * 4) * 4, src, true);
        }
    };

    float c[4][4][4];
#pragma unroll
    for (int i = 0; i < 4; i++)
#pragma unroll
        for (int j = 0; j < 4; j++)
#pragma unroll
            for (int q = 0; q < 4; q++) c[i][j][q] = 0.f;

#pragma unroll
    for (int s = 0; s < STAGES - 1; s++) {
        load_stage(s, s * BK);
        cp_commit();
    }

    for (int ki = 0; ki < nK; ki++) {
        asm volatile("cp.async.wait_group %0;" :: "n"(STAGES - 2) : "memory");
        __syncthreads();

        const uint32_t* As = reinterpret_cast<const uint32_t*>(sm + (ki % STAGES) * STAGE_WORDS);
        const uint32_t* Bs = As + A_WORDS;

#pragma unroll
        for (int ks = 0; ks < 4; ks++) {
            const int kk = ks * 8 + (lane & 3);
            uint32_t a[4][4];
#pragma unroll
            for (int im = 0; im < 4; im++) {
                int m = wm * 64 + im * 16 + (lane >> 2);
                a[im][0] = As[m * ASTR + kk];
                a[im][1] = As[(m + 8) * ASTR + kk];
                a[im][2] = As[m * ASTR + kk + 4];
                a[im][3] = As[(m + 8) * ASTR + kk + 4];
            }
            uint32_t b[4][2];
#pragma unroll
            for (int in_ = 0; in_ < 4; in_++) {
                int n = wn * 32 + in_ * 8 + (lane >> 2);
                b[in_][0] = f2tf_u(Bs[kk * BSTR + n]);        // raw weight -> tf32 (rna)
                b[in_][1] = f2tf_u(Bs[(kk + 4) * BSTR + n]);
            }
#pragma unroll
            for (int im = 0; im < 4; im++)
#pragma unroll
                for (int in_ = 0; in_ < 4; in_++)
                    asm volatile(
                        "mma.sync.aligned.m16n8k8.row.col.f32.tf32.tf32.f32 "
                        "{%0,%1,%2,%3}, {%4,%5,%6,%7}, {%8,%9}, {%0,%1,%2,%3};"
                        : "+f"(c[im][in_][0]), "+f"(c[im][in_][1]),
                          "+f"(c[im][in_][2]), "+f"(c[im][in_][3])
                        : "r"(a[im][0]), "r"(a[im][1]), "r"(a[im][2]), "r"(a[im][3]),
                          "r"(b[in_][0]), "r"(b[in_][1]));
        }

        int kn = ki + STAGES - 1;
        if (kn < nK) load_stage(kn % STAGES, kn * BK);
        cp_commit();
    }

    // ---- epilogue: registers -> smem -> coalesced stores (no atomics) ----
    __syncthreads();
    float* ep = sm;
#pragma unroll
    for (int im = 0; im < 4; im++) {
#pragma unroll
        for (int in_ = 0; in_ < 4; in_++) {
#pragma unroll
            for (int half = 0; half < 2; half++) {
                int rr = wm * 64 + im * 16 + half * 8 + (lane >> 2);
                int cc = wn * 32 + in_ * 8 + 2 * (lane & 3);
                float v0 = c[im][in_][half * 2 + 0];
                float v1 = c[im][in_][half * 2 + 1];
                if (PHASE == 0) {
                    v0 = gelu_f(v0);
                    v1 = gelu_f(v1);
                    if (!sh) {
                        float gate = s_gate[rr];
                        v0 *= gate; v1 *= gate;
                    }
                    v0 = __uint_as_float(f2tf(v0));   // store tf32-rounded
                    v1 = __uint_as_float(f2tf(v1));
                }
                ep[rr * EPI_PITCH + cc]     = v0;
                ep[rr * EPI_PITCH + cc + 1] = v1;
            }
        }
    }
    __syncthreads();

#pragma unroll
    for (int jj = 0; jj < 16; jj++) {
        int idx = tid + NTHR * jj;
        int r   = idx >> 5;
        int c4  = idx & 31;
        float4 v = *reinterpret_cast<float4*>(&ep[r * EPI_PITCH + c4 * 4]);
        int grow = m0 + r;
        int gcol = n0 + c4 * 4;
        if (PHASE == 0) {
            if (sh) {
                *reinterpret_cast<float4*>(
                    g_mid_sh + (size_t)e * T_TOK * D_DIM + (size_t)grow * D_DIM + gcol) = v;
            } else if (s_tok[r] >= 0) {
                *reinterpret_cast<float4*>(
                    g_mid_rt + ((size_t)e * T_TOK + grow) * D_DIM + gcol) = v;
            }
        } else {
            if (sh) {
                float* dst = (e == 0) ? OUT : g_out_sh1;
                *reinterpret_cast<float4*>(dst + (size_t)grow * H_DIM + gcol) = v;
            } else if (s_tok[r] >= 0) {
                *reinterpret_cast<float4*>(
                    g_out_rt + ((size_t)e * T_TOK + grow) * H_DIM + gcol) = v;
            }
        }
    }
}

// -------- final combine: out[t] += shared-expert-1 + both routed bucket rows --------
__global__ void combine_kernel(float4* __restrict__ out) {
    const int HQ = H_DIM / 4;
    int idx = blockIdx.x * blockDim.x + threadIdx.x;
    if (idx >= T_TOK * HQ) return;
    int t = idx >> 9;           // / HQ (512)
    int c = idx & (HQ - 1);
    int a0 = g_assign[2 * t];
    int a1 = g_assign[2 * t + 1];
    const float4* rt  = reinterpret_cast<const float4*>(g_out_rt);
    const float4* sh1 = reinterpret_cast<const float4*>(g_out_sh1);
    float4 o  = out[idx];
    float4 s1 = sh1[idx];
    float4 r0 = rt[(size_t)a0 * HQ + c];
    float4 r1 = rt[(size_t)a1 * HQ + c];
    o.x += s1.x + r0.x + r1.x;
    o.y += s1.y + r0.y + r1.y;
    o.z += s1.z + r0.z + r1.z;
    o.w += s1.w + r0.w + r1.w;
    out[idx] = o;
}

// ---------------- launch ----------------
extern "C" void kernel_launch(void* const* d_in, const int* in_sizes, int n_in,
                              void* d_out, int out_size) {
    const float* x      = (const float*)d_in[0];
    const float* Wsh_up = (const float*)d_in[1];
    const float* Wsh_dn = (const float*)d_in[2];
    const float* Wrt_up = (const float*)d_in[3];
    const float* Wrt_dn = (const float*)d_in[4];
    const float* Wr     = (const float*)d_in[5];
    float* out = (float*)d_out;

    cudaFuncSetAttribute(gemm_fused<0>, cudaFuncAttributeMaxDynamicSharedMemorySize, SMEM_BYTES);
    cudaFuncSetAttribute(gemm_fused<1>, cudaFuncAttributeMaxDynamicSharedMemorySize, SMEM_BYTES);

    float* d_xc;
    cudaGetSymbolAddress((void**)&d_xc, g_xc);

    conv_x_kernel<<<1184, 256>>>((const float4*)x, (float4*)d_xc);
    router_kernel<<<T_TOK / 8, 256>>>(x, Wr);

    gemm_fused<0><<<dim3(D_DIM / BN, T_TOK / BM, NE_SH + NE_RT), NTHR, SMEM_BYTES>>>(
        Wsh_up, Wrt_up, nullptr);
    gemm_fused<1><<<dim3(H_DIM / BN, T_TOK / BM, NE_RT + NE_SH), NTHR, SMEM_BYTES>>>(
        Wrt_dn, Wsh_dn, out);

    combine_kernel<<<(T_TOK * (H_DIM / 4)) / 256, 256>>>((float4*)out);
}

// round 12
// speedup vs baseline: 1.9640x; 1.0658x over previous
#include <cuda_runtime.h>
#include <math.h>
#include <stdint.h>

#define T_TOK 4096
#define H_DIM 2048
#define D_DIM 1024
#define NE_RT 16
#define NE_SH 2

// ---------------- scratch (device globals; no allocations) ----------------
__device__ int   g_cnt[NE_RT];
__device__ int   g_tok[NE_RT * T_TOK];
__device__ float g_gate[NE_RT * T_TOK];
__device__ int   g_assign[2 * T_TOK];                     // per-token bucket slots
__device__ float g_mid_sh[(size_t)NE_SH * T_TOK * D_DIM];
__device__ float g_mid_rt[(size_t)NE_RT * T_TOK * D_DIM];
__device__ float g_out_rt[(size_t)NE_RT * T_TOK * H_DIM]; // routed down buckets
__device__ float g_out_sh1[(size_t)T_TOK * H_DIM];        // shared expert 1 partial
__device__ float g_xc[(size_t)T_TOK * H_DIM];             // tf32-rounded x (reused 18x)

// ---------------- helpers ----------------
__device__ __forceinline__ uint32_t f2tf(float f) {
    uint32_t u;
    asm("cvt.rna.tf32.f32 %0, %1;" : "=r"(u) : "f"(f));
    return u;
}
__device__ __forceinline__ uint32_t f2tf_u(uint32_t raw) {
    uint32_t u;
    asm("cvt.rna.tf32.f32 %0, %1;" : "=r"(u) : "f"(__uint_as_float(raw)));
    return u;
}
__device__ __forceinline__ float gelu_f(float v) {
    return 0.5f * v * (1.0f + erff(v * 0.70710678118654752440f));
}
__device__ __forceinline__ void cp16(uint32_t dst_smem, const void* src, bool pred) {
    int sz = pred ? 16 : 0;
    asm volatile("cp.async.cg.shared.global [%0], [%1], 16, %2;\n"
                 :: "r"(dst_smem), "l"(src), "r"(sz) : "memory");
}
__device__ __forceinline__ void cp_commit() {
    asm volatile("cp.async.commit_group;" ::: "memory");
}

// ---------------- x pre-conversion (only reused tensor) + cnt zero ----------------
__global__ void conv_x_kernel(const float4* __restrict__ src, float4* __restrict__ dst) {
    if (blockIdx.x == 0 && threadIdx.x < NE_RT) g_cnt[threadIdx.x] = 0;
    const int n4 = (T_TOK * H_DIM) / 4;
    int stride = gridDim.x * blockDim.x;
    for (int i = blockIdx.x * blockDim.x + threadIdx.x; i < n4; i += stride) {
        float4 v = src[i];
        float4 o;
        o.x = __uint_as_float(f2tf(v.x));
        o.y = __uint_as_float(f2tf(v.y));
        o.z = __uint_as_float(f2tf(v.z));
        o.w = __uint_as_float(f2tf(v.w));
        dst[i] = o;
    }
}

// ---------------- router ----------------
__global__ void router_kernel(const float* __restrict__ x,
                              const float* __restrict__ Wr) {
    int warp = threadIdx.x >> 5;
    int lane = threadIdx.x & 31;
    int t = blockIdx.x * 8 + warp;
    if (t >= T_TOK) return;

    float acc[NE_RT];
#pragma unroll
    for (int e = 0; e < NE_RT; e++) acc[e] = 0.f;

    const float* xr = x + (size_t)t * H_DIM;
    for (int h = lane; h < H_DIM; h += 32) {
        float xv = xr[h];
        const float4* w4 = reinterpret_cast<const float4*>(Wr + (size_t)h * NE_RT);
#pragma unroll
        for (int q = 0; q < 4; q++) {
            float4 w = w4[q];
            acc[4*q+0] += xv * w.x;
            acc[4*q+1] += xv * w.y;
            acc[4*q+2] += xv * w.z;
            acc[4*q+3] += xv * w.w;
        }
    }
#pragma unroll
    for (int e = 0; e < NE_RT; e++) {
#pragma unroll
        for (int off = 16; off > 0; off >>= 1)
            acc[e] += __shfl_xor_sync(0xffffffffu, acc[e], off);
    }
    if (lane == 0) {
        float mx = acc[0];
#pragma unroll
        for (int e = 1; e < NE_RT; e++) mx = fmaxf(mx, acc[e]);
        float p[NE_RT];
        float s = 0.f;
#pragma unroll
        for (int e = 0; e < NE_RT; e++) { p[e] = expf(acc[e] - mx); s += p[e]; }
        float inv = 1.0f / s;

        int i1 = 0; float v1 = p[0];
#pragma unroll
        for (int e = 1; e < NE_RT; e++) if (p[e] > v1) { v1 = p[e]; i1 = e; }
        int i2 = -1; float v2 = -1.f;
#pragma unroll
        for (int e = 0; e < NE_RT; e++) if (e != i1 && p[e] > v2) { v2 = p[e]; i2 = e; }

        int pos = atomicAdd(&g_cnt[i1], 1);
        g_tok[i1 * T_TOK + pos]  = t;
        g_gate[i1 * T_TOK + pos] = v1 * inv;
        g_assign[2 * t]          = i1 * T_TOK + pos;
        pos = atomicAdd(&g_cnt[i2], 1);
        g_tok[i2 * T_TOK + pos]  = t;
        g_gate[i2 * T_TOK + pos] = v2 * inv;
        g_assign[2 * t + 1]      = i2 * T_TOK + pos;
    }
}

// ------ unified 3-stage cp.async tf32 GEMM, 128x128 tile, 64x32 warp tiles ------
// A operands are tf32 already (g_xc / mids); B = RAW weights, cvt.rna at use.
// z (= blockIdx.z + zoff) semantics:
// PHASE 0 (up, K=2048): z<2 shared e=z; z>=2 routed e=z-2 (gather+gate)
// PHASE 1 (down, K=1024): z<16 routed e=z (bucket store);
//   z==16 shared e0 -> OUT ; z==17 shared e1 -> out_sh1

#define BM 128
#define BN 128
#define BK 32
#define STAGES 3
#define NTHR 256
#define ASTR 36
#define BSTR 136
#define A_WORDS (BM * ASTR)
#define B_WORDS (BK * BSTR)
#define STAGE_WORDS (A_WORDS + B_WORDS)
#define EPI_PITCH 132
#define SMEM_BYTES (STAGES * STAGE_WORDS * 4)

template <int PHASE>
__global__ void __launch_bounds__(NTHR) gemm_fused(const float* __restrict__ Wb0,
                                                   const float* __restrict__ Wb1,
                                                   float* __restrict__ OUT,
                                                   int zoff) {
    constexpr int NN   = (PHASE == 0) ? 1024 : 2048;
    constexpr int LDA  = (PHASE == 0) ? 2048 : 1024;
    constexpr int KTOT = (PHASE == 0) ? 2048 : 1024;
    constexpr int nK   = KTOT / BK;

    const int z  = blockIdx.z + zoff;
    const bool sh = (PHASE == 0) ? (z < 2) : (z >= 16);
    const int e  = (PHASE == 0) ? (sh ? z : z - 2) : (sh ? z - 16 : z);

    const int m0 = blockIdx.y * BM;
    const int n0 = blockIdx.x * BN;

    int cnt = T_TOK;
    if (!sh) {
        cnt = g_cnt[e];
        if (m0 >= cnt) return;
    }

    extern __shared__ float sm[];
    __shared__ int   s_tok[BM];
    __shared__ float s_gate[BM];

    const int tid  = threadIdx.x;
    const int lane = tid & 31;
    const int warp = tid >> 5;
    const int wm   = warp >> 2;
    const int wn   = warp & 3;

    // A base (always tf32 bit patterns); B base = raw weights
    const float* Abase;
    const float* Bbase;
    if (PHASE == 0) {
        Abase = g_xc;
        Bbase = (sh ? Wb0 : Wb1) + (size_t)e * H_DIM * D_DIM;   // Wb0=Wsh_up, Wb1=Wrt_up
    } else {
        if (sh) {
            Abase = g_mid_sh + (size_t)e * T_TOK * D_DIM;
            Bbase = Wb1 + (size_t)e * D_DIM * H_DIM;            // Wb1=Wsh_dn
        } else {
            Abase = g_mid_rt + (size_t)e * T_TOK * D_DIM;
            Bbase = Wb0 + (size_t)e * D_DIM * H_DIM;            // Wb0=Wrt_dn
        }
    }

    // per-row table. up-routed: src token + gate; down-routed: validity; shared: identity.
    if (tid < BM) {
        int grow = m0 + tid;
        int tok;
        float gate = 0.f;
        if (sh) {
            tok = grow;
        } else if (PHASE == 0) {
            if (grow < cnt) {
                tok  = g_tok[e * T_TOK + grow];
                gate = g_gate[e * T_TOK + grow];
            } else tok = -1;
        } else {
            tok = (grow < cnt) ? grow : -1;
        }
        s_tok[tid]  = tok;
        s_gate[tid] = gate;
    }
    __syncthreads();

    // hoist per-thread A staging coords (invariant across k)
    int  a_srow[4];
    bool a_valid[4];
#pragma unroll
    for (int j = 0; j < 4; j++) {
        int r   = (tid + NTHR * j) >> 3;
        int tok = s_tok[r];
        if (PHASE == 0 && !sh) { a_valid[j] = tok >= 0; a_srow[j] = a_valid[j] ? tok : 0; }
        else                   { a_valid[j] = tok >= 0; a_srow[j] = m0 + r; }
    }

    auto load_stage = [&](int s, int k0) {
        float* As = sm + s * STAGE_WORDS;
        float* Bs = As + A_WORDS;
        uint32_t a_sm = (uint32_t)__cvta_generic_to_shared(As);
        uint32_t b_sm = (uint32_t)__cvta_generic_to_shared(Bs);
#pragma unroll
        for (int j = 0; j < 4; j++) {
            int idx = tid + NTHR * j;
            int r   = idx >> 3;
            int c4  = idx & 7;
            const float* src = Abase + (size_t)a_srow[j] * LDA + k0 + c4 * 4;
            cp16(a_sm + (r * ASTR + c4 * 4) * 4, src, a_valid[j]);
        }
#pragma unroll
        for (int j = 0; j < 4; j++) {
            int idx = tid + NTHR * j;
            int r   = idx >> 5;
            int c4  = idx & 31;
            const float* src = Bbase + (size_t)(k0 + r) * NN + n0 + c4 * 4;
            cp16(b_sm + (r * BSTR + c4 * 4) * 4, src, true);
        }
    };

    float c[4][4][4];
#pragma unroll
    for (int i = 0; i < 4; i++)
#pragma unroll
        for (int j = 0; j < 4; j++)
#pragma unroll
            for (int q = 0; q < 4; q++) c[i][j][q] = 0.f;

#pragma unroll
    for (int s = 0; s < STAGES - 1; s++) {
        load_stage(s, s * BK);
        cp_commit();
    }

    for (int ki = 0; ki < nK; ki++) {
        asm volatile("cp.async.wait_group %0;" :: "n"(STAGES - 2) : "memory");
        __syncthreads();

        const uint32_t* As = reinterpret_cast<const uint32_t*>(sm + (ki % STAGES) * STAGE_WORDS);
        const uint32_t* Bs = As + A_WORDS;

#pragma unroll
        for (int ks = 0; ks < 4; ks++) {
            const int kk = ks * 8 + (lane & 3);
            uint32_t a[4][4];
#pragma unroll
            for (int im = 0; im < 4; im++) {
                int m = wm * 64 + im * 16 + (lane >> 2);
                a[im][0] = As[m * ASTR + kk];
                a[im][1] = As[(m + 8) * ASTR + kk];
                a[im][2] = As[m * ASTR + kk + 4];
                a[im][3] = As[(m + 8) * ASTR + kk + 4];
            }
            uint32_t b[4][2];
#pragma unroll
            for (int in_ = 0; in_ < 4; in_++) {
                int n = wn * 32 + in_ * 8 + (lane >> 2);
                b[in_][0] = f2tf_u(Bs[kk * BSTR + n]);        // raw weight -> tf32 (rna)
                b[in_][1] = f2tf_u(Bs[(kk + 4) * BSTR + n]);
            }
#pragma unroll
            for (int im = 0; im < 4; im++)
#pragma unroll
                for (int in_ = 0; in_ < 4; in_++)
                    asm volatile(
                        "mma.sync.aligned.m16n8k8.row.col.f32.tf32.tf32.f32 "
                        "{%0,%1,%2,%3}, {%4,%5,%6,%7}, {%8,%9}, {%0,%1,%2,%3};"
                        : "+f"(c[im][in_][0]), "+f"(c[im][in_][1]),
                          "+f"(c[im][in_][2]), "+f"(c[im][in_][3])
                        : "r"(a[im][0]), "r"(a[im][1]), "r"(a[im][2]), "r"(a[im][3]),
                          "r"(b[in_][0]), "r"(b[in_][1]));
        }

        int kn = ki + STAGES - 1;
        if (kn < nK) load_stage(kn % STAGES, kn * BK);
        cp_commit();
    }

    // ---- epilogue: registers -> smem -> coalesced stores (no atomics) ----
    __syncthreads();
    float* ep = sm;
#pragma unroll
    for (int im = 0; im < 4; im++) {
#pragma unroll
        for (int in_ = 0; in_ < 4; in_++) {
#pragma unroll
            for (int half = 0; half < 2; half++) {
                int rr = wm * 64 + im * 16 + half * 8 + (lane >> 2);
                int cc = wn * 32 + in_ * 8 + 2 * (lane & 3);
                float v0 = c[im][in_][half * 2 + 0];
                float v1 = c[im][in_][half * 2 + 1];
                if (PHASE == 0) {
                    v0 = gelu_f(v0);
                    v1 = gelu_f(v1);
                    if (!sh) {
                        float gate = s_gate[rr];
                        v0 *= gate; v1 *= gate;
                    }
                    v0 = __uint_as_float(f2tf(v0));   // store tf32-rounded
                    v1 = __uint_as_float(f2tf(v1));
                }
                ep[rr * EPI_PITCH + cc]     = v0;
                ep[rr * EPI_PITCH + cc + 1] = v1;
            }
        }
    }
    __syncthreads();

#pragma unroll
    for (int jj = 0; jj < 16; jj++) {
        int idx = tid + NTHR * jj;
        int r   = idx >> 5;
        int c4  = idx & 31;
        float4 v = *reinterpret_cast<float4*>(&ep[r * EPI_PITCH + c4 * 4]);
        int grow = m0 + r;
        int gcol = n0 + c4 * 4;
        if (PHASE == 0) {
            if (sh) {
                *reinterpret_cast<float4*>(
                    g_mid_sh + (size_t)e * T_TOK * D_DIM + (size_t)grow * D_DIM + gcol) = v;
            } else if (s_tok[r] >= 0) {
                *reinterpret_cast<float4*>(
                    g_mid_rt + ((size_t)e * T_TOK + grow) * D_DIM + gcol) = v;
            }
        } else {
            if (sh) {
                float* dst = (e == 0) ? OUT : g_out_sh1;
                *reinterpret_cast<float4*>(dst + (size_t)grow * H_DIM + gcol) = v;
            } else if (s_tok[r] >= 0) {
                *reinterpret_cast<float4*>(
                    g_out_rt + ((size_t)e * T_TOK + grow) * H_DIM + gcol) = v;
            }
        }
    }
}

// -------- final combine: out[t] += shared-expert-1 + both routed bucket rows --------
__global__ void combine_kernel(float4* __restrict__ out) {
    const int HQ = H_DIM / 4;
    int idx = blockIdx.x * blockDim.x + threadIdx.x;
    if (idx >= T_TOK * HQ) return;
    int t = idx >> 9;           // / HQ (512)
    int c = idx & (HQ - 1);
    int a0 = g_assign[2 * t];
    int a1 = g_assign[2 * t + 1];
    const float4* rt  = reinterpret_cast<const float4*>(g_out_rt);
    const float4* sh1 = reinterpret_cast<const float4*>(g_out_sh1);
    float4 o  = out[idx];
    float4 s1 = sh1[idx];
    float4 r0 = rt[(size_t)a0 * HQ + c];
    float4 r1 = rt[(size_t)a1 * HQ + c];
    o.x += s1.x + r0.x + r1.x;
    o.y += s1.y + r0.y + r1.y;
    o.z += s1.z + r0.z + r1.z;
    o.w += s1.w + r0.w + r1.w;
    out[idx] = o;
}

// ---------------- launch (fork-join: shared chain || routed chain) ----------------
extern "C" void kernel_launch(void* const* d_in, const int* in_sizes, int n_in,
                              void* d_out, int out_size) {
    const float* x      = (const float*)d_in[0];
    const float* Wsh_up = (const float*)d_in[1];
    const float* Wsh_dn = (const float*)d_in[2];
    const float* Wrt_up = (const float*)d_in[3];
    const float* Wrt_dn = (const float*)d_in[4];
    const float* Wr     = (const float*)d_in[5];
    float* out = (float*)d_out;

    // one-time handles (created on first, non-captured, correctness call)
    static cudaStream_t s2 = nullptr;
    static cudaEvent_t evFork = nullptr, evJoin = nullptr;
    if (s2 == nullptr) {
        cudaStreamCreateWithFlags(&s2, cudaStreamNonBlocking);
        cudaEventCreateWithFlags(&evFork, cudaEventDisableTiming);
        cudaEventCreateWithFlags(&evJoin, cudaEventDisableTiming);
        cudaFuncSetAttribute(gemm_fused<0>, cudaFuncAttributeMaxDynamicSharedMemorySize, SMEM_BYTES);
        cudaFuncSetAttribute(gemm_fused<1>, cudaFuncAttributeMaxDynamicSharedMemorySize, SMEM_BYTES);
    }

    float* d_xc;
    cudaGetSymbolAddress((void**)&d_xc, g_xc);

    // stream 0: prologue shared by both chains
    conv_x_kernel<<<1184, 256>>>((const float4*)x, (float4*)d_xc);
    cudaEventRecord(evFork, 0);
    cudaStreamWaitEvent(s2, evFork, 0);

    // ---- chain A (stream 0): router -> up-routed -> down-routed ----
    router_kernel<<<T_TOK / 8, 256>>>(x, Wr);
    gemm_fused<0><<<dim3(D_DIM / BN, T_TOK / BM, NE_RT), NTHR, SMEM_BYTES>>>(
        Wsh_up, Wrt_up, nullptr, /*zoff=*/2);
    gemm_fused<1><<<dim3(H_DIM / BN, T_TOK / BM, NE_RT), NTHR, SMEM_BYTES>>>(
        Wrt_dn, Wsh_dn, out, /*zoff=*/0);

    // ---- chain B (stream s2): up-shared -> down-shared ----
    gemm_fused<0><<<dim3(D_DIM / BN, T_TOK / BM, NE_SH), NTHR, SMEM_BYTES, s2>>>(
        Wsh_up, Wrt_up, nullptr, /*zoff=*/0);
    gemm_fused<1><<<dim3(H_DIM / BN, T_TOK / BM, NE_SH), NTHR, SMEM_BYTES, s2>>>(
        Wrt_dn, Wsh_dn, out, /*zoff=*/16);
    cudaEventRecord(evJoin, s2);

    // join + combine on stream 0
    cudaStreamWaitEvent(0, evJoin, 0);
    combine_kernel<<<(T_TOK * (H_DIM / 4)) / 256, 256>>>((float4*)out);
}

// round 14
// speedup vs baseline: 1.9735x; 1.0048x over previous
#include <cuda_runtime.h>
#include <math.h>
#include <stdint.h>

#define T_TOK 4096
#define H_DIM 2048
#define D_DIM 1024
#define NE_RT 16
#define NE_SH 2

// ---------------- scratch (device globals; no allocations) ----------------
__device__ int   g_cnt[NE_RT];
__device__ int   g_tok[NE_RT * T_TOK];
__device__ float g_gate[NE_RT * T_TOK];
__device__ int   g_assign[2 * T_TOK];                     // per-token bucket slots
__device__ float g_mid_sh[(size_t)NE_SH * T_TOK * D_DIM];
__device__ float g_mid_rt[(size_t)NE_RT * T_TOK * D_DIM];
__device__ float g_out_rt[(size_t)NE_RT * T_TOK * H_DIM]; // routed down buckets
__device__ float g_out_sh1[(size_t)T_TOK * H_DIM];        // shared expert 1 partial
__device__ float g_xc[(size_t)T_TOK * H_DIM];             // tf32-rounded x (reused 18x)

// ---------------- helpers ----------------
__device__ __forceinline__ uint32_t f2tf(float f) {
    uint32_t u;
    asm("cvt.rna.tf32.f32 %0, %1;" : "=r"(u) : "f"(f));
    return u;
}
__device__ __forceinline__ uint32_t f2tf_u(uint32_t raw) {
    uint32_t u;
    asm("cvt.rna.tf32.f32 %0, %1;" : "=r"(u) : "f"(__uint_as_float(raw)));
    return u;
}
__device__ __forceinline__ float gelu_f(float v) {
    return 0.5f * v * (1.0f + erff(v * 0.70710678118654752440f));
}
__device__ __forceinline__ void cp16(uint32_t dst_smem, const void* src, bool pred) {
    int sz = pred ? 16 : 0;
    asm volatile("cp.async.cg.shared.global [%0], [%1], 16, %2;\n"
                 :: "r"(dst_smem), "l"(src), "r"(sz) : "memory");
}
__device__ __forceinline__ void cp_commit() {
    asm volatile("cp.async.commit_group;" ::: "memory");
}

// ---------------- tiny cnt zero (must precede router) ----------------
__global__ void zero_cnt_kernel() {
    if (threadIdx.x < NE_RT) g_cnt[threadIdx.x] = 0;
}

// ---------------- x pre-conversion (only reused tensor) ----------------
__global__ void conv_x_kernel(const float4* __restrict__ src, float4* __restrict__ dst) {
    const int n4 = (T_TOK * H_DIM) / 4;
    int stride = gridDim.x * blockDim.x;
    for (int i = blockIdx.x * blockDim.x + threadIdx.x; i < n4; i += stride) {
        float4 v = src[i];
        float4 o;
        o.x = __uint_as_float(f2tf(v.x));
        o.y = __uint_as_float(f2tf(v.y));
        o.z = __uint_as_float(f2tf(v.z));
        o.w = __uint_as_float(f2tf(v.w));
        dst[i] = o;
    }
}

// ---------------- router ----------------
__global__ void router_kernel(const float* __restrict__ x,
                              const float* __restrict__ Wr) {
    int warp = threadIdx.x >> 5;
    int lane = threadIdx.x & 31;
    int t = blockIdx.x * 8 + warp;
    if (t >= T_TOK) return;

    float acc[NE_RT];
#pragma unroll
    for (int e = 0; e < NE_RT; e++) acc[e] = 0.f;

    const float* xr = x + (size_t)t * H_DIM;
    for (int h = lane; h < H_DIM; h += 32) {
        float xv = xr[h];
        const float4* w4 = reinterpret_cast<const float4*>(Wr + (size_t)h * NE_RT);
#pragma unroll
        for (int q = 0; q < 4; q++) {
            float4 w = w4[q];
            acc[4*q+0] += xv * w.x;
            acc[4*q+1] += xv * w.y;
            acc[4*q+2] += xv * w.z;
            acc[4*q+3] += xv * w.w;
        }
    }
#pragma unroll
    for (int e = 0; e < NE_RT; e++) {
#pragma unroll
        for (int off = 16; off > 0; off >>= 1)
            acc[e] += __shfl_xor_sync(0xffffffffu, acc[e], off);
    }
    if (lane == 0) {
        float mx = acc[0];
#pragma unroll
        for (int e = 1; e < NE_RT; e++) mx = fmaxf(mx, acc[e]);
        float p[NE_RT];
        float s = 0.f;
#pragma unroll
        for (int e = 0; e < NE_RT; e++) { p[e] = expf(acc[e] - mx); s += p[e]; }
        float inv = 1.0f / s;

        int i1 = 0; float v1 = p[0];
#pragma unroll
        for (int e = 1; e < NE_RT; e++) if (p[e] > v1) { v1 = p[e]; i1 = e; }
        int i2 = -1; float v2 = -1.f;
#pragma unroll
        for (int e = 0; e < NE_RT; e++) if (e != i1 && p[e] > v2) { v2 = p[e]; i2 = e; }

        int pos = atomicAdd(&g_cnt[i1], 1);
        g_tok[i1 * T_TOK + pos]  = t;
        g_gate[i1 * T_TOK + pos] = v1 * inv;
        g_assign[2 * t]          = i1 * T_TOK + pos;
        pos = atomicAdd(&g_cnt[i2], 1);
        g_tok[i2 * T_TOK + pos]  = t;
        g_gate[i2 * T_TOK + pos] = v2 * inv;
        g_assign[2 * t + 1]      = i2 * T_TOK + pos;
    }
}

// ------ unified 3-stage cp.async tf32 GEMM, 128x128 tile, 64x32 warp tiles ------
// A operands are tf32 already (g_xc / mids); B = RAW weights, cvt.rna at use.
// z (= blockIdx.z + zoff) semantics:
// PHASE 0 (up, K=2048): z<2 shared e=z; z>=2 routed e=z-2 (gather+gate)
// PHASE 1 (down, K=1024): z<16 routed e=z (bucket store);
//   z==16 shared e0 -> OUT ; z==17 shared e1 -> out_sh1

#define BM 128
#define BN 128
#define BK 32
#define STAGES 3
#define NTHR 256
#define ASTR 36
#define BSTR 136
#define A_WORDS (BM * ASTR)
#define B_WORDS (BK * BSTR)
#define STAGE_WORDS (A_WORDS + B_WORDS)
#define EPI_PITCH 132
#define SMEM_BYTES (STAGES * STAGE_WORDS * 4)

template <int PHASE>
__global__ void __launch_bounds__(NTHR) gemm_fused(const float* __restrict__ Wb0,
                                                   const float* __restrict__ Wb1,
                                                   float* __restrict__ OUT,
                                                   int zoff) {
    constexpr int NN   = (PHASE == 0) ? 1024 : 2048;
    constexpr int LDA  = (PHASE == 0) ? 2048 : 1024;
    constexpr int KTOT = (PHASE == 0) ? 2048 : 1024;
    constexpr int nK   = KTOT / BK;

    const int z  = blockIdx.z + zoff;
    const bool sh = (PHASE == 0) ? (z < 2) : (z >= 16);
    const int e  = (PHASE == 0) ? (sh ? z : z - 2) : (sh ? z - 16 : z);

    const int m0 = blockIdx.y * BM;
    const int n0 = blockIdx.x * BN;

    int cnt = T_TOK;
    if (!sh) {
        cnt = g_cnt[e];
        if (m0 >= cnt) return;
    }

    extern __shared__ float sm[];
    __shared__ int   s_tok[BM];
    __shared__ float s_gate[BM];

    const int tid  = threadIdx.x;
    const int lane = tid & 31;
    const int warp = tid >> 5;
    const int wm   = warp >> 2;
    const int wn   = warp & 3;

    // A base (always tf32 bit patterns); B base = raw weights
    const float* Abase;
    const float* Bbase;
    if (PHASE == 0) {
        Abase = g_xc;
        Bbase = (sh ? Wb0 : Wb1) + (size_t)e * H_DIM * D_DIM;   // Wb0=Wsh_up, Wb1=Wrt_up
    } else {
        if (sh) {
            Abase = g_mid_sh + (size_t)e * T_TOK * D_DIM;
            Bbase = Wb1 + (size_t)e * D_DIM * H_DIM;            // Wb1=Wsh_dn
        } else {
            Abase = g_mid_rt + (size_t)e * T_TOK * D_DIM;
            Bbase = Wb0 + (size_t)e * D_DIM * H_DIM;            // Wb0=Wrt_dn
        }
    }

    // per-row table. up-routed: src token + gate; down-routed: validity; shared: identity.
    if (tid < BM) {
        int grow = m0 + tid;
        int tok;
        float gate = 0.f;
        if (sh) {
            tok = grow;
        } else if (PHASE == 0) {
            if (grow < cnt) {
                tok  = g_tok[e * T_TOK + grow];
                gate = g_gate[e * T_TOK + grow];
            } else tok = -1;
        } else {
            tok = (grow < cnt) ? grow : -1;
        }
        s_tok[tid]  = tok;
        s_gate[tid] = gate;
    }
    __syncthreads();

    // hoist per-thread A staging coords (invariant across k)
    int  a_srow[4];
    bool a_valid[4];
#pragma unroll
    for (int j = 0; j < 4; j++) {
        int r   = (tid + NTHR * j) >> 3;
        int tok = s_tok[r];
        if (PHASE == 0 && !sh) { a_valid[j] = tok >= 0; a_srow[j] = a_valid[j] ? tok : 0; }
        else                   { a_valid[j] = tok >= 0; a_srow[j] = m0 + r; }
    }

    auto load_stage = [&](int s, int k0) {
        float* As = sm + s * STAGE_WORDS;
        float* Bs = As + A_WORDS;
        uint32_t a_sm = (uint32_t)__cvta_generic_to_shared(As);
        uint32_t b_sm = (uint32_t)__cvta_generic_to_shared(Bs);
#pragma unroll
        for (int j = 0; j < 4; j++) {
            int idx = tid + NTHR * j;
            int r   = idx >> 3;
            int c4  = idx & 7;
            const float* src = Abase + (size_t)a_srow[j] * LDA + k0 + c4 * 4;
            cp16(a_sm + (r * ASTR + c4 * 4) * 4, src, a_valid[j]);
        }
#pragma unroll
        for (int j = 0; j < 4; j++) {
            int idx = tid + NTHR * j;
            int r   = idx >> 5;
            int c4  = idx & 31;
            const float* src = Bbase + (size_t)(k0 + r) * NN + n0 + c4 * 4;
            cp16(b_sm + (r * BSTR + c4 * 4) * 4, src, true);
        }
    };

    float c[4][4][4];
#pragma unroll
    for (int i = 0; i < 4; i++)
#pragma unroll
        for (int j = 0; j < 4; j++)
#pragma unroll
            for (int q = 0; q < 4; q++) c[i][j][q] = 0.f;

#pragma unroll
    for (int s = 0; s < STAGES - 1; s++) {
        load_stage(s, s * BK);
        cp_commit();
    }

    for (int ki = 0; ki < nK; ki++) {
        asm volatile("cp.async.wait_group %0;" :: "n"(STAGES - 2) : "memory");
        __syncthreads();

        const uint32_t* As = reinterpret_cast<const uint32_t*>(sm + (ki % STAGES) * STAGE_WORDS);
        const uint32_t* Bs = As + A_WORDS;

#pragma unroll
        for (int ks = 0; ks < 4; ks++) {
            const int kk = ks * 8 + (lane & 3);
            uint32_t a[4][4];
#pragma unroll
            for (int im = 0; im < 4; im++) {
                int m = wm * 64 + im * 16 + (lane >> 2);
                a[im][0] = As[m * ASTR + kk];
                a[im][1] = As[(m + 8) * ASTR + kk];
                a[im][2] = As[m * ASTR + kk + 4];
                a[im][3] = As[(m + 8) * ASTR + kk + 4];
            }
            uint32_t b[4][2];
#pragma unroll
            for (int in_ = 0; in_ < 4; in_++) {
                int n = wn * 32 + in_ * 8 + (lane >> 2);
                b[in_][0] = f2tf_u(Bs[kk * BSTR + n]);        // raw weight -> tf32 (rna)
                b[in_][1] = f2tf_u(Bs[(kk + 4) * BSTR + n]);
            }
#pragma unroll
            for (int im = 0; im < 4; im++)
#pragma unroll
                for (int in_ = 0; in_ < 4; in_++)
                    asm volatile(
                        "mma.sync.aligned.m16n8k8.row.col.f32.tf32.tf32.f32 "
                        "{%0,%1,%2,%3}, {%4,%5,%6,%7}, {%8,%9}, {%0,%1,%2,%3};"
                        : "+f"(c[im][in_][0]), "+f"(c[im][in_][1]),
                          "+f"(c[im][in_][2]), "+f"(c[im][in_][3])
                        : "r"(a[im][0]), "r"(a[im][1]), "r"(a[im][2]), "r"(a[im][3]),
                          "r"(b[in_][0]), "r"(b[in_][1]));
        }

        int kn = ki + STAGES - 1;
        if (kn < nK) load_stage(kn % STAGES, kn * BK);
        cp_commit();
    }

    // ---- epilogue: registers -> smem -> coalesced stores (no atomics) ----
    __syncthreads();
    float* ep = sm;
#pragma unroll
    for (int im = 0; im < 4; im++) {
#pragma unroll
        for (int in_ = 0; in_ < 4; in_++) {
#pragma unroll
            for (int half = 0; half < 2; half++) {
                int rr = wm * 64 + im * 16 + half * 8 + (lane >> 2);
                int cc = wn * 32 + in_ * 8 + 2 * (lane & 3);
                float v0 = c[im][in_][half * 2 + 0];
                float v1 = c[im][in_][half * 2 + 1];
                if (PHASE == 0) {
                    v0 = gelu_f(v0);
                    v1 = gelu_f(v1);
                    if (!sh) {
                        float gate = s_gate[rr];
                        v0 *= gate; v1 *= gate;
                    }
                    v0 = __uint_as_float(f2tf(v0));   // store tf32-rounded
                    v1 = __uint_as_float(f2tf(v1));
                }
                ep[rr * EPI_PITCH + cc]     = v0;
                ep[rr * EPI_PITCH + cc + 1] = v1;
            }
        }
    }
    __syncthreads();

#pragma unroll
    for (int jj = 0; jj < 16; jj++) {
        int idx = tid + NTHR * jj;
        int r   = idx >> 5;
        int c4  = idx & 31;
        float4 v = *reinterpret_cast<float4*>(&ep[r * EPI_PITCH + c4 * 4]);
        int grow = m0 + r;
        int gcol = n0 + c4 * 4;
        if (PHASE == 0) {
            if (sh) {
                *reinterpret_cast<float4*>(
                    g_mid_sh + (size_t)e * T_TOK * D_DIM + (size_t)grow * D_DIM + gcol) = v;
            } else if (s_tok[r] >= 0) {
                *reinterpret_cast<float4*>(
                    g_mid_rt + ((size_t)e * T_TOK + grow) * D_DIM + gcol) = v;
            }
        } else {
            if (sh) {
                float* dst = (e == 0) ? OUT : g_out_sh1;
                *reinterpret_cast<float4*>(dst + (size_t)grow * H_DIM + gcol) = v;
            } else if (s_tok[r] >= 0) {
                *reinterpret_cast<float4*>(
                    g_out_rt + ((size_t)e * T_TOK + grow) * H_DIM + gcol) = v;
            }
        }
    }
}

// -------- final combine: out[t] += shared-expert-1 + both routed bucket rows --------
__global__ void combine_kernel(float4* __restrict__ out) {
    const int HQ = H_DIM / 4;
    int idx = blockIdx.x * blockDim.x + threadIdx.x;
    if (idx >= T_TOK * HQ) return;
    int t = idx >> 9;           // / HQ (512)
    int c = idx & (HQ - 1);
    int a0 = g_assign[2 * t];
    int a1 = g_assign[2 * t + 1];
    const float4* rt  = reinterpret_cast<const float4*>(g_out_rt);
    const float4* sh1 = reinterpret_cast<const float4*>(g_out_sh1);
    float4 o  = out[idx];
    float4 s1 = sh1[idx];
    float4 r0 = rt[(size_t)a0 * HQ + c];
    float4 r1 = rt[(size_t)a1 * HQ + c];
    o.x += s1.x + r0.x + r1.x;
    o.y += s1.y + r0.y + r1.y;
    o.z += s1.z + r0.z + r1.z;
    o.w += s1.w + r0.w + r1.w;
    out[idx] = o;
}

// ------------- launch: 3 concurrent GEMM chains, capture-legal fork-join -------------
extern "C" void kernel_launch(void* const* d_in, const int* in_sizes, int n_in,
                              void* d_out, int out_size) {
    const float* x      = (const float*)d_in[0];
    const float* Wsh_up = (const float*)d_in[1];
    const float* Wsh_dn = (const float*)d_in[2];
    const float* Wrt_up = (const float*)d_in[3];
    const float* Wrt_dn = (const float*)d_in[4];
    const float* Wr     = (const float*)d_in[5];
    float* out = (float*)d_out;

    // one-time handles (created on first, non-captured, correctness call)
    static cudaStream_t s2 = nullptr, s3 = nullptr;
    static cudaEvent_t evFork = nullptr, evConv = nullptr, evRouter = nullptr;
    static cudaEvent_t evJ2 = nullptr, evJ3 = nullptr;
    if (s2 == nullptr) {
        cudaStreamCreateWithFlags(&s2, cudaStreamNonBlocking);
        cudaStreamCreateWithFlags(&s3, cudaStreamNonBlocking);
        cudaEventCreateWithFlags(&evFork,   cudaEventDisableTiming);
        cudaEventCreateWithFlags(&evConv,   cudaEventDisableTiming);
        cudaEventCreateWithFlags(&evRouter, cudaEventDisableTiming);
        cudaEventCreateWithFlags(&evJ2,     cudaEventDisableTiming);
        cudaEventCreateWithFlags(&evJ3,     cudaEventDisableTiming);
        cudaFuncSetAttribute(gemm_fused<0>, cudaFuncAttributeMaxDynamicSharedMemorySize, SMEM_BYTES);
        cudaFuncSetAttribute(gemm_fused<1>, cudaFuncAttributeMaxDynamicSharedMemorySize, SMEM_BYTES);
    }

    float* d_xc;
    cudaGetSymbolAddress((void**)&d_xc, g_xc);

    // ---- fork FROM the capture-origin stream (stream 0) ----
    // First captured op must be on stream 0; side streams join via event wait.
    zero_cnt_kernel<<<1, 32>>>();
    cudaEventRecord(evFork, 0);
    cudaStreamWaitEvent(s2, evFork, 0);
    cudaStreamWaitEvent(s3, evFork, 0);

    // s2: x conversion (parallel with router) -> shared chain (needs conv only)
    conv_x_kernel<<<1184, 256, 0, s2>>>((const float4*)x, (float4*)d_xc);
    cudaEventRecord(evConv, s2);
    gemm_fused<0><<<dim3(D_DIM / BN, T_TOK / BM, NE_SH), NTHR, SMEM_BYTES, s2>>>(
        Wsh_up, Wrt_up, nullptr, /*zoff=*/0);
    gemm_fused<1><<<dim3(H_DIM / BN, T_TOK / BM, NE_SH), NTHR, SMEM_BYTES, s2>>>(
        Wrt_dn, Wsh_dn, out, /*zoff=*/16);
    cudaEventRecord(evJ2, s2);

    // s0: router (needs raw x + zeroed cnt only)
    router_kernel<<<T_TOK / 8, 256>>>(x, Wr);
    cudaEventRecord(evRouter, 0);

    // s0: routed chain, experts 0-7 (needs router [program order] + conv)
    cudaStreamWaitEvent(0, evConv, 0);
    gemm_fused<0><<<dim3(D_DIM / BN, T_TOK / BM, 8), NTHR, SMEM_BYTES>>>(
        Wsh_up, Wrt_up, nullptr, /*zoff=*/2);
    gemm_fused<1><<<dim3(H_DIM / BN, T_TOK / BM, 8), NTHR, SMEM_BYTES>>>(
        Wrt_dn, Wsh_dn, out, /*zoff=*/0);

    // s3: routed chain, experts 8-15 (needs conv + router)
    cudaStreamWaitEvent(s3, evConv, 0);
    cudaStreamWaitEvent(s3, evRouter, 0);
    gemm_fused<0><<<dim3(D_DIM / BN, T_TOK / BM, 8), NTHR, SMEM_BYTES, s3>>>(
        Wsh_up, Wrt_up, nullptr, /*zoff=*/10);
    gemm_fused<1><<<dim3(H_DIM / BN, T_TOK / BM, 8), NTHR, SMEM_BYTES, s3>>>(
        Wrt_dn, Wsh_dn, out, /*zoff=*/8);
    cudaEventRecord(evJ3, s3);

    // join + combine on s0
    cudaStreamWaitEvent(0, evJ2, 0);
    cudaStreamWaitEvent(0, evJ3, 0);
    combine_kernel<<<(T_TOK * (H_DIM / 4)) / 256, 256>>>((float4*)out);
}

// round 15
// speedup vs baseline: 2.6513x; 1.3435x over previous
#include <cuda_runtime.h>
#include <cuda_fp16.h>
#include <math.h>
#include <stdint.h>

#define T_TOK 4096
#define H_DIM 2048
#define D_DIM 1024
#define NE_RT 16
#define NE_SH 2

// ---------------- scratch (device globals; no allocations) ----------------
__device__ int    g_cnt[NE_RT];
__device__ int    g_tok[NE_RT * T_TOK];
__device__ float  g_gate[NE_RT * T_TOK];
__device__ int    g_assign[2 * T_TOK];
__device__ float  g_out_rt[(size_t)NE_RT * T_TOK * H_DIM];
__device__ float  g_out_sh1[(size_t)T_TOK * H_DIM];
// fp16 operands
__device__ __half g_x16[(size_t)T_TOK * H_DIM];
__device__ __half g_wsh_up16[(size_t)NE_SH * H_DIM * D_DIM];
__device__ __half g_wrt_up16[(size_t)NE_RT * H_DIM * D_DIM];
__device__ __half g_wsh_dn16[(size_t)NE_SH * D_DIM * H_DIM];
__device__ __half g_wrt_dn16[(size_t)NE_RT * D_DIM * H_DIM];
__device__ __half g_mid_sh16[(size_t)NE_SH * T_TOK * D_DIM];
__device__ __half g_mid_rt16[(size_t)NE_RT * T_TOK * D_DIM];

// ---------------- helpers ----------------
__device__ __forceinline__ uint32_t pack_half2(float lo, float hi) {
    uint32_t r;
    asm("cvt.rn.f16x2.f32 %0, %1, %2;" : "=r"(r) : "f"(hi), "f"(lo));
    return r;
}
__device__ __forceinline__ float gelu_f(float v) {
    return 0.5f * v * (1.0f + erff(v * 0.70710678118654752440f));
}
__device__ __forceinline__ void cp16(uint32_t dst_smem, const void* src, bool pred) {
    int sz = pred ? 16 : 0;
    asm volatile("cp.async.cg.shared.global [%0], [%1], 16, %2;\n"
                 :: "r"(dst_smem), "l"(src), "r"(sz) : "memory");
}
__device__ __forceinline__ void cp_commit() {
    asm volatile("cp.async.commit_group;" ::: "memory");
}
__device__ __forceinline__ void ldsm_x4_trans(uint32_t& r0, uint32_t& r1,
                                              uint32_t& r2, uint32_t& r3,
                                              uint32_t addr) {
    asm volatile("ldmatrix.sync.aligned.m8n8.x4.trans.shared.b16 {%0,%1,%2,%3}, [%4];"
                 : "=r"(r0), "=r"(r1), "=r"(r2), "=r"(r3) : "r"(addr));
}

// ---------------- fp32 -> fp16 streaming convert ----------------
__global__ void conv16_kernel(const float4* __restrict__ src,
                              uint4* __restrict__ dst, int n8) {
    int stride = gridDim.x * blockDim.x;
    for (int i = blockIdx.x * blockDim.x + threadIdx.x; i < n8; i += stride) {
        float4 a = src[2 * i], b = src[2 * i + 1];
        uint4 o;
        o.x = pack_half2(a.x, a.y);
        o.y = pack_half2(a.z, a.w);
        o.z = pack_half2(b.x, b.y);
        o.w = pack_half2(b.z, b.w);
        dst[i] = o;
    }
}

__global__ void zero_cnt_kernel() {
    if (threadIdx.x < NE_RT) g_cnt[threadIdx.x] = 0;
}

// ---------------- router (fp32, unchanged) ----------------
__global__ void router_kernel(const float* __restrict__ x,
                              const float* __restrict__ Wr) {
    int warp = threadIdx.x >> 5;
    int lane = threadIdx.x & 31;
    int t = blockIdx.x * 8 + warp;
    if (t >= T_TOK) return;

    float acc[NE_RT];
#pragma unroll
    for (int e = 0; e < NE_RT; e++) acc[e] = 0.f;

    const float* xr = x + (size_t)t * H_DIM;
    for (int h = lane; h < H_DIM; h += 32) {
        float xv = xr[h];
        const float4* w4 = reinterpret_cast<const float4*>(Wr + (size_t)h * NE_RT);
#pragma unroll
        for (int q = 0; q < 4; q++) {
            float4 w = w4[q];
            acc[4*q+0] += xv * w.x;
            acc[4*q+1] += xv * w.y;
            acc[4*q+2] += xv * w.z;
            acc[4*q+3] += xv * w.w;
        }
    }
#pragma unroll
    for (int e = 0; e < NE_RT; e++) {
#pragma unroll
        for (int off = 16; off > 0; off >>= 1)
            acc[e] += __shfl_xor_sync(0xffffffffu, acc[e], off);
    }
    if (lane == 0) {
        float mx = acc[0];
#pragma unroll
        for (int e = 1; e < NE_RT; e++) mx = fmaxf(mx, acc[e]);
        float p[NE_RT];
        float s = 0.f;
#pragma unroll
        for (int e = 0; e < NE_RT; e++) { p[e] = expf(acc[e] - mx); s += p[e]; }
        float inv = 1.0f / s;

        int i1 = 0; float v1 = p[0];
#pragma unroll
        for (int e = 1; e < NE_RT; e++) if (p[e] > v1) { v1 = p[e]; i1 = e; }
        int i2 = -1; float v2 = -1.f;
#pragma unroll
        for (int e = 0; e < NE_RT; e++) if (e != i1 && p[e] > v2) { v2 = p[e]; i2 = e; }

        int pos = atomicAdd(&g_cnt[i1], 1);
        g_tok[i1 * T_TOK + pos]  = t;
        g_gate[i1 * T_TOK + pos] = v1 * inv;
        g_assign[2 * t]          = i1 * T_TOK + pos;
        pos = atomicAdd(&g_cnt[i2], 1);
        g_tok[i2 * T_TOK + pos]  = t;
        g_gate[i2 * T_TOK + pos] = v2 * inv;
        g_assign[2 * t + 1]      = i2 * T_TOK + pos;
    }
}

// ------ fp16 GEMM: 3-stage cp.async, 128x128x32 tile, m16n8k16, ldmatrix B ------
// z = blockIdx.z + zoff:
// PHASE 0 (up, K=2048): z<2 shared e=z; z>=2 routed e=z-2 (gather+gate), mid fp16
// PHASE 1 (down, K=1024): z<16 routed e=z (bucket fp32); z==16 -> OUT; z==17 -> out_sh1

#define BM 128
#define BN 128
#define BK 32
#define STAGES 3
#define NTHR 256
#define AP 20                       // A smem pitch, 32-bit words (fp16x2 k-pairs)
#define BP 68                       // B smem pitch, words (128 fp16 + pad)
#define A_W16 (BM * AP)             // 2560
#define B_W16 (BK * BP)             // 2176
#define STG_W (A_W16 + B_W16)       // 4736 words = 18944 B
#define EPI_PITCH 132               // phase-1 fp32 epilogue pitch (floats)
#define EP16 68                     // phase-0 fp16 epilogue pitch (words)
#define SMEM_BYTES (BM * EPI_PITCH * 4)   // 67584 > 3*STG_W*4 = 56832

template <int PHASE>
__global__ void __launch_bounds__(NTHR) gemm_fused(float* __restrict__ OUT, int zoff) {
    constexpr int NN   = (PHASE == 0) ? 1024 : 2048;   // B row length (fp16 elems)
    constexpr int LDA  = (PHASE == 0) ? 2048 : 1024;   // A row length (fp16 elems)
    constexpr int KTOT = (PHASE == 0) ? 2048 : 1024;
    constexpr int nK   = KTOT / BK;

    const int z  = blockIdx.z + zoff;
    const bool sh = (PHASE == 0) ? (z < 2) : (z >= 16);
    const int e  = (PHASE == 0) ? (sh ? z : z - 2) : (sh ? z - 16 : z);

    const int m0 = blockIdx.y * BM;
    const int n0 = blockIdx.x * BN;

    int cnt = T_TOK;
    if (!sh) {
        cnt = g_cnt[e];
        if (m0 >= cnt) return;
    }

    extern __shared__ float sm[];
    __shared__ int   s_tok[BM];
    __shared__ float s_gate[BM];

    const int tid  = threadIdx.x;
    const int lane = tid & 31;
    const int warp = tid >> 5;
    const int wm   = warp >> 2;   // 0..1 (64-row band)
    const int wn   = warp & 3;    // 0..3 (32-col band)

    const __half* Abase;
    const __half* Bbase;
    if (PHASE == 0) {
        Abase = g_x16;
        Bbase = (sh ? g_wsh_up16 : g_wrt_up16) + (size_t)e * H_DIM * D_DIM;
    } else {
        if (sh) {
            Abase = g_mid_sh16 + (size_t)e * T_TOK * D_DIM;
            Bbase = g_wsh_dn16 + (size_t)e * D_DIM * H_DIM;
        } else {
            Abase = g_mid_rt16 + (size_t)e * T_TOK * D_DIM;
            Bbase = g_wrt_dn16 + (size_t)e * D_DIM * H_DIM;
        }
    }

    if (tid < BM) {
        int grow = m0 + tid;
        int tok;
        float gate = 0.f;
        if (sh) {
            tok = grow;
        } else if (PHASE == 0) {
            if (grow < cnt) {
                tok  = g_tok[e * T_TOK + grow];
                gate = g_gate[e * T_TOK + grow];
            } else tok = -1;
        } else {
            tok = (grow < cnt) ? grow : -1;
        }
        s_tok[tid]  = tok;
        s_gate[tid] = gate;
    }
    __syncthreads();

    // per-thread A staging coords (2 chunks/thread, invariant across k)
    int  a_srow[2];
    bool a_valid[2];
#pragma unroll
    for (int j = 0; j < 2; j++) {
        int r   = (tid + NTHR * j) >> 2;
        int tok = s_tok[r];
        if (PHASE == 0 && !sh) { a_valid[j] = tok >= 0; a_srow[j] = a_valid[j] ? tok : 0; }
        else                   { a_valid[j] = tok >= 0; a_srow[j] = m0 + r; }
    }

    const uint32_t sm_u32 = (uint32_t)__cvta_generic_to_shared(sm);

    auto load_stage = [&](int s, int k0) {
        uint32_t a_sm = sm_u32 + (uint32_t)(s * STG_W) * 4;
        uint32_t b_sm = a_sm + A_W16 * 4;
#pragma unroll
        for (int j = 0; j < 2; j++) {              // A: 128 rows x 4 chunks (8 fp16)
            int idx = tid + NTHR * j;
            int r   = idx >> 2;
            int c4  = idx & 3;
            const __half* src = Abase + (size_t)a_srow[j] * LDA + k0 + c4 * 8;
            cp16(a_sm + (uint32_t)(r * AP + c4 * 4) * 4, src, a_valid[j]);
        }
#pragma unroll
        for (int j = 0; j < 2; j++) {              // B: 32 k-rows x 16 chunks
            int idx = tid + NTHR * j;
            int r   = idx >> 4;
            int c4  = idx & 15;
            const __half* src = Bbase + (size_t)(k0 + r) * NN + n0 + c4 * 8;
            cp16(b_sm + (uint32_t)(r * BP + c4 * 4) * 4, src, true);
        }
    };

    float c[4][4][4];
#pragma unroll
    for (int i = 0; i < 4; i++)
#pragma unroll
        for (int j = 0; j < 4; j++)
#pragma unroll
            for (int q = 0; q < 4; q++) c[i][j][q] = 0.f;

#pragma unroll
    for (int s = 0; s < STAGES - 1; s++) {
        load_stage(s, s * BK);
        cp_commit();
    }

    for (int ki = 0; ki < nK; ki++) {
        asm volatile("cp.async.wait_group %0;" :: "n"(STAGES - 2) : "memory");
        __syncthreads();

        const int st = ki % STAGES;
        const uint32_t* Aw = reinterpret_cast<const uint32_t*>(sm) + st * STG_W;
        const uint32_t bs_u32 = sm_u32 + (uint32_t)(st * STG_W + A_W16) * 4;

#pragma unroll
        for (int s = 0; s < 2; s++) {              // two k16 steps per BK=32
            const int cb = s * 8 + (lane & 3);
            uint32_t a[4][4];
#pragma unroll
            for (int im = 0; im < 4; im++) {
                int m = wm * 64 + im * 16 + (lane >> 2);
                a[im][0] = Aw[m * AP + cb];
                a[im][1] = Aw[(m + 8) * AP + cb];
                a[im][2] = Aw[m * AP + cb + 4];
                a[im][3] = Aw[(m + 8) * AP + cb + 4];
            }
            // B fragments via ldmatrix.trans: 4 n-tiles x (k0-7, k8-15)
            uint32_t b0[4], b1[4];
            uint32_t addr0 = bs_u32 +
                (uint32_t)((s * 16 + (lane & 7)) * BP) * 4 +
                (uint32_t)(wn * 32 + (lane >> 3) * 8) * 2;
            ldsm_x4_trans(b0[0], b0[1], b0[2], b0[3], addr0);
            ldsm_x4_trans(b1[0], b1[1], b1[2], b1[3], addr0 + 8 * BP * 4);
#pragma unroll
            for (int im = 0; im < 4; im++)
#pragma unroll
                for (int in_ = 0; in_ < 4; in_++)
                    asm volatile(
                        "mma.sync.aligned.m16n8k16.row.col.f32.f16.f16.f32 "
                        "{%0,%1,%2,%3}, {%4,%5,%6,%7}, {%8,%9}, {%0,%1,%2,%3};"
                        : "+f"(c[im][in_][0]), "+f"(c[im][in_][1]),
                          "+f"(c[im][in_][2]), "+f"(c[im][in_][3])
                        : "r"(a[im][0]), "r"(a[im][1]), "r"(a[im][2]), "r"(a[im][3]),
                          "r"(b0[in_]), "r"(b1[in_]));
        }

        int kn = ki + STAGES - 1;
        if (kn < nK) load_stage(kn % STAGES, kn * BK);
        cp_commit();
    }

    __syncthreads();

    if (PHASE == 0) {
        // ---- fp16 epilogue: gelu(+gate) -> packed fp16x2 smem -> uint4 stores ----
        uint32_t* epw = reinterpret_cast<uint32_t*>(sm);
#pragma unroll
        for (int im = 0; im < 4; im++) {
#pragma unroll
            for (int in_ = 0; in_ < 4; in_++) {
#pragma unroll
                for (int half = 0; half < 2; half++) {
                    int rr  = wm * 64 + im * 16 + half * 8 + (lane >> 2);
                    int ccw = wn * 16 + in_ * 4 + (lane & 3);
                    float v0 = gelu_f(c[im][in_][half * 2 + 0]);
                    float v1 = gelu_f(c[im][in_][half * 2 + 1]);
                    if (!sh) {
                        float gate = s_gate[rr];
                        v0 *= gate; v1 *= gate;
                    }
                    epw[rr * EP16 + ccw] = pack_half2(v0, v1);
                }
            }
        }
        __syncthreads();

        __half* mid = sh ? (g_mid_sh16 + (size_t)e * T_TOK * D_DIM)
                         : (g_mid_rt16 + (size_t)e * T_TOK * D_DIM);
#pragma unroll
        for (int jj = 0; jj < 8; jj++) {
            int idx = tid + NTHR * jj;
            int r   = idx >> 4;
            int c4  = idx & 15;
            uint4 v = *reinterpret_cast<uint4*>(&epw[r * EP16 + c4 * 4]);
            int grow = m0 + r;
            if (sh || s_tok[r] >= 0) {
                uint4* dst = reinterpret_cast<uint4*>(
                    mid + (size_t)grow * D_DIM + n0) + c4;
                *dst = v;
            }
        }
    } else {
        // ---- fp32 epilogue (unchanged): smem pitch 132 -> float4 stores ----
        float* ep = sm;
#pragma unroll
        for (int im = 0; im < 4; im++) {
#pragma unroll
            for (int in_ = 0; in_ < 4; in_++) {
#pragma unroll
                for (int half = 0; half < 2; half++) {
                    int rr = wm * 64 + im * 16 + half * 8 + (lane >> 2);
                    int cc = wn * 32 + in_ * 8 + 2 * (lane & 3);
                    ep[rr * EPI_PITCH + cc]     = c[im][in_][half * 2 + 0];
                    ep[rr * EPI_PITCH + cc + 1] = c[im][in_][half * 2 + 1];
                }
            }
        }
        __syncthreads();

#pragma unroll
        for (int jj = 0; jj < 16; jj++) {
            int idx = tid + NTHR * jj;
            int r   = idx >> 5;
            int c4  = idx & 31;
            float4 v = *reinterpret_cast<float4*>(&ep[r * EPI_PITCH + c4 * 4]);
            int grow = m0 + r;
            int gcol = n0 + c4 * 4;
            if (sh) {
                float* dst = (e == 0) ? OUT : g_out_sh1;
                *reinterpret_cast<float4*>(dst + (size_t)grow * H_DIM + gcol) = v;
            } else if (s_tok[r] >= 0) {
                *reinterpret_cast<float4*>(
                    g_out_rt + ((size_t)e * T_TOK + grow) * H_DIM + gcol) = v;
            }
        }
    }
}

// -------- final combine: out[t] += shared-expert-1 + both routed bucket rows --------
__global__ void combine_kernel(float4* __restrict__ out) {
    const int HQ = H_DIM / 4;
    int idx = blockIdx.x * blockDim.x + threadIdx.x;
    if (idx >= T_TOK * HQ) return;
    int t = idx >> 9;
    int c = idx & (HQ - 1);
    int a0 = g_assign[2 * t];
    int a1 = g_assign[2 * t + 1];
    const float4* rt  = reinterpret_cast<const float4*>(g_out_rt);
    const float4* sh1 = reinterpret_cast<const float4*>(g_out_sh1);
    float4 o  = out[idx];
    float4 s1 = sh1[idx];
    float4 r0 = rt[(size_t)a0 * HQ + c];
    float4 r1 = rt[(size_t)a1 * HQ + c];
    o.x += s1.x + r0.x + r1.x;
    o.y += s1.y + r0.y + r1.y;
    o.z += s1.z + r0.z + r1.z;
    o.w += s1.w + r0.w + r1.w;
    out[idx] = o;
}

// ------------- launch: fp16 convert prologue + 3 concurrent GEMM chains -------------
extern "C" void kernel_launch(void* const* d_in, const int* in_sizes, int n_in,
                              void* d_out, int out_size) {
    const float* x      = (const float*)d_in[0];
    const float* Wsh_up = (const float*)d_in[1];
    const float* Wsh_dn = (const float*)d_in[2];
    const float* Wrt_up = (const float*)d_in[3];
    const float* Wrt_dn = (const float*)d_in[4];
    const float* Wr     = (const float*)d_in[5];
    float* out = (float*)d_out;

    static cudaStream_t s2 = nullptr, s3 = nullptr;
    static cudaEvent_t evFork = nullptr, evCup = nullptr, evCdn = nullptr,
                       evRouter = nullptr, evJ2 = nullptr, evJ3 = nullptr;
    if (s2 == nullptr) {
        cudaStreamCreateWithFlags(&s2, cudaStreamNonBlocking);
        cudaStreamCreateWithFlags(&s3, cudaStreamNonBlocking);
        cudaEventCreateWithFlags(&evFork,   cudaEventDisableTiming);
        cudaEventCreateWithFlags(&evCup,    cudaEventDisableTiming);
        cudaEventCreateWithFlags(&evCdn,    cudaEventDisableTiming);
        cudaEventCreateWithFlags(&evRouter, cudaEventDisableTiming);
        cudaEventCreateWithFlags(&evJ2,     cudaEventDisableTiming);
        cudaEventCreateWithFlags(&evJ3,     cudaEventDisableTiming);
        cudaFuncSetAttribute(gemm_fused<0>, cudaFuncAttributeMaxDynamicSharedMemorySize, SMEM_BYTES);
        cudaFuncSetAttribute(gemm_fused<1>, cudaFuncAttributeMaxDynamicSharedMemorySize, SMEM_BYTES);
    }

    void *d_x16, *d_wshup, *d_wrtup, *d_wshdn, *d_wrtdn;
    cudaGetSymbolAddress(&d_x16,   g_x16);
    cudaGetSymbolAddress(&d_wshup, g_wsh_up16);
    cudaGetSymbolAddress(&d_wrtup, g_wrt_up16);
    cudaGetSymbolAddress(&d_wshdn, g_wsh_dn16);
    cudaGetSymbolAddress(&d_wrtdn, g_wrt_dn16);

    // fork from origin stream
    zero_cnt_kernel<<<1, 32>>>();
    cudaEventRecord(evFork, 0);
    cudaStreamWaitEvent(s2, evFork, 0);
    cudaStreamWaitEvent(s3, evFork, 0);

    // s2: convert x + up weights -> up-shared
    conv16_kernel<<<592, 256, 0, s2>>>((const float4*)x, (uint4*)d_x16,
                                       T_TOK * H_DIM / 8);
    conv16_kernel<<<128, 256, 0, s2>>>((const float4*)Wsh_up, (uint4*)d_wshup,
                                       NE_SH * H_DIM * D_DIM / 8);
    conv16_kernel<<<1184, 256, 0, s2>>>((const float4*)Wrt_up, (uint4*)d_wrtup,
                                        NE_RT * H_DIM * D_DIM / 8);
    cudaEventRecord(evCup, s2);
    gemm_fused<0><<<dim3(D_DIM / BN, T_TOK / BM, NE_SH), NTHR, SMEM_BYTES, s2>>>(
        nullptr, /*zoff=*/0);

    // s3: convert down weights
    conv16_kernel<<<128, 256, 0, s3>>>((const float4*)Wsh_dn, (uint4*)d_wshdn,
                                       NE_SH * D_DIM * H_DIM / 8);
    conv16_kernel<<<1184, 256, 0, s3>>>((const float4*)Wrt_dn, (uint4*)d_wrtdn,
                                        NE_RT * D_DIM * H_DIM / 8);
    cudaEventRecord(evCdn, s3);

    // s0: router
    router_kernel<<<T_TOK / 8, 256>>>(x, Wr);
    cudaEventRecord(evRouter, 0);

    // s0: routed experts 0-7
    cudaStreamWaitEvent(0, evCup, 0);
    gemm_fused<0><<<dim3(D_DIM / BN, T_TOK / BM, 8), NTHR, SMEM_BYTES>>>(
        nullptr, /*zoff=*/2);
    cudaStreamWaitEvent(0, evCdn, 0);
    gemm_fused<1><<<dim3(H_DIM / BN, T_TOK / BM, 8), NTHR, SMEM_BYTES>>>(
        out, /*zoff=*/0);

    // s3: routed experts 8-15 (conv_dn done in program order on s3)
    cudaStreamWaitEvent(s3, evCup, 0);
    cudaStreamWaitEvent(s3, evRouter, 0);
    gemm_fused<0><<<dim3(D_DIM / BN, T_TOK / BM, 8), NTHR, SMEM_BYTES, s3>>>(
        nullptr, /*zoff=*/10);
    gemm_fused<1><<<dim3(H_DIM / BN, T_TOK / BM, 8), NTHR, SMEM_BYTES, s3>>>(
        out, /*zoff=*/8);
    cudaEventRecord(evJ3, s3);

    // s2: down-shared (needs down weights)
    cudaStreamWaitEvent(s2, evCdn, 0);
    gemm_fused<1><<<dim3(H_DIM / BN, T_TOK / BM, NE_SH), NTHR, SMEM_BYTES, s2>>>(
        out, /*zoff=*/16);
    cudaEventRecord(evJ2, s2);

    // join + combine
    cudaStreamWaitEvent(0, evJ2, 0);
    cudaStreamWaitEvent(0, evJ3, 0);
    combine_kernel<<<(T_TOK * (H_DIM / 4)) / 256, 256>>>((float4*)out);
}

// round 16
// speedup vs baseline: 2.9460x; 1.1112x over previous
#include <cuda_runtime.h>
#include <cuda_fp16.h>
#include <math.h>
#include <stdint.h>

#define T_TOK 4096
#define H_DIM 2048
#define D_DIM 1024
#define NE_RT 16
#define NE_SH 2

// ---------------- scratch (device globals; no allocations) ----------------
__device__ int    g_cnt[NE_RT];
__device__ int    g_tok[NE_RT * T_TOK];
__device__ float  g_gate[NE_RT * T_TOK];
__device__ int    g_assign[2 * T_TOK];
__device__ float  g_out_rt[(size_t)NE_RT * T_TOK * H_DIM];
__device__ float  g_out_sh1[(size_t)T_TOK * H_DIM];
// fp16 operands
__device__ __half g_x16[(size_t)T_TOK * H_DIM];
__device__ __half g_wsh_up16[(size_t)NE_SH * H_DIM * D_DIM];
__device__ __half g_wrt_up16[(size_t)NE_RT * H_DIM * D_DIM];
__device__ __half g_wsh_dn16[(size_t)NE_SH * D_DIM * H_DIM];
__device__ __half g_wrt_dn16[(size_t)NE_RT * D_DIM * H_DIM];
__device__ __half g_mid_sh16[(size_t)NE_SH * T_TOK * D_DIM];
__device__ __half g_mid_rt16[(size_t)NE_RT * T_TOK * D_DIM];

// ---------------- helpers ----------------
__device__ __forceinline__ uint32_t pack_half2(float lo, float hi) {
    uint32_t r;
    asm("cvt.rn.f16x2.f32 %0, %1, %2;" : "=r"(r) : "f"(hi), "f"(lo));
    return r;
}
__device__ __forceinline__ float gelu_f(float v) {
    return 0.5f * v * (1.0f + erff(v * 0.70710678118654752440f));
}
__device__ __forceinline__ void cp16(uint32_t dst_smem, const void* src, bool pred) {
    int sz = pred ? 16 : 0;
    asm volatile("cp.async.cg.shared.global [%0], [%1], 16, %2;\n"
                 :: "r"(dst_smem), "l"(src), "r"(sz) : "memory");
}
__device__ __forceinline__ void cp_commit() {
    asm volatile("cp.async.commit_group;" ::: "memory");
}
__device__ __forceinline__ void ldsm_x4(uint32_t& r0, uint32_t& r1,
                                        uint32_t& r2, uint32_t& r3,
                                        uint32_t addr) {
    asm volatile("ldmatrix.sync.aligned.m8n8.x4.shared.b16 {%0,%1,%2,%3}, [%4];"
                 : "=r"(r0), "=r"(r1), "=r"(r2), "=r"(r3) : "r"(addr));
}
__device__ __forceinline__ void ldsm_x4_trans(uint32_t& r0, uint32_t& r1,
                                              uint32_t& r2, uint32_t& r3,
                                              uint32_t addr) {
    asm volatile("ldmatrix.sync.aligned.m8n8.x4.trans.shared.b16 {%0,%1,%2,%3}, [%4];"
                 : "=r"(r0), "=r"(r1), "=r"(r2), "=r"(r3) : "r"(addr));
}

// ---------------- fp32 -> fp16 streaming convert ----------------
__global__ void conv16_kernel(const float4* __restrict__ src,
                              uint4* __restrict__ dst, int n8) {
    int stride = gridDim.x * blockDim.x;
    for (int i = blockIdx.x * blockDim.x + threadIdx.x; i < n8; i += stride) {
        float4 a = src[2 * i], b = src[2 * i + 1];
        uint4 o;
        o.x = pack_half2(a.x, a.y);
        o.y = pack_half2(a.z, a.w);
        o.z = pack_half2(b.x, b.y);
        o.w = pack_half2(b.z, b.w);
        dst[i] = o;
    }
}

__global__ void zero_cnt_kernel() {
    if (threadIdx.x < NE_RT) g_cnt[threadIdx.x] = 0;
}

// ---------------- router (fp32, unchanged) ----------------
__global__ void router_kernel(const float* __restrict__ x,
                              const float* __restrict__ Wr) {
    int warp = threadIdx.x >> 5;
    int lane = threadIdx.x & 31;
    int t = blockIdx.x * 8 + warp;
    if (t >= T_TOK) return;

    float acc[NE_RT];
#pragma unroll
    for (int e = 0; e < NE_RT; e++) acc[e] = 0.f;

    const float* xr = x + (size_t)t * H_DIM;
    for (int h = lane; h < H_DIM; h += 32) {
        float xv = xr[h];
        const float4* w4 = reinterpret_cast<const float4*>(Wr + (size_t)h * NE_RT);
#pragma unroll
        for (int q = 0; q < 4; q++) {
            float4 w = w4[q];
            acc[4*q+0] += xv * w.x;
            acc[4*q+1] += xv * w.y;
            acc[4*q+2] += xv * w.z;
            acc[4*q+3] += xv * w.w;
        }
    }
#pragma unroll
    for (int e = 0; e < NE_RT; e++) {
#pragma unroll
        for (int off = 16; off > 0; off >>= 1)
            acc[e] += __shfl_xor_sync(0xffffffffu, acc[e], off);
    }
    if (lane == 0) {
        float mx = acc[0];
#pragma unroll
        for (int e = 1; e < NE_RT; e++) mx = fmaxf(mx, acc[e]);
        float p[NE_RT];
        float s = 0.f;
#pragma unroll
        for (int e = 0; e < NE_RT; e++) { p[e] = expf(acc[e] - mx); s += p[e]; }
        float inv = 1.0f / s;

        int i1 = 0; float v1 = p[0];
#pragma unroll
        for (int e = 1; e < NE_RT; e++) if (p[e] > v1) { v1 = p[e]; i1 = e; }
        int i2 = -1; float v2 = -1.f;
#pragma unroll
        for (int e = 0; e < NE_RT; e++) if (e != i1 && p[e] > v2) { v2 = p[e]; i2 = e; }

        int pos = atomicAdd(&g_cnt[i1], 1);
        g_tok[i1 * T_TOK + pos]  = t;
        g_gate[i1 * T_TOK + pos] = v1 * inv;
        g_assign[2 * t]          = i1 * T_TOK + pos;
        pos = atomicAdd(&g_cnt[i2], 1);
        g_tok[i2 * T_TOK + pos]  = t;
        g_gate[i2 * T_TOK + pos] = v2 * inv;
        g_assign[2 * t + 1]      = i2 * T_TOK + pos;
    }
}

// ---- fp16 GEMM: 3-stage cp.async, 128x128x64 tile, ldmatrix A+B, m16n8k16 ----
// z = blockIdx.z + zoff:
// PHASE 0 (up, K=2048): z<2 shared e=z; z>=2 routed e=z-2 (gather+gate), mid fp16
// PHASE 1 (down, K=1024): z<16 routed e=z (bucket fp32); z==16 -> OUT; z==17 -> out_sh1

#define BM 128
#define BN 128
#define BK 64
#define STAGES 3
#define NTHR 256
#define AP 36                       // A smem pitch in words (64 halves + pad)
#define BP 68                       // B smem pitch in words (128 halves + pad)
#define A_W (BM * AP)               // 4608 words
#define B_W (BK * BP)               // 4352 words
#define STG_W (A_W + B_W)           // 8960 words = 35840 B
#define EPI_PITCH 132
#define EP16 68
#define SMEM_BYTES (STAGES * STG_W * 4)   // 107520 B (>= epilogue 67584)

template <int PHASE>
__global__ void __launch_bounds__(NTHR) gemm_fused(float* __restrict__ OUT, int zoff) {
    constexpr int NN   = (PHASE == 0) ? 1024 : 2048;
    constexpr int LDA  = (PHASE == 0) ? 2048 : 1024;
    constexpr int KTOT = (PHASE == 0) ? 2048 : 1024;
    constexpr int nK   = KTOT / BK;

    const int z  = blockIdx.z + zoff;
    const bool sh = (PHASE == 0) ? (z < 2) : (z >= 16);
    const int e  = (PHASE == 0) ? (sh ? z : z - 2) : (sh ? z - 16 : z);

    const int m0 = blockIdx.y * BM;
    const int n0 = blockIdx.x * BN;

    int cnt = T_TOK;
    if (!sh) {
        cnt = g_cnt[e];
        if (m0 >= cnt) return;
    }

    extern __shared__ float sm[];
    __shared__ int   s_tok[BM];
    __shared__ float s_gate[BM];

    const int tid  = threadIdx.x;
    const int lane = tid & 31;
    const int warp = tid >> 5;
    const int wm   = warp >> 2;
    const int wn   = warp & 3;

    const __half* Abase;
    const __half* Bbase;
    if (PHASE == 0) {
        Abase = g_x16;
        Bbase = (sh ? g_wsh_up16 : g_wrt_up16) + (size_t)e * H_DIM * D_DIM;
    } else {
        if (sh) {
            Abase = g_mid_sh16 + (size_t)e * T_TOK * D_DIM;
            Bbase = g_wsh_dn16 + (size_t)e * D_DIM * H_DIM;
        } else {
            Abase = g_mid_rt16 + (size_t)e * T_TOK * D_DIM;
            Bbase = g_wrt_dn16 + (size_t)e * D_DIM * H_DIM;
        }
    }

    if (tid < BM) {
        int grow = m0 + tid;
        int tok;
        float gate = 0.f;
        if (sh) {
            tok = grow;
        } else if (PHASE == 0) {
            if (grow < cnt) {
                tok  = g_tok[e * T_TOK + grow];
                gate = g_gate[e * T_TOK + grow];
            } else tok = -1;
        } else {
            tok = (grow < cnt) ? grow : -1;
        }
        s_tok[tid]  = tok;
        s_gate[tid] = gate;
    }
    __syncthreads();

    // per-thread A staging coords (4 chunks/thread: 128 rows x 8 chunks of 8 halves)
    int  a_srow[4];
    bool a_valid[4];
#pragma unroll
    for (int j = 0; j < 4; j++) {
        int r   = (tid + NTHR * j) >> 3;
        int tok = s_tok[r];
        if (PHASE == 0 && !sh) { a_valid[j] = tok >= 0; a_srow[j] = a_valid[j] ? tok : 0; }
        else                   { a_valid[j] = tok >= 0; a_srow[j] = m0 + r; }
    }

    const uint32_t sm_u32 = (uint32_t)__cvta_generic_to_shared(sm);

    auto load_stage = [&](int s, int k0) {
        uint32_t a_sm = sm_u32 + (uint32_t)(s * STG_W) * 4;
        uint32_t b_sm = a_sm + A_W * 4;
#pragma unroll
        for (int j = 0; j < 4; j++) {              // A: 128 rows x 8 chunks
            int idx = tid + NTHR * j;
            int r   = idx >> 3;
            int c4  = idx & 7;
            const __half* src = Abase + (size_t)a_srow[j] * LDA + k0 + c4 * 8;
            cp16(a_sm + (uint32_t)(r * AP + c4 * 4) * 4, src, a_valid[j]);
        }
#pragma unroll
        for (int j = 0; j < 4; j++) {              // B: 64 k-rows x 16 chunks
            int idx = tid + NTHR * j;
            int r   = idx >> 4;
            int c4  = idx & 15;
            const __half* src = Bbase + (size_t)(k0 + r) * NN + n0 + c4 * 8;
            cp16(b_sm + (uint32_t)(r * BP + c4 * 4) * 4, src, true);
        }
    };

    float c[4][4][4];
#pragma unroll
    for (int i = 0; i < 4; i++)
#pragma unroll
        for (int j = 0; j < 4; j++)
#pragma unroll
            for (int q = 0; q < 4; q++) c[i][j][q] = 0.f;

#pragma unroll
    for (int s = 0; s < STAGES - 1; s++) {
        load_stage(s, s * BK);
        cp_commit();
    }

    // A ldmatrix lane addressing (invariant parts)
    const int a_lrow = ((lane >> 3) & 1) * 8 + (lane & 7);  // row within m16 tile pair
    const int a_kw   = (lane >> 4) * 4;                     // klo/khi word offset

    for (int ki = 0; ki < nK; ki++) {
        asm volatile("cp.async.wait_group %0;" :: "n"(STAGES - 2) : "memory");
        __syncthreads();

        const int st = ki % STAGES;
        const uint32_t as_u32 = sm_u32 + (uint32_t)(st * STG_W) * 4;
        const uint32_t bs_u32 = as_u32 + A_W * 4;

#pragma unroll
        for (int s = 0; s < 4; s++) {              // four k16 steps per BK=64
            uint32_t a[4][4];
#pragma unroll
            for (int im = 0; im < 4; im++) {
                uint32_t arow = wm * 64 + im * 16 + a_lrow;
                uint32_t aaddr = as_u32 + (uint32_t)(arow * AP + s * 8 + a_kw) * 4;
                ldsm_x4(a[im][0], a[im][1], a[im][2], a[im][3], aaddr);
            }
            uint32_t b0[4], b1[4];
            uint32_t addr0 = bs_u32 +
                (uint32_t)((s * 16 + (lane & 7)) * BP) * 4 +
                (uint32_t)(wn * 32 + (lane >> 3) * 8) * 2;
            ldsm_x4_trans(b0[0], b0[1], b0[2], b0[3], addr0);
            ldsm_x4_trans(b1[0], b1[1], b1[2], b1[3], addr0 + 8 * BP * 4);
#pragma unroll
            for (int im = 0; im < 4; im++)
#pragma unroll
                for (int in_ = 0; in_ < 4; in_++)
                    asm volatile(
                        "mma.sync.aligned.m16n8k16.row.col.f32.f16.f16.f32 "
                        "{%0,%1,%2,%3}, {%4,%5,%6,%7}, {%8,%9}, {%0,%1,%2,%3};"
                        : "+f"(c[im][in_][0]), "+f"(c[im][in_][1]),
                          "+f"(c[im][in_][2]), "+f"(c[im][in_][3])
                        : "r"(a[im][0]), "r"(a[im][1]), "r"(a[im][2]), "r"(a[im][3]),
                          "r"(b0[in_]), "r"(b1[in_]));
        }

        int kn = ki + STAGES - 1;
        if (kn < nK) load_stage(kn % STAGES, kn * BK);
        cp_commit();
    }

    __syncthreads();

    if (PHASE == 0) {
        uint32_t* epw = reinterpret_cast<uint32_t*>(sm);
#pragma unroll
        for (int im = 0; im < 4; im++) {
#pragma unroll
            for (int in_ = 0; in_ < 4; in_++) {
#pragma unroll
                for (int half = 0; half < 2; half++) {
                    int rr  = wm * 64 + im * 16 + half * 8 + (lane >> 2);
                    int ccw = wn * 16 + in_ * 4 + (lane & 3);
                    float v0 = gelu_f(c[im][in_][half * 2 + 0]);
                    float v1 = gelu_f(c[im][in_][half * 2 + 1]);
                    if (!sh) {
                        float gate = s_gate[rr];
                        v0 *= gate; v1 *= gate;
                    }
                    epw[rr * EP16 + ccw] = pack_half2(v0, v1);
                }
            }
        }
        __syncthreads();

        __half* mid = sh ? (g_mid_sh16 + (size_t)e * T_TOK * D_DIM)
                         : (g_mid_rt16 + (size_t)e * T_TOK * D_DIM);
#pragma unroll
        for (int jj = 0; jj < 8; jj++) {
            int idx = tid + NTHR * jj;
            int r   = idx >> 4;
            int c4  = idx & 15;
            uint4 v = *reinterpret_cast<uint4*>(&epw[r * EP16 + c4 * 4]);
            int grow = m0 + r;
            if (sh || s_tok[r] >= 0) {
                uint4* dst = reinterpret_cast<uint4*>(
                    mid + (size_t)grow * D_DIM + n0) + c4;
                *dst = v;
            }
        }
    } else {
        float* ep = sm;
#pragma unroll
        for (int im = 0; im < 4; im++) {
#pragma unroll
            for (int in_ = 0; in_ < 4; in_++) {
#pragma unroll
                for (int half = 0; half < 2; half++) {
                    int rr = wm * 64 + im * 16 + half * 8 + (lane >> 2);
                    int cc = wn * 32 + in_ * 8 + 2 * (lane & 3);
                    ep[rr * EPI_PITCH + cc]     = c[im][in_][half * 2 + 0];
                    ep[rr * EPI_PITCH + cc + 1] = c[im][in_][half * 2 + 1];
                }
            }
        }
        __syncthreads();

#pragma unroll
        for (int jj = 0; jj < 16; jj++) {
            int idx = tid + NTHR * jj;
            int r   = idx >> 5;
            int c4  = idx & 31;
            float4 v = *reinterpret_cast<float4*>(&ep[r * EPI_PITCH + c4 * 4]);
            int grow = m0 + r;
            int gcol = n0 + c4 * 4;
            if (sh) {
                float* dst = (e == 0) ? OUT : g_out_sh1;
                *reinterpret_cast<float4*>(dst + (size_t)grow * H_DIM + gcol) = v;
            } else if (s_tok[r] >= 0) {
                *reinterpret_cast<float4*>(
                    g_out_rt + ((size_t)e * T_TOK + grow) * H_DIM + gcol) = v;
            }
        }
    }
}

// -------- final combine: out[t] += shared-expert-1 + both routed bucket rows --------
__global__ void combine_kernel(float4* __restrict__ out) {
    const int HQ = H_DIM / 4;
    int idx = blockIdx.x * blockDim.x + threadIdx.x;
    if (idx >= T_TOK * HQ) return;
    int t = idx >> 9;
    int c = idx & (HQ - 1);
    int a0 = g_assign[2 * t];
    int a1 = g_assign[2 * t + 1];
    const float4* rt  = reinterpret_cast<const float4*>(g_out_rt);
    const float4* sh1 = reinterpret_cast<const float4*>(g_out_sh1);
    float4 o  = out[idx];
    float4 s1 = sh1[idx];
    float4 r0 = rt[(size_t)a0 * HQ + c];
    float4 r1 = rt[(size_t)a1 * HQ + c];
    o.x += s1.x + r0.x + r1.x;
    o.y += s1.y + r0.y + r1.y;
    o.z += s1.z + r0.z + r1.z;
    o.w += s1.w + r0.w + r1.w;
    out[idx] = o;
}

// ------------- launch: fp16 convert prologue + 3 concurrent GEMM chains -------------
extern "C" void kernel_launch(void* const* d_in, const int* in_sizes, int n_in,
                              void* d_out, int out_size) {
    const float* x      = (const float*)d_in[0];
    const float* Wsh_up = (const float*)d_in[1];
    const float* Wsh_dn = (const float*)d_in[2];
    const float* Wrt_up = (const float*)d_in[3];
    const float* Wrt_dn = (const float*)d_in[4];
    const float* Wr     = (const float*)d_in[5];
    float* out = (float*)d_out;

    static cudaStream_t s2 = nullptr, s3 = nullptr;
    static cudaEvent_t evFork = nullptr, evCup = nullptr, evCdn = nullptr,
                       evRouter = nullptr, evJ2 = nullptr, evJ3 = nullptr;
    if (s2 == nullptr) {
        cudaStreamCreateWithFlags(&s2, cudaStreamNonBlocking);
        cudaStreamCreateWithFlags(&s3, cudaStreamNonBlocking);
        cudaEventCreateWithFlags(&evFork,   cudaEventDisableTiming);
        cudaEventCreateWithFlags(&evCup,    cudaEventDisableTiming);
        cudaEventCreateWithFlags(&evCdn,    cudaEventDisableTiming);
        cudaEventCreateWithFlags(&evRouter, cudaEventDisableTiming);
        cudaEventCreateWithFlags(&evJ2,     cudaEventDisableTiming);
        cudaEventCreateWithFlags(&evJ3,     cudaEventDisableTiming);
        cudaFuncSetAttribute(gemm_fused<0>, cudaFuncAttributeMaxDynamicSharedMemorySize, SMEM_BYTES);
        cudaFuncSetAttribute(gemm_fused<1>, cudaFuncAttributeMaxDynamicSharedMemorySize, SMEM_BYTES);
    }

    void *d_x16, *d_wshup, *d_wrtup, *d_wshdn, *d_wrtdn;
    cudaGetSymbolAddress(&d_x16,   g_x16);
    cudaGetSymbolAddress(&d_wshup, g_wsh_up16);
    cudaGetSymbolAddress(&d_wrtup, g_wrt_up16);
    cudaGetSymbolAddress(&d_wshdn, g_wsh_dn16);
    cudaGetSymbolAddress(&d_wrtdn, g_wrt_dn16);

    // fork from origin stream
    zero_cnt_kernel<<<1, 32>>>();
    cudaEventRecord(evFork, 0);
    cudaStreamWaitEvent(s2, evFork, 0);
    cudaStreamWaitEvent(s3, evFork, 0);

    // s2: convert x + up weights -> up-shared
    conv16_kernel<<<592, 256, 0, s2>>>((const float4*)x, (uint4*)d_x16,
                                       T_TOK * H_DIM / 8);
    conv16_kernel<<<128, 256, 0, s2>>>((const float4*)Wsh_up, (uint4*)d_wshup,
                                       NE_SH * H_DIM * D_DIM / 8);
    conv16_kernel<<<1184, 256, 0, s2>>>((const float4*)Wrt_up, (uint4*)d_wrtup,
                                        NE_RT * H_DIM * D_DIM / 8);
    cudaEventRecord(evCup, s2);
    gemm_fused<0><<<dim3(D_DIM / BN, T_TOK / BM, NE_SH), NTHR, SMEM_BYTES, s2>>>(
        nullptr, /*zoff=*/0);

    // s3: convert down weights
    conv16_kernel<<<128, 256, 0, s3>>>((const float4*)Wsh_dn, (uint4*)d_wshdn,
                                       NE_SH * D_DIM * H_DIM / 8);
    conv16_kernel<<<1184, 256, 0, s3>>>((const float4*)Wrt_dn, (uint4*)d_wrtdn,
                                        NE_RT * D_DIM * H_DIM / 8);
    cudaEventRecord(evCdn, s3);

    // s0: router
    router_kernel<<<T_TOK / 8, 256>>>(x, Wr);
    cudaEventRecord(evRouter, 0);

    // s0: routed experts 0-7
    cudaStreamWaitEvent(0, evCup, 0);
    gemm_fused<0><<<dim3(D_DIM / BN, T_TOK / BM, 8), NTHR, SMEM_BYTES>>>(
        nullptr, /*zoff=*/2);
    cudaStreamWaitEvent(0, evCdn, 0);
    gemm_fused<1><<<dim3(H_DIM / BN, T_TOK / BM, 8), NTHR, SMEM_BYTES>>>(
        out, /*zoff=*/0);

    // s3: routed experts 8-15
    cudaStreamWaitEvent(s3, evCup, 0);
    cudaStreamWaitEvent(s3, evRouter, 0);
    gemm_fused<0><<<dim3(D_DIM / BN, T_TOK / BM, 8), NTHR, SMEM_BYTES, s3>>>(
        nullptr, /*zoff=*/10);
    gemm_fused<1><<<dim3(H_DIM / BN, T_TOK / BM, 8), NTHR, SMEM_BYTES, s3>>>(
        out, /*zoff=*/8);
    cudaEventRecord(evJ3, s3);

    // s2: down-shared
    cudaStreamWaitEvent(s2, evCdn, 0);
    gemm_fused<1><<<dim3(H_DIM / BN, T_TOK / BM, NE_SH), NTHR, SMEM_BYTES, s2>>>(
        out, /*zoff=*/16);
    cudaEventRecord(evJ2, s2);

    // join + combine
    cudaStreamWaitEvent(0, evJ2, 0);
    cudaStreamWaitEvent(0, evJ3, 0);
    combine_kernel<<<(T_TOK * (H_DIM / 4)) / 256, 256>>>((float4*)out);
}

// round 17
// speedup vs baseline: 2.9579x; 1.0040x over previous
#include <cuda_runtime.h>
#include <cuda_fp16.h>
#include <math.h>
#include <stdint.h>

#define T_TOK 4096
#define H_DIM 2048
#define D_DIM 1024
#define NE_RT 16
#define NE_SH 2

// ---------------- scratch (device globals; no allocations) ----------------
__device__ int    g_cnt[NE_RT];
__device__ int    g_tok[NE_RT * T_TOK];
__device__ float  g_gate[NE_RT * T_TOK];
__device__ int    g_assign[2 * T_TOK];
__device__ float  g_out_rt[(size_t)NE_RT * T_TOK * H_DIM];
__device__ float  g_out_sh1[(size_t)T_TOK * H_DIM];
// fp16 operands
__device__ __half g_x16[(size_t)T_TOK * H_DIM];
__device__ __half g_wsh_up16[(size_t)NE_SH * H_DIM * D_DIM];
__device__ __half g_wrt_up16[(size_t)NE_RT * H_DIM * D_DIM];
__device__ __half g_wsh_dn16[(size_t)NE_SH * D_DIM * H_DIM];
__device__ __half g_wrt_dn16[(size_t)NE_RT * D_DIM * H_DIM];
__device__ __half g_mid_sh16[(size_t)NE_SH * T_TOK * D_DIM];
__device__ __half g_mid_rt16[(size_t)NE_RT * T_TOK * D_DIM];

// ---------------- helpers ----------------
__device__ __forceinline__ uint32_t pack_half2(float lo, float hi) {
    uint32_t r;
    asm("cvt.rn.f16x2.f32 %0, %1, %2;" : "=r"(r) : "f"(hi), "f"(lo));
    return r;
}
__device__ __forceinline__ float gelu_f(float v) {
    return 0.5f * v * (1.0f + erff(v * 0.70710678118654752440f));
}
__device__ __forceinline__ void cp16(uint32_t dst_smem, const void* src, bool pred) {
    int sz = pred ? 16 : 0;
    asm volatile("cp.async.cg.shared.global [%0], [%1], 16, %2;\n"
                 :: "r"(dst_smem), "l"(src), "r"(sz) : "memory");
}
__device__ __forceinline__ void cp_commit() {
    asm volatile("cp.async.commit_group;" ::: "memory");
}
__device__ __forceinline__ void ldsm_x4(uint32_t& r0, uint32_t& r1,
                                        uint32_t& r2, uint32_t& r3,
                                        uint32_t addr) {
    asm volatile("ldmatrix.sync.aligned.m8n8.x4.shared.b16 {%0,%1,%2,%3}, [%4];"
                 : "=r"(r0), "=r"(r1), "=r"(r2), "=r"(r3) : "r"(addr));
}
__device__ __forceinline__ void ldsm_x4_trans(uint32_t& r0, uint32_t& r1,
                                              uint32_t& r2, uint32_t& r3,
                                              uint32_t addr) {
    asm volatile("ldmatrix.sync.aligned.m8n8.x4.trans.shared.b16 {%0,%1,%2,%3}, [%4];"
                 : "=r"(r0), "=r"(r1), "=r"(r2), "=r"(r3) : "r"(addr));
}

// ---------------- fp32 -> fp16 streaming convert ----------------
__global__ void conv16_kernel(const float4* __restrict__ src,
                              uint4* __restrict__ dst, int n8) {
    int stride = gridDim.x * blockDim.x;
    for (int i = blockIdx.x * blockDim.x + threadIdx.x; i < n8; i += stride) {
        float4 a = src[2 * i], b = src[2 * i + 1];
        uint4 o;
        o.x = pack_half2(a.x, a.y);
        o.y = pack_half2(a.z, a.w);
        o.z = pack_half2(b.x, b.y);
        o.w = pack_half2(b.z, b.w);
        dst[i] = o;
    }
}

__global__ void zero_cnt_kernel() {
    if (threadIdx.x < NE_RT) g_cnt[threadIdx.x] = 0;
}

// ---------------- router (fp32, unchanged) ----------------
__global__ void router_kernel(const float* __restrict__ x,
                              const float* __restrict__ Wr) {
    int warp = threadIdx.x >> 5;
    int lane = threadIdx.x & 31;
    int t = blockIdx.x * 8 + warp;
    if (t >= T_TOK) return;

    float acc[NE_RT];
#pragma unroll
    for (int e = 0; e < NE_RT; e++) acc[e] = 0.f;

    const float* xr = x + (size_t)t * H_DIM;
    for (int h = lane; h < H_DIM; h += 32) {
        float xv = xr[h];
        const float4* w4 = reinterpret_cast<const float4*>(Wr + (size_t)h * NE_RT);
#pragma unroll
        for (int q = 0; q < 4; q++) {
            float4 w = w4[q];
            acc[4*q+0] += xv * w.x;
            acc[4*q+1] += xv * w.y;
            acc[4*q+2] += xv * w.z;
            acc[4*q+3] += xv * w.w;
        }
    }
#pragma unroll
    for (int e = 0; e < NE_RT; e++) {
#pragma unroll
        for (int off = 16; off > 0; off >>= 1)
            acc[e] += __shfl_xor_sync(0xffffffffu, acc[e], off);
    }
    if (lane == 0) {
        float mx = acc[0];
#pragma unroll
        for (int e = 1; e < NE_RT; e++) mx = fmaxf(mx, acc[e]);
        float p[NE_RT];
        float s = 0.f;
#pragma unroll
        for (int e = 0; e < NE_RT; e++) { p[e] = expf(acc[e] - mx); s += p[e]; }
        float inv = 1.0f / s;

        int i1 = 0; float v1 = p[0];
#pragma unroll
        for (int e = 1; e < NE_RT; e++) if (p[e] > v1) { v1 = p[e]; i1 = e; }
        int i2 = -1; float v2 = -1.f;
#pragma unroll
        for (int e = 0; e < NE_RT; e++) if (e != i1 && p[e] > v2) { v2 = p[e]; i2 = e; }

        int pos = atomicAdd(&g_cnt[i1], 1);
        g_tok[i1 * T_TOK + pos]  = t;
        g_gate[i1 * T_TOK + pos] = v1 * inv;
        g_assign[2 * t]          = i1 * T_TOK + pos;
        pos = atomicAdd(&g_cnt[i2], 1);
        g_tok[i2 * T_TOK + pos]  = t;
        g_gate[i2 * T_TOK + pos] = v2 * inv;
        g_assign[2 * t + 1]      = i2 * T_TOK + pos;
    }
}

// ---- fp16 GEMM: 3-stage cp.async, 128x128x64 tile, ldmatrix A+B, m16n8k16 ----
// z = blockIdx.z + zoff:
// PHASE 0 (up, K=2048): z<2 shared e=z; z>=2 routed e=z-2 (gather+gate), mid fp16
// PHASE 1 (down, K=1024): z<16 routed e=z (bucket fp32); z==16 -> OUT; z==17 -> out_sh1

#define BM 128
#define BN 128
#define BK 64
#define STAGES 3
#define NTHR 256
#define AP 36
#define BP 68
#define A_W (BM * AP)
#define B_W (BK * BP)
#define STG_W (A_W + B_W)
#define EPI_PITCH 132
#define EP16 68
#define SMEM_BYTES (STAGES * STG_W * 4)

template <int PHASE>
__global__ void __launch_bounds__(NTHR) gemm_fused(float* __restrict__ OUT, int zoff) {
    constexpr int NN   = (PHASE == 0) ? 1024 : 2048;
    constexpr int LDA  = (PHASE == 0) ? 2048 : 1024;
    constexpr int KTOT = (PHASE == 0) ? 2048 : 1024;
    constexpr int nK   = KTOT / BK;

    const int z  = blockIdx.z + zoff;
    const bool sh = (PHASE == 0) ? (z < 2) : (z >= 16);
    const int e  = (PHASE == 0) ? (sh ? z : z - 2) : (sh ? z - 16 : z);

    const int m0 = blockIdx.y * BM;
    const int n0 = blockIdx.x * BN;

    int cnt = T_TOK;
    if (!sh) {
        cnt = g_cnt[e];
        if (m0 >= cnt) return;
    }

    extern __shared__ float sm[];
    __shared__ int   s_tok[BM];
    __shared__ float s_gate[BM];

    const int tid  = threadIdx.x;
    const int lane = tid & 31;
    const int warp = tid >> 5;
    const int wm   = warp >> 2;
    const int wn   = warp & 3;

    const __half* Abase;
    const __half* Bbase;
    if (PHASE == 0) {
        Abase = g_x16;
        Bbase = (sh ? g_wsh_up16 : g_wrt_up16) + (size_t)e * H_DIM * D_DIM;
    } else {
        if (sh) {
            Abase = g_mid_sh16 + (size_t)e * T_TOK * D_DIM;
            Bbase = g_wsh_dn16 + (size_t)e * D_DIM * H_DIM;
        } else {
            Abase = g_mid_rt16 + (size_t)e * T_TOK * D_DIM;
            Bbase = g_wrt_dn16 + (size_t)e * D_DIM * H_DIM;
        }
    }

    if (tid < BM) {
        int grow = m0 + tid;
        int tok;
        float gate = 0.f;
        if (sh) {
            tok = grow;
        } else if (PHASE == 0) {
            if (grow < cnt) {
                tok  = g_tok[e * T_TOK + grow];
                gate = g_gate[e * T_TOK + grow];
            } else tok = -1;
        } else {
            tok = (grow < cnt) ? grow : -1;
        }
        s_tok[tid]  = tok;
        s_gate[tid] = gate;
    }
    __syncthreads();

    int  a_srow[4];
    bool a_valid[4];
#pragma unroll
    for (int j = 0; j < 4; j++) {
        int r   = (tid + NTHR * j) >> 3;
        int tok = s_tok[r];
        if (PHASE == 0 && !sh) { a_valid[j] = tok >= 0; a_srow[j] = a_valid[j] ? tok : 0; }
        else                   { a_valid[j] = tok >= 0; a_srow[j] = m0 + r; }
    }

    const uint32_t sm_u32 = (uint32_t)__cvta_generic_to_shared(sm);

    auto load_stage = [&](int s, int k0) {
        uint32_t a_sm = sm_u32 + (uint32_t)(s * STG_W) * 4;
        uint32_t b_sm = a_sm + A_W * 4;
#pragma unroll
        for (int j = 0; j < 4; j++) {
            int idx = tid + NTHR * j;
            int r   = idx >> 3;
            int c4  = idx & 7;
            const __half* src = Abase + (size_t)a_srow[j] * LDA + k0 + c4 * 8;
            cp16(a_sm + (uint32_t)(r * AP + c4 * 4) * 4, src, a_valid[j]);
        }
#pragma unroll
        for (int j = 0; j < 4; j++) {
            int idx = tid + NTHR * j;
            int r   = idx >> 4;
            int c4  = idx & 15;
            const __half* src = Bbase + (size_t)(k0 + r) * NN + n0 + c4 * 8;
            cp16(b_sm + (uint32_t)(r * BP + c4 * 4) * 4, src, true);
        }
    };

    float c[4][4][4];
#pragma unroll
    for (int i = 0; i < 4; i++)
#pragma unroll
        for (int j = 0; j < 4; j++)
#pragma unroll
            for (int q = 0; q < 4; q++) c[i][j][q] = 0.f;

#pragma unroll
    for (int s = 0; s < STAGES - 1; s++) {
        load_stage(s, s * BK);
        cp_commit();
    }

    const int a_lrow = ((lane >> 3) & 1) * 8 + (lane & 7);
    const int a_kw   = (lane >> 4) * 4;

    for (int ki = 0; ki < nK; ki++) {
        asm volatile("cp.async.wait_group %0;" :: "n"(STAGES - 2) : "memory");
        __syncthreads();

        const int st = ki % STAGES;
        const uint32_t as_u32 = sm_u32 + (uint32_t)(st * STG_W) * 4;
        const uint32_t bs_u32 = as_u32 + A_W * 4;

#pragma unroll
        for (int s = 0; s < 4; s++) {
            uint32_t a[4][4];
#pragma unroll
            for (int im = 0; im < 4; im++) {
                uint32_t arow = wm * 64 + im * 16 + a_lrow;
                uint32_t aaddr = as_u32 + (uint32_t)(arow * AP + s * 8 + a_kw) * 4;
                ldsm_x4(a[im][0], a[im][1], a[im][2], a[im][3], aaddr);
            }
            uint32_t b0[4], b1[4];
            uint32_t addr0 = bs_u32 +
                (uint32_t)((s * 16 + (lane & 7)) * BP) * 4 +
                (uint32_t)(wn * 32 + (lane >> 3) * 8) * 2;
            ldsm_x4_trans(b0[0], b0[1], b0[2], b0[3], addr0);
            ldsm_x4_trans(b1[0], b1[1], b1[2], b1[3], addr0 + 8 * BP * 4);
#pragma unroll
            for (int im = 0; im < 4; im++)
#pragma unroll
                for (int in_ = 0; in_ < 4; in_++)
                    asm volatile(
                        "mma.sync.aligned.m16n8k16.row.col.f32.f16.f16.f32 "
                        "{%0,%1,%2,%3}, {%4,%5,%6,%7}, {%8,%9}, {%0,%1,%2,%3};"
                        : "+f"(c[im][in_][0]), "+f"(c[im][in_][1]),
                          "+f"(c[im][in_][2]), "+f"(c[im][in_][3])
                        : "r"(a[im][0]), "r"(a[im][1]), "r"(a[im][2]), "r"(a[im][3]),
                          "r"(b0[in_]), "r"(b1[in_]));
        }

        int kn = ki + STAGES - 1;
        if (kn < nK) load_stage(kn % STAGES, kn * BK);
        cp_commit();
    }

    __syncthreads();

    if (PHASE == 0) {
        uint32_t* epw = reinterpret_cast<uint32_t*>(sm);
#pragma unroll
        for (int im = 0; im < 4; im++) {
#pragma unroll
            for (int in_ = 0; in_ < 4; in_++) {
#pragma unroll
                for (int half = 0; half < 2; half++) {
                    int rr  = wm * 64 + im * 16 + half * 8 + (lane >> 2);
                    int ccw = wn * 16 + in_ * 4 + (lane & 3);
                    float v0 = gelu_f(c[im][in_][half * 2 + 0]);
                    float v1 = gelu_f(c[im][in_][half * 2 + 1]);
                    if (!sh) {
                        float gate = s_gate[rr];
                        v0 *= gate; v1 *= gate;
                    }
                    epw[rr * EP16 + ccw] = pack_half2(v0, v1);
                }
            }
        }
        __syncthreads();

        __half* mid = sh ? (g_mid_sh16 + (size_t)e * T_TOK * D_DIM)
                         : (g_mid_rt16 + (size_t)e * T_TOK * D_DIM);
#pragma unroll
        for (int jj = 0; jj < 8; jj++) {
            int idx = tid + NTHR * jj;
            int r   = idx >> 4;
            int c4  = idx & 15;
            uint4 v = *reinterpret_cast<uint4*>(&epw[r * EP16 + c4 * 4]);
            int grow = m0 + r;
            if (sh || s_tok[r] >= 0) {
                uint4* dst = reinterpret_cast<uint4*>(
                    mid + (size_t)grow * D_DIM + n0) + c4;
                *dst = v;
            }
        }
    } else {
        float* ep = sm;
#pragma unroll
        for (int im = 0; im < 4; im++) {
#pragma unroll
            for (int in_ = 0; in_ < 4; in_++) {
#pragma unroll
                for (int half = 0; half < 2; half++) {
                    int rr = wm * 64 + im * 16 + half * 8 + (lane >> 2);
                    int cc = wn * 32 + in_ * 8 + 2 * (lane & 3);
                    ep[rr * EPI_PITCH + cc]     = c[im][in_][half * 2 + 0];
                    ep[rr * EPI_PITCH + cc + 1] = c[im][in_][half * 2 + 1];
                }
            }
        }
        __syncthreads();

#pragma unroll
        for (int jj = 0; jj < 16; jj++) {
            int idx = tid + NTHR * jj;
            int r   = idx >> 5;
            int c4  = idx & 31;
            float4 v = *reinterpret_cast<float4*>(&ep[r * EPI_PITCH + c4 * 4]);
            int grow = m0 + r;
            int gcol = n0 + c4 * 4;
            if (sh) {
                float* dst = (e == 0) ? OUT : g_out_sh1;
                *reinterpret_cast<float4*>(dst + (size_t)grow * H_DIM + gcol) = v;
            } else if (s_tok[r] >= 0) {
                *reinterpret_cast<float4*>(
                    g_out_rt + ((size_t)e * T_TOK + grow) * H_DIM + gcol) = v;
            }
        }
    }
}

// -------- final combine: out[t] += shared-expert-1 + both routed bucket rows --------
__global__ void combine_kernel(float4* __restrict__ out) {
    const int HQ = H_DIM / 4;
    int idx = blockIdx.x * blockDim.x + threadIdx.x;
    if (idx >= T_TOK * HQ) return;
    int t = idx >> 9;
    int c = idx & (HQ - 1);
    int a0 = g_assign[2 * t];
    int a1 = g_assign[2 * t + 1];
    const float4* rt  = reinterpret_cast<const float4*>(g_out_rt);
    const float4* sh1 = reinterpret_cast<const float4*>(g_out_sh1);
    float4 o  = out[idx];
    float4 s1 = sh1[idx];
    float4 r0 = rt[(size_t)a0 * HQ + c];
    float4 r1 = rt[(size_t)a1 * HQ + c];
    o.x += s1.x + r0.x + r1.x;
    o.y += s1.y + r0.y + r1.y;
    o.z += s1.z + r0.z + r1.z;
    o.w += s1.w + r0.w + r1.w;
    out[idx] = o;
}

// ---- launch: split-half conversion events shorten the routed critical path ----
extern "C" void kernel_launch(void* const* d_in, const int* in_sizes, int n_in,
                              void* d_out, int out_size) {
    const float* x      = (const float*)d_in[0];
    const float* Wsh_up = (const float*)d_in[1];
    const float* Wsh_dn = (const float*)d_in[2];
    const float* Wrt_up = (const float*)d_in[3];
    const float* Wrt_dn = (const float*)d_in[4];
    const float* Wr     = (const float*)d_in[5];
    float* out = (float*)d_out;

    static cudaStream_t s2 = nullptr, s3 = nullptr;
    static cudaEvent_t evFork = nullptr, evCupA = nullptr, evCupB = nullptr,
                       evCdn = nullptr, evRouter = nullptr,
                       evJ2 = nullptr, evJ3 = nullptr;
    if (s2 == nullptr) {
        cudaStreamCreateWithFlags(&s2, cudaStreamNonBlocking);
        cudaStreamCreateWithFlags(&s3, cudaStreamNonBlocking);
        cudaEventCreateWithFlags(&evFork,   cudaEventDisableTiming);
        cudaEventCreateWithFlags(&evCupA,   cudaEventDisableTiming);
        cudaEventCreateWithFlags(&evCupB,   cudaEventDisableTiming);
        cudaEventCreateWithFlags(&evCdn,    cudaEventDisableTiming);
        cudaEventCreateWithFlags(&evRouter, cudaEventDisableTiming);
        cudaEventCreateWithFlags(&evJ2,     cudaEventDisableTiming);
        cudaEventCreateWithFlags(&evJ3,     cudaEventDisableTiming);
        cudaFuncSetAttribute(gemm_fused<0>, cudaFuncAttributeMaxDynamicSharedMemorySize, SMEM_BYTES);
        cudaFuncSetAttribute(gemm_fused<1>, cudaFuncAttributeMaxDynamicSharedMemorySize, SMEM_BYTES);
    }

    void *d_x16, *d_wshup, *d_wrtup, *d_wshdn, *d_wrtdn;
    cudaGetSymbolAddress(&d_x16,   g_x16);
    cudaGetSymbolAddress(&d_wshup, g_wsh_up16);
    cudaGetSymbolAddress(&d_wrtup, g_wrt_up16);
    cudaGetSymbolAddress(&d_wshdn, g_wsh_dn16);
    cudaGetSymbolAddress(&d_wrtdn, g_wrt_dn16);

    const size_t HALF_UP = (size_t)8 * H_DIM * D_DIM;   // 8 experts of wrt_up

    // fork from origin stream
    zero_cnt_kernel<<<1, 32>>>();
    cudaEventRecord(evFork, 0);
    cudaStreamWaitEvent(s2, evFork, 0);
    cudaStreamWaitEvent(s3, evFork, 0);

    // s2: x -> wrt_up[0:8] -> (evCupA) -> wrt_up[8:16] -> (evCupB) -> wsh_up -> up-shared
    conv16_kernel<<<592, 256, 0, s2>>>((const float4*)x, (uint4*)d_x16,
                                       T_TOK * H_DIM / 8);
    conv16_kernel<<<592, 256, 0, s2>>>((const float4*)Wrt_up,
                                       (uint4*)d_wrtup, (int)(HALF_UP / 8));
    cudaEventRecord(evCupA, s2);
    conv16_kernel<<<592, 256, 0, s2>>>((const float4*)(Wrt_up + HALF_UP),
                                       (uint4*)((__half*)d_wrtup + HALF_UP),
                                       (int)(HALF_UP / 8));
    cudaEventRecord(evCupB, s2);
    conv16_kernel<<<128, 256, 0, s2>>>((const float4*)Wsh_up, (uint4*)d_wshup,
                                       NE_SH * H_DIM * D_DIM / 8);
    gemm_fused<0><<<dim3(D_DIM / BN, T_TOK / BM, NE_SH), NTHR, SMEM_BYTES, s2>>>(
        nullptr, /*zoff=*/0);

    // s3: down-weight conversions (off the critical path)
    conv16_kernel<<<128, 256, 0, s3>>>((const float4*)Wsh_dn, (uint4*)d_wshdn,
                                       NE_SH * D_DIM * H_DIM / 8);
    conv16_kernel<<<1184, 256, 0, s3>>>((const float4*)Wrt_dn, (uint4*)d_wrtdn,
                                        NE_RT * D_DIM * H_DIM / 8);
    cudaEventRecord(evCdn, s3);

    // s0: router (parallel with conversions)
    router_kernel<<<T_TOK / 8, 256>>>(x, Wr);
    cudaEventRecord(evRouter, 0);

    // s0: routed experts 0-7 (needs x + wrt_up[0:8] only)
    cudaStreamWaitEvent(0, evCupA, 0);
    gemm_fused<0><<<dim3(D_DIM / BN, T_TOK / BM, 8), NTHR, SMEM_BYTES>>>(
        nullptr, /*zoff=*/2);
    cudaStreamWaitEvent(0, evCdn, 0);
    gemm_fused<1><<<dim3(H_DIM / BN, T_TOK / BM, 8), NTHR, SMEM_BYTES>>>(
        out, /*zoff=*/0);

    // s3: routed experts 8-15 (needs x + wrt_up[8:16] + router; down conv in order)
    cudaStreamWaitEvent(s3, evCupB, 0);
    cudaStreamWaitEvent(s3, evRouter, 0);
    gemm_fused<0><<<dim3(D_DIM / BN, T_TOK / BM, 8), NTHR, SMEM_BYTES, s3>>>(
        nullptr, /*zoff=*/10);
    gemm_fused<1><<<dim3(H_DIM / BN, T_TOK / BM, 8), NTHR, SMEM_BYTES, s3>>>(
        out, /*zoff=*/8);
    cudaEventRecord(evJ3, s3);

    // s2: down-shared (needs down weights)
    cudaStreamWaitEvent(s2, evCdn, 0);
    gemm_fused<1><<<dim3(H_DIM / BN, T_TOK / BM, NE_SH), NTHR, SMEM_BYTES, s2>>>(
        out, /*zoff=*/16);
    cudaEventRecord(evJ2, s2);

    // join + combine
    cudaStreamWaitEvent(0, evJ2, 0);
    cudaStreamWaitEvent(0, evJ3, 0);
    combine_kernel<<<(T_TOK * (H_DIM / 4)) / 256, 256>>>((float4*)out);
}